// round 7
// baseline (speedup 1.0000x reference)
#include <cuda_runtime.h>
#include <cuda_bf16.h>
#include <cstdint>
#include <cstddef>

#define HEADS 24
#define HEAD_DIM 128
#define INNER 3072
#define RANK 1024
#define S_IMG 2048
#define S_TXT 512
#define S_REF 2048
#define SQ (S_TXT + S_IMG)          // 2560
#define SK (S_TXT + S_IMG + S_REF)  // 4608

// ---------------- scratch (device globals; no allocation) ----------------
__device__ float g_q[(size_t)SQ * INNER];
__device__ float g_k[(size_t)SK * INNER];

__device__ __nv_bfloat16 g_Wh[(size_t)8 * INNER * INNER];
__device__ __nv_bfloat16 g_Wl[(size_t)8 * INNER * INNER];
__device__ __nv_bfloat16 g_Uh[(size_t)4 * INNER * RANK];
__device__ __nv_bfloat16 g_Ul[(size_t)4 * INNER * RANK];
__device__ __nv_bfloat16 g_xh[(size_t)(S_IMG + S_TXT + S_REF) * INNER];
__device__ __nv_bfloat16 g_xl[(size_t)(S_IMG + S_TXT + S_REF) * INNER];
__device__ __nv_bfloat16 g_th[(size_t)S_REF * RANK];
__device__ __nv_bfloat16 g_tl[(size_t)S_REF * RANK];
__device__ __nv_bfloat16 g_oh[(size_t)SQ * INNER];
__device__ __nv_bfloat16 g_ol[(size_t)SQ * INNER];
__device__ __nv_bfloat16 g_qh[(size_t)SQ * INNER];
__device__ __nv_bfloat16 g_ql[(size_t)SQ * INNER];
__device__ __nv_bfloat16 g_kh[(size_t)SK * INNER];
__device__ __nv_bfloat16 g_kl[(size_t)SK * INNER];
__device__ __nv_bfloat16 g_vh[(size_t)SK * INNER];
__device__ __nv_bfloat16 g_vl[(size_t)SK * INNER];

// ---------------- fp32 -> bf16 hi/lo split (4x float4 per thread) --------
__global__ void split_kernel(const float* __restrict__ x,
                             __nv_bfloat16* __restrict__ h,
                             __nv_bfloat16* __restrict__ l)
{
    size_t base = ((size_t)blockIdx.x * 256 + threadIdx.x) * 16;
    float4 v[4];
#pragma unroll
    for (int u = 0; u < 4; u++) v[u] = *(const float4*)(x + base + u * 4);
#pragma unroll
    for (int u = 0; u < 4; u++) {
        float4 w = v[u];
        __nv_bfloat16 h0 = __float2bfloat16(w.x);
        __nv_bfloat16 h1 = __float2bfloat16(w.y);
        __nv_bfloat16 h2 = __float2bfloat16(w.z);
        __nv_bfloat16 h3 = __float2bfloat16(w.w);
        __nv_bfloat16 l0 = __float2bfloat16(w.x - __bfloat162float(h0));
        __nv_bfloat16 l1 = __float2bfloat16(w.y - __bfloat162float(h1));
        __nv_bfloat16 l2 = __float2bfloat16(w.z - __bfloat162float(h2));
        __nv_bfloat16 l3 = __float2bfloat16(w.w - __bfloat162float(h3));
        __nv_bfloat162* hp = (__nv_bfloat162*)(h + base + u * 4);
        hp[0] = __nv_bfloat162{h0, h1}; hp[1] = __nv_bfloat162{h2, h3};
        __nv_bfloat162* lp = (__nv_bfloat162*)(l + base + u * 4);
        lp[0] = __nv_bfloat162{l0, l1}; lp[1] = __nv_bfloat162{l2, l3};
    }
}

// ---------------- ptx helpers ----------------
#define LDSM4(R, addr) \
    asm volatile("ldmatrix.sync.aligned.m8n8.x4.shared.b16 {%0,%1,%2,%3},[%4];" \
        : "=r"((R)[0]), "=r"((R)[1]), "=r"((R)[2]), "=r"((R)[3]) : "r"(addr))
#define LDSM4T(R, addr) \
    asm volatile("ldmatrix.sync.aligned.m8n8.x4.trans.shared.b16 {%0,%1,%2,%3},[%4];" \
        : "=r"((R)[0]), "=r"((R)[1]), "=r"((R)[2]), "=r"((R)[3]) : "r"(addr))
#define MMA_BF16(C, A, B) \
    asm volatile("mma.sync.aligned.m16n8k16.row.col.f32.bf16.bf16.f32 " \
        "{%0,%1,%2,%3},{%4,%5,%6,%7},{%8,%9},{%0,%1,%2,%3};" \
        : "+f"((C)[0]), "+f"((C)[1]), "+f"((C)[2]), "+f"((C)[3]) \
        : "r"((A)[0]), "r"((A)[1]), "r"((A)[2]), "r"((A)[3]), "r"((B)[0]), "r"((B)[1]))
#define MMA_B2(C, A, B0, B1) \
    asm volatile("mma.sync.aligned.m16n8k16.row.col.f32.bf16.bf16.f32 " \
        "{%0,%1,%2,%3},{%4,%5,%6,%7},{%8,%9},{%0,%1,%2,%3};" \
        : "+f"((C)[0]), "+f"((C)[1]), "+f"((C)[2]), "+f"((C)[3]) \
        : "r"((A)[0]), "r"((A)[1]), "r"((A)[2]), "r"((A)[3]), "r"(B0), "r"(B1))

__device__ __forceinline__ void cp16(__nv_bfloat16* dst, const __nv_bfloat16* src) {
    unsigned d = (unsigned)__cvta_generic_to_shared(dst);
    asm volatile("cp.async.cg.shared.global [%0],[%1],16;" :: "r"(d), "l"(src));
}
#define CP_COMMIT() asm volatile("cp.async.commit_group;")
#define CP_WAIT0()  asm volatile("cp.async.wait_group 0;")
#define CP_WAIT1()  asm volatile("cp.async.wait_group 1;")

// ---------------- bf16x3 split-precision GEMM (3-stage cp.async) ---------
#define A_LD 40
#define B_LD 136
#define SA_ELEMS (128 * A_LD)
#define SB_ELEMS (32 * B_LD)
#define GSTAGE_ELEMS (2 * SA_ELEMS + 2 * SB_ELEMS)
#define GEMM_SMEM_BYTES (GSTAGE_ELEMS * 3 * 2)

__global__ __launch_bounds__(256, 1) void gemm_bf16x3_kernel(
    const __nv_bfloat16* __restrict__ Ah, const __nv_bfloat16* __restrict__ Al,
    const __nv_bfloat16* __restrict__ Bh, const __nv_bfloat16* __restrict__ Bl,
    const float* __restrict__ bias, float* __restrict__ Cf,
    __nv_bfloat16* __restrict__ Ch, __nv_bfloat16* __restrict__ Cl,
    int M, int N, int K)
{
    extern __shared__ __nv_bfloat16 dsm[];

    const int tid  = threadIdx.x;
    const int lane = tid & 31;
    const int wid  = tid >> 5;
    const int wm   = wid & 3;
    const int wn   = wid >> 2;
    const int bm   = blockIdx.y * 128;
    const int bn   = blockIdx.x * 128;

    const int ar = tid >> 2;
    const int ac = (tid & 3) * 8;
    const int br = tid >> 4;
    const int bc = (tid & 15) * 8;

    float c[2][8][4];
#pragma unroll
    for (int mi = 0; mi < 2; mi++)
#pragma unroll
        for (int ni = 0; ni < 8; ni++)
#pragma unroll
            for (int r = 0; r < 4; r++) c[mi][ni][r] = 0.f;

    const int iters = K >> 5;

    auto load_stage = [&](int s, int it) {
        int k0 = it << 5;
        __nv_bfloat16* st  = dsm + s * GSTAGE_ELEMS;
        __nv_bfloat16* pAh = st;
        __nv_bfloat16* pAl = st + SA_ELEMS;
        __nv_bfloat16* pBh = st + 2 * SA_ELEMS;
        __nv_bfloat16* pBl = pBh + SB_ELEMS;
        cp16(pAh + ar * A_LD + ac,        Ah + (size_t)(bm + ar) * K + k0 + ac);
        cp16(pAh + (ar + 64) * A_LD + ac, Ah + (size_t)(bm + ar + 64) * K + k0 + ac);
        cp16(pAl + ar * A_LD + ac,        Al + (size_t)(bm + ar) * K + k0 + ac);
        cp16(pAl + (ar + 64) * A_LD + ac, Al + (size_t)(bm + ar + 64) * K + k0 + ac);
        cp16(pBh + br * B_LD + bc,        Bh + (size_t)(k0 + br) * N + bn + bc);
        cp16(pBh + (br + 16) * B_LD + bc, Bh + (size_t)(k0 + br + 16) * N + bn + bc);
        cp16(pBl + br * B_LD + bc,        Bl + (size_t)(k0 + br) * N + bn + bc);
        cp16(pBl + (br + 16) * B_LD + bc, Bl + (size_t)(k0 + br + 16) * N + bn + bc);
    };

    load_stage(0, 0); CP_COMMIT();
    load_stage(1, 1); CP_COMMIT();

    for (int it = 0; it < iters; it++) {
        if (it == iters - 1) { CP_WAIT0(); } else { CP_WAIT1(); }
        __syncthreads();
        if (it + 2 < iters) { load_stage((it + 2) % 3, it + 2); CP_COMMIT(); }

        const __nv_bfloat16* st = dsm + (it % 3) * GSTAGE_ELEMS;
        const unsigned sAh_b = (unsigned)__cvta_generic_to_shared(st);
        const unsigned sAl_b = sAh_b + SA_ELEMS * 2;
        const unsigned sBh_b = sAh_b + 4 * SA_ELEMS;
        const unsigned sBl_b = sBh_b + SB_ELEMS * 2;

        // --- prefetch ALL fragments for both k-halves up front (double buffer)
        unsigned ahf[2][2][4], alf[2][2][4], bhf[2][4][4], blf[2][4][4];
#pragma unroll
        for (int kh = 0; kh < 2; kh++) {
#pragma unroll
            for (int mi = 0; mi < 2; mi++) {
                unsigned off = (unsigned)(((wm * 32 + mi * 16 + (lane & 15)) * A_LD
                                           + kh * 16 + ((lane >> 4) << 3)) * 2);
                LDSM4(ahf[kh][mi], sAh_b + off);
                LDSM4(alf[kh][mi], sAl_b + off);
            }
#pragma unroll
            for (int p = 0; p < 4; p++) {
                unsigned off = (unsigned)(((kh * 16 + (lane & 15)) * B_LD
                                           + wn * 64 + p * 16 + ((lane >> 4) << 3)) * 2);
                LDSM4T(bhf[kh][p], sBh_b + off);
                LDSM4T(blf[kh][p], sBl_b + off);
            }
        }
        // --- uninterrupted MMA stream
#pragma unroll
        for (int kh = 0; kh < 2; kh++) {
#pragma unroll
            for (int p = 0; p < 4; p++) {
#pragma unroll
                for (int mi = 0; mi < 2; mi++) {
                    MMA_BF16(c[mi][2 * p],     ahf[kh][mi], bhf[kh][p]);
                    MMA_BF16(c[mi][2 * p + 1], ahf[kh][mi], bhf[kh][p] + 2);
                    MMA_BF16(c[mi][2 * p],     ahf[kh][mi], blf[kh][p]);
                    MMA_BF16(c[mi][2 * p + 1], ahf[kh][mi], blf[kh][p] + 2);
                    MMA_BF16(c[mi][2 * p],     alf[kh][mi], bhf[kh][p]);
                    MMA_BF16(c[mi][2 * p + 1], alf[kh][mi], bhf[kh][p] + 2);
                }
            }
        }
    }

    const int row0 = bm + wm * 32 + (lane >> 2);
    const int col0 = bn + wn * 64 + (lane & 3) * 2;
#pragma unroll
    for (int mi = 0; mi < 2; mi++) {
#pragma unroll
        for (int ni = 0; ni < 8; ni++) {
            int r  = row0 + mi * 16;
            int cc = col0 + ni * 8;
            float b0 = bias ? bias[cc] : 0.f;
            float b1 = bias ? bias[cc + 1] : 0.f;
            float v0 = c[mi][ni][0] + b0, v1 = c[mi][ni][1] + b1;
            float v2 = c[mi][ni][2] + b0, v3 = c[mi][ni][3] + b1;
            if (Ch) {
                __nv_bfloat162 h01 = __floats2bfloat162_rn(v0, v1);
                __nv_bfloat162 h23 = __floats2bfloat162_rn(v2, v3);
                __nv_bfloat162 l01 = __floats2bfloat162_rn(v0 - __bfloat162float(h01.x),
                                                           v1 - __bfloat162float(h01.y));
                __nv_bfloat162 l23 = __floats2bfloat162_rn(v2 - __bfloat162float(h23.x),
                                                           v3 - __bfloat162float(h23.y));
                *(__nv_bfloat162*)(Ch + (size_t)r * N + cc)       = h01;
                *(__nv_bfloat162*)(Cl + (size_t)r * N + cc)       = l01;
                *(__nv_bfloat162*)(Ch + (size_t)(r + 8) * N + cc) = h23;
                *(__nv_bfloat162*)(Cl + (size_t)(r + 8) * N + cc) = l23;
            } else {
                *(float2*)(Cf + (size_t)r * N + cc)       = float2{v0, v1};
                *(float2*)(Cf + (size_t)(r + 8) * N + cc) = float2{v2, v3};
            }
        }
    }
}

// ---------------- fused RMSNorm + RoPE -> bf16 hi/lo split ----------------
__global__ void rmsnorm_rope_split_kernel(
    const float* __restrict__ src,
    __nv_bfloat16* __restrict__ outh, __nv_bfloat16* __restrict__ outl,
    const float* __restrict__ w0, const float* __restrict__ w1, int split,
    const float* __restrict__ cos_t, const float* __restrict__ sin_t,
    float eps)
{
    const int row = blockIdx.x;
    const int h   = blockIdx.y;
    const int d   = threadIdx.x;

    const float* x = src + (size_t)row * INNER + h * HEAD_DIM;
    float v = x[d];
    float ss = v * v;
#pragma unroll
    for (int o = 16; o; o >>= 1) ss += __shfl_xor_sync(0xffffffffu, ss, o);
    __shared__ float red[4];
    if ((d & 31) == 0) red[d >> 5] = ss;
    __syncthreads();
    float tot = red[0] + red[1] + red[2] + red[3];
    float r = rsqrtf(tot * (1.0f / HEAD_DIM) + eps);

    const float* w = (row < split) ? w0 : w1;
    float y = v * r;
    if (w) y *= w[d];

    float other = __shfl_xor_sync(0xffffffffu, y, 1);
    float c = cos_t[(size_t)row * HEAD_DIM + d];
    float s = sin_t[(size_t)row * HEAD_DIM + d];
    float rot = (d & 1) ? other : -other;
    float out = y * c + rot * s;

    __nv_bfloat16 hv = __float2bfloat16(out);
    __nv_bfloat16 lv = __float2bfloat16(out - __bfloat162float(hv));
    size_t idx = (size_t)row * INNER + h * HEAD_DIM + d;
    outh[idx] = hv;
    outl[idx] = lv;
}

// ---------------- tensor-core flash attention (bf16x3, cp.async KV) ------
#define LDQ 136
#define Q_ELEMS (128 * LDQ)
#define KV_ELEMS (64 * LDQ)
#define KVSTAGE_ELEMS (4 * KV_ELEMS)
#define ATTN_SMEM_BYTES ((2 * Q_ELEMS + 2 * KVSTAGE_ELEMS) * 2)

__global__ __launch_bounds__(256, 1) void attn_bf16_kernel(
    const __nv_bfloat16* __restrict__ Qh, const __nv_bfloat16* __restrict__ Ql,
    const __nv_bfloat16* __restrict__ Kh, const __nv_bfloat16* __restrict__ Kl,
    const __nv_bfloat16* __restrict__ Vh, const __nv_bfloat16* __restrict__ Vl,
    __nv_bfloat16* __restrict__ Oh, __nv_bfloat16* __restrict__ Ol)
{
    extern __shared__ __nv_bfloat16 smb[];
    __nv_bfloat16* sQh = smb;
    __nv_bfloat16* sQl = sQh + Q_ELEMS;
    __nv_bfloat16* kvBase = sQl + Q_ELEMS;

    const int h    = blockIdx.y;
    const int q0   = blockIdx.x * 128;
    const int tid  = threadIdx.x;
    const int lane = tid & 31;
    const int w    = tid >> 5;
    const float scale = 0.08838834764831845f;

    const unsigned sQh_b = (unsigned)__cvta_generic_to_shared(sQh);
    const unsigned sQl_b = sQh_b + Q_ELEMS * 2;

    const int krow = tid >> 2;
    const int kcol = (tid & 3) * 32;

    auto load_kv = [&](int s, int kt) {
        __nv_bfloat16* st = kvBase + s * KVSTAGE_ELEMS;
        __nv_bfloat16* pKh = st;
        __nv_bfloat16* pKl = st + KV_ELEMS;
        __nv_bfloat16* pVh = st + 2 * KV_ELEMS;
        __nv_bfloat16* pVl = st + 3 * KV_ELEMS;
#pragma unroll
        for (int seg = 0; seg < 4; seg++) {
            int cc = kcol + seg * 8;
            size_t g = (size_t)(kt * 64 + krow) * INNER + h * HEAD_DIM + cc;
            cp16(pKh + krow * LDQ + cc, Kh + g);
            cp16(pKl + krow * LDQ + cc, Kl + g);
            cp16(pVh + krow * LDQ + cc, Vh + g);
            cp16(pVl + krow * LDQ + cc, Vl + g);
        }
    };

    load_kv(0, 0); CP_COMMIT();

    for (int i = tid; i < 128 * 16; i += 256) {
        int row = i >> 4;
        int c8  = (i & 15) * 8;
        size_t g = (size_t)(q0 + row) * INNER + h * HEAD_DIM + c8;
        *(uint4*)(sQh + row * LDQ + c8) = *(const uint4*)(Qh + g);
        *(uint4*)(sQl + row * LDQ + c8) = *(const uint4*)(Ql + g);
    }

    float o[16][4];
#pragma unroll
    for (int nt = 0; nt < 16; nt++)
#pragma unroll
        for (int r = 0; r < 4; r++) o[nt][r] = 0.f;
    float m_lo = -1e30f, m_hi = -1e30f, l_lo = 0.f, l_hi = 0.f;

    const int NT = SK / 64;
    for (int kt = 0; kt < NT; kt++) {
        CP_WAIT0();
        __syncthreads();
        if (kt + 1 < NT) { load_kv((kt + 1) & 1, kt + 1); CP_COMMIT(); }

        const __nv_bfloat16* st = kvBase + (kt & 1) * KVSTAGE_ELEMS;
        const unsigned sKh_b = (unsigned)__cvta_generic_to_shared(st);
        const unsigned sKl_b = sKh_b + KV_ELEMS * 2;
        const unsigned sVh_b = sKh_b + 2 * KV_ELEMS * 2;
        const unsigned sVl_b = sKh_b + 3 * KV_ELEMS * 2;

        float c[8][4];
#pragma unroll
        for (int n = 0; n < 8; n++)
#pragma unroll
            for (int r = 0; r < 4; r++) c[n][r] = 0.f;

#pragma unroll
        for (int kk = 0; kk < 8; kk++) {
            unsigned ah[4], al[4];
            unsigned qoff = (unsigned)(((w * 16 + (lane & 15)) * LDQ
                                        + kk * 16 + ((lane >> 4) << 3)) * 2);
            LDSM4(ah, sQh_b + qoff);
            LDSM4(al, sQl_b + qoff);
#pragma unroll
            for (int ng = 0; ng < 4; ng++) {
                unsigned bh[4], bl[4];
                unsigned koff = (unsigned)(((ng * 16 + (lane & 15)) * LDQ
                                            + kk * 16 + ((lane >> 4) << 3)) * 2);
                LDSM4(bh, sKh_b + koff);
                LDSM4(bl, sKl_b + koff);
                MMA_B2(c[2 * ng],     ah, bh[0], bh[2]);
                MMA_B2(c[2 * ng],     ah, bl[0], bl[2]);
                MMA_B2(c[2 * ng],     al, bh[0], bh[2]);
                MMA_B2(c[2 * ng + 1], ah, bh[1], bh[3]);
                MMA_B2(c[2 * ng + 1], ah, bl[1], bl[3]);
                MMA_B2(c[2 * ng + 1], al, bh[1], bh[3]);
            }
        }

        float tmx_lo = -1e30f, tmx_hi = -1e30f;
#pragma unroll
        for (int n = 0; n < 8; n++) {
            c[n][0] *= scale; c[n][1] *= scale; c[n][2] *= scale; c[n][3] *= scale;
            tmx_lo = fmaxf(tmx_lo, fmaxf(c[n][0], c[n][1]));
            tmx_hi = fmaxf(tmx_hi, fmaxf(c[n][2], c[n][3]));
        }
        tmx_lo = fmaxf(tmx_lo, __shfl_xor_sync(0xffffffffu, tmx_lo, 1));
        tmx_lo = fmaxf(tmx_lo, __shfl_xor_sync(0xffffffffu, tmx_lo, 2));
        tmx_hi = fmaxf(tmx_hi, __shfl_xor_sync(0xffffffffu, tmx_hi, 1));
        tmx_hi = fmaxf(tmx_hi, __shfl_xor_sync(0xffffffffu, tmx_hi, 2));

        float mn_lo = fmaxf(m_lo, tmx_lo);
        float mn_hi = fmaxf(m_hi, tmx_hi);
        float al_lo = __expf(m_lo - mn_lo);
        float al_hi = __expf(m_hi - mn_hi);
        m_lo = mn_lo; m_hi = mn_hi;

        unsigned ph[8][2], pl[8][2];
        float sum_lo = 0.f, sum_hi = 0.f;
#pragma unroll
        for (int n = 0; n < 8; n++) {
            float p0 = __expf(c[n][0] - m_lo);
            float p1 = __expf(c[n][1] - m_lo);
            float p2 = __expf(c[n][2] - m_hi);
            float p3 = __expf(c[n][3] - m_hi);
            sum_lo += p0 + p1;
            sum_hi += p2 + p3;
            __nv_bfloat162 h01 = __floats2bfloat162_rn(p0, p1);
            __nv_bfloat162 h23 = __floats2bfloat162_rn(p2, p3);
            __nv_bfloat162 l01 = __floats2bfloat162_rn(p0 - __bfloat162float(h01.x),
                                                       p1 - __bfloat162float(h01.y));
            __nv_bfloat162 l23 = __floats2bfloat162_rn(p2 - __bfloat162float(h23.x),
                                                       p3 - __bfloat162float(h23.y));
            ph[n][0] = *(unsigned*)&h01; ph[n][1] = *(unsigned*)&h23;
            pl[n][0] = *(unsigned*)&l01; pl[n][1] = *(unsigned*)&l23;
        }
        sum_lo += __shfl_xor_sync(0xffffffffu, sum_lo, 1);
        sum_lo += __shfl_xor_sync(0xffffffffu, sum_lo, 2);
        sum_hi += __shfl_xor_sync(0xffffffffu, sum_hi, 1);
        sum_hi += __shfl_xor_sync(0xffffffffu, sum_hi, 2);
        l_lo = l_lo * al_lo + sum_lo;
        l_hi = l_hi * al_hi + sum_hi;

#pragma unroll
        for (int nt = 0; nt < 16; nt++) {
            o[nt][0] *= al_lo; o[nt][1] *= al_lo;
            o[nt][2] *= al_hi; o[nt][3] *= al_hi;
        }

#pragma unroll
        for (int j = 0; j < 4; j++) {
            unsigned Ah_[4] = {ph[2 * j][0], ph[2 * j][1], ph[2 * j + 1][0], ph[2 * j + 1][1]};
            unsigned Al_[4] = {pl[2 * j][0], pl[2 * j][1], pl[2 * j + 1][0], pl[2 * j + 1][1]};
#pragma unroll
            for (int dp = 0; dp < 8; dp++) {
                unsigned vh4[4], vl4[4];
                unsigned voff = (unsigned)(((j * 16 + (lane & 15)) * LDQ
                                            + dp * 16 + ((lane >> 4) << 3)) * 2);
                LDSM4T(vh4, sVh_b + voff);
                LDSM4T(vl4, sVl_b + voff);
                MMA_B2(o[2 * dp],     Ah_, vh4[0], vh4[1]);
                MMA_B2(o[2 * dp],     Ah_, vl4[0], vl4[1]);
                MMA_B2(o[2 * dp],     Al_, vh4[0], vh4[1]);
                MMA_B2(o[2 * dp + 1], Ah_, vh4[2], vh4[3]);
                MMA_B2(o[2 * dp + 1], Ah_, vl4[2], vl4[3]);
                MMA_B2(o[2 * dp + 1], Al_, vh4[2], vh4[3]);
            }
        }
        __syncthreads();
    }

    float inv_lo = 1.0f / l_lo;
    float inv_hi = 1.0f / l_hi;
    const int row_lo = q0 + w * 16 + (lane >> 2);
    const int row_hi = row_lo + 8;
    const int cbase  = h * HEAD_DIM + (lane & 3) * 2;
#pragma unroll
    for (int nt = 0; nt < 16; nt++) {
        int d = cbase + nt * 8;
        float v0 = o[nt][0] * inv_lo, v1 = o[nt][1] * inv_lo;
        float v2 = o[nt][2] * inv_hi, v3 = o[nt][3] * inv_hi;
        __nv_bfloat162 h01 = __floats2bfloat162_rn(v0, v1);
        __nv_bfloat162 h23 = __floats2bfloat162_rn(v2, v3);
        __nv_bfloat162 l01 = __floats2bfloat162_rn(v0 - __bfloat162float(h01.x),
                                                   v1 - __bfloat162float(h01.y));
        __nv_bfloat162 l23 = __floats2bfloat162_rn(v2 - __bfloat162float(h23.x),
                                                   v3 - __bfloat162float(h23.y));
        *(__nv_bfloat162*)(Oh + (size_t)row_lo * INNER + d) = h01;
        *(__nv_bfloat162*)(Ol + (size_t)row_lo * INNER + d) = l01;
        *(__nv_bfloat162*)(Oh + (size_t)row_hi * INNER + d) = h23;
        *(__nv_bfloat162*)(Ol + (size_t)row_hi * INNER + d) = l23;
    }
}

// ---------------- launch ----------------
extern "C" void kernel_launch(void* const* d_in, const int* in_sizes, int n_in,
                              void* d_out, int out_size)
{
    (void)in_sizes; (void)n_in; (void)out_size;
    const float* hid   = (const float*)d_in[0];
    const float* enc   = (const float*)d_in[1];
    const float* ref   = (const float*)d_in[2];
    const float* rcos  = (const float*)d_in[3];
    const float* rsin  = (const float*)d_in[4];
    const float* ccos  = (const float*)d_in[5];
    const float* csin  = (const float*)d_in[6];
    const float* Wq    = (const float*)d_in[7];
    const float* bq    = (const float*)d_in[8];
    const float* Wk    = (const float*)d_in[9];
    const float* bk    = (const float*)d_in[10];
    const float* Wv    = (const float*)d_in[11];
    const float* bv    = (const float*)d_in[12];
    const float* Waq   = (const float*)d_in[13];
    const float* baq   = (const float*)d_in[14];
    const float* Wak   = (const float*)d_in[15];
    const float* bak   = (const float*)d_in[16];
    const float* Wav   = (const float*)d_in[17];
    const float* bav   = (const float*)d_in[18];
    const float* Wout  = (const float*)d_in[19];
    const float* bout  = (const float*)d_in[20];
    const float* Wadd  = (const float*)d_in[21];
    const float* badd  = (const float*)d_in[22];
    const float* nq_w  = (const float*)d_in[23];
    const float* nk_w  = (const float*)d_in[24];
    const float* naq_w = (const float*)d_in[25];
    const float* nak_w = (const float*)d_in[26];
    const float* lkd   = (const float*)d_in[27];
    const float* lku   = (const float*)d_in[28];
    const float* lvd   = (const float*)d_in[29];
    const float* lvu   = (const float*)d_in[30];

    float *q, *k;
    cudaGetSymbolAddress((void**)&q, g_q);
    cudaGetSymbolAddress((void**)&k, g_k);

    __nv_bfloat16 *Wh, *Wl, *Uh, *Ul, *xh, *xl, *th, *tl, *oh, *ol;
    __nv_bfloat16 *qh, *ql, *kh, *kl, *vh, *vl;
    cudaGetSymbolAddress((void**)&Wh, g_Wh);
    cudaGetSymbolAddress((void**)&Wl, g_Wl);
    cudaGetSymbolAddress((void**)&Uh, g_Uh);
    cudaGetSymbolAddress((void**)&Ul, g_Ul);
    cudaGetSymbolAddress((void**)&xh, g_xh);
    cudaGetSymbolAddress((void**)&xl, g_xl);
    cudaGetSymbolAddress((void**)&th, g_th);
    cudaGetSymbolAddress((void**)&tl, g_tl);
    cudaGetSymbolAddress((void**)&oh, g_oh);
    cudaGetSymbolAddress((void**)&ol, g_ol);
    cudaGetSymbolAddress((void**)&qh, g_qh);
    cudaGetSymbolAddress((void**)&ql, g_ql);
    cudaGetSymbolAddress((void**)&kh, g_kh);
    cudaGetSymbolAddress((void**)&kl, g_kl);
    cudaGetSymbolAddress((void**)&vh, g_vh);
    cudaGetSymbolAddress((void**)&vl, g_vl);

    cudaFuncSetAttribute(gemm_bf16x3_kernel, cudaFuncAttributeMaxDynamicSharedMemorySize,
                         GEMM_SMEM_BYTES);
    cudaFuncSetAttribute(attn_bf16_kernel, cudaFuncAttributeMaxDynamicSharedMemorySize,
                         ATTN_SMEM_BYTES);

    auto split = [](const float* src, __nv_bfloat16* h, __nv_bfloat16* l, size_t n) {
        split_kernel<<<(unsigned)(n >> 12), 256>>>(src, h, l);
    };
    auto gemmF = [](const __nv_bfloat16* Ah, const __nv_bfloat16* Al,
                    const __nv_bfloat16* Bh, const __nv_bfloat16* Bl,
                    const float* bi, float* C, int M, int N, int K) {
        dim3 grid(N / 128, M / 128);
        gemm_bf16x3_kernel<<<grid, 256, GEMM_SMEM_BYTES>>>(Ah, Al, Bh, Bl, bi, C,
                                                           nullptr, nullptr, M, N, K);
    };
    auto gemmB = [](const __nv_bfloat16* Ah, const __nv_bfloat16* Al,
                    const __nv_bfloat16* Bh, const __nv_bfloat16* Bl,
                    const float* bi, __nv_bfloat16* Ch, __nv_bfloat16* Cl,
                    int M, int N, int K) {
        dim3 grid(N / 128, M / 128);
        gemm_bf16x3_kernel<<<grid, 256, GEMM_SMEM_BYTES>>>(Ah, Al, Bh, Bl, bi, nullptr,
                                                           Ch, Cl, M, N, K);
    };

    const size_t WSZ = (size_t)INNER * INNER;
    const size_t USZ = (size_t)INNER * RANK;
    const size_t off_hid = 0;
    const size_t off_enc = (size_t)S_IMG * INNER;
    const size_t off_ref = (size_t)(S_IMG + S_TXT) * INNER;

    // --- first 5 launches: minimal deps for the big GEMM; launch 6 = big GEMM
    // (ncu captures launch 6 with -s 5 -c 1 -> we finally profile the GEMM)
    split(Wq,   Wh + 1 * WSZ, Wl + 1 * WSZ, WSZ);                       // L1
    split(hid,  xh + off_hid, xl + off_hid, (size_t)S_IMG * INNER);     // L2
    split(Waq,  Wh + 0 * WSZ, Wl + 0 * WSZ, WSZ);                       // L3
    split(enc,  xh + off_enc, xl + off_enc, (size_t)S_TXT * INNER);     // L4
    split(ref,  xh + off_ref, xl + off_ref, (size_t)S_REF * INNER);     // L5
    gemmF(xh + off_hid, xl + off_hid, Wh + 1 * WSZ, Wl + 1 * WSZ, bq,   // L6 (profiled)
          q + (size_t)S_TXT * INNER, S_IMG, INNER, INNER);

    split(Wak,  Wh + 2 * WSZ, Wl + 2 * WSZ, WSZ);
    split(Wk,   Wh + 3 * WSZ, Wl + 3 * WSZ, WSZ);
    split(Wav,  Wh + 4 * WSZ, Wl + 4 * WSZ, WSZ);
    split(Wv,   Wh + 5 * WSZ, Wl + 5 * WSZ, WSZ);
    split(Wout, Wh + 6 * WSZ, Wl + 6 * WSZ, WSZ);
    split(Wadd, Wh + 7 * WSZ, Wl + 7 * WSZ, WSZ);
    split(lkd,  Uh + 0 * USZ, Ul + 0 * USZ, USZ);
    split(lvd,  Uh + 1 * USZ, Ul + 1 * USZ, USZ);
    split(lku,  Uh + 2 * USZ, Ul + 2 * USZ, USZ);
    split(lvu,  Uh + 3 * USZ, Ul + 3 * USZ, USZ);

    gemmF(xh + off_enc, xl + off_enc, Wh + 0 * WSZ, Wl + 0 * WSZ, baq, q,                         S_TXT, INNER, INNER);
    gemmF(xh + off_enc, xl + off_enc, Wh + 2 * WSZ, Wl + 2 * WSZ, bak, k,                         S_TXT, INNER, INNER);
    gemmF(xh + off_hid, xl + off_hid, Wh + 3 * WSZ, Wl + 3 * WSZ, bk,  k + (size_t)S_TXT * INNER, S_IMG, INNER, INNER);
    // v projections write bf16 hi/lo directly (with bias)
    gemmB(xh + off_enc, xl + off_enc, Wh + 4 * WSZ, Wl + 4 * WSZ, bav, vh, vl,                    S_TXT, INNER, INNER);
    gemmB(xh + off_hid, xl + off_hid, Wh + 5 * WSZ, Wl + 5 * WSZ, bv,
          vh + (size_t)S_TXT * INNER, vl + (size_t)S_TXT * INNER,                                 S_IMG, INNER, INNER);

    // LoRA ref branch: down emits bf16 pair, up consumes it
    gemmB(xh + off_ref, xl + off_ref, Uh + 0 * USZ, Ul + 0 * USZ, nullptr, th, tl, S_REF, RANK, INNER);
    gemmF(th, tl, Uh + 2 * USZ, Ul + 2 * USZ, nullptr, k + (size_t)SQ * INNER, S_REF, INNER, RANK);
    gemmB(xh + off_ref, xl + off_ref, Uh + 1 * USZ, Ul + 1 * USZ, nullptr, th, tl, S_REF, RANK, INNER);
    gemmB(th, tl, Uh + 3 * USZ, Ul + 3 * USZ, nullptr,
          vh + (size_t)SQ * INNER, vl + (size_t)SQ * INNER, S_REF, INNER, RANK);

    // RMSNorm + RoPE -> bf16 hi/lo attention inputs
    rmsnorm_rope_split_kernel<<<dim3(SQ, HEADS), 128>>>(q, qh, ql, naq_w, nq_w, S_TXT, rcos, rsin, 1e-6f);
    rmsnorm_rope_split_kernel<<<dim3(SQ, HEADS), 128>>>(k, kh, kl, nak_w, nk_w, S_TXT, rcos, rsin, 1e-6f);
    rmsnorm_rope_split_kernel<<<dim3(S_REF, HEADS), 128>>>(
        k + (size_t)SQ * INNER, kh + (size_t)SQ * INNER, kl + (size_t)SQ * INNER,
        nullptr, nullptr, 0, ccos, csin, 1e-5f);

    attn_bf16_kernel<<<dim3(SQ / 128, HEADS), 256, ATTN_SMEM_BYTES>>>(
        qh, ql, kh, kl, vh, vl, oh, ol);

    float* outp = (float*)d_out;
    gemmF(oh + (size_t)S_TXT * INNER, ol + (size_t)S_TXT * INNER,
          Wh + 6 * WSZ, Wl + 6 * WSZ, bout, outp, S_IMG, INNER, INNER);
    gemmF(oh, ol, Wh + 7 * WSZ, Wl + 7 * WSZ, badd,
          outp + (size_t)S_IMG * INNER, S_TXT, INNER, INNER);
}

// round 8
// speedup vs baseline: 1.1710x; 1.1710x over previous
#include <cuda_runtime.h>
#include <cuda_bf16.h>
#include <cuda_fp16.h>
#include <cstdint>
#include <cstddef>

#define HEADS 24
#define HEAD_DIM 128
#define INNER 3072
#define RANK 1024
#define S_IMG 2048
#define S_TXT 512
#define S_REF 2048
#define SQ (S_TXT + S_IMG)          // 2560
#define SK (S_TXT + S_IMG + S_REF)  // 4608

// ---------------- scratch (device globals; no allocation) ----------------
__device__ float g_q[(size_t)SQ * INNER];
__device__ float g_k[(size_t)SK * INNER];

__device__ __half g_W16h[(size_t)8 * INNER * INNER];
__device__ __half g_W16l[(size_t)8 * INNER * INNER];
__device__ __half g_U16h[(size_t)4 * INNER * RANK];
__device__ __half g_U16l[(size_t)4 * INNER * RANK];
__device__ __half g_x16[(size_t)(S_IMG + S_TXT + S_REF) * INNER];
__device__ __half g_t16[(size_t)S_REF * RANK];
__device__ __half g_o16[(size_t)SQ * INNER];
__device__ __nv_bfloat16 g_qh[(size_t)SQ * INNER];
__device__ __nv_bfloat16 g_ql[(size_t)SQ * INNER];
__device__ __nv_bfloat16 g_kh[(size_t)SK * INNER];
__device__ __nv_bfloat16 g_kl[(size_t)SK * INNER];
__device__ __nv_bfloat16 g_vh[(size_t)SK * INNER];
__device__ __nv_bfloat16 g_vl[(size_t)SK * INNER];

// ---------------- fp32 -> fp16 convert (16 elems/thread) ----------------
__global__ void cvt16_kernel(const float* __restrict__ x, __half* __restrict__ y)
{
    size_t base = ((size_t)blockIdx.x * 256 + threadIdx.x) * 16;
#pragma unroll
    for (int u = 0; u < 4; u++) {
        float4 v = *(const float4*)(x + base + u * 4);
        __half2* yp = (__half2*)(y + base + u * 4);
        yp[0] = __floats2half2_rn(v.x, v.y);
        yp[1] = __floats2half2_rn(v.z, v.w);
    }
}

// ---------------- fp32 -> fp16 hi/lo split (weights) ----------------
__global__ void splitw_kernel(const float* __restrict__ x,
                              __half* __restrict__ h, __half* __restrict__ l)
{
    size_t base = ((size_t)blockIdx.x * 256 + threadIdx.x) * 16;
#pragma unroll
    for (int u = 0; u < 4; u++) {
        float4 v = *(const float4*)(x + base + u * 4);
        __half h0 = __float2half_rn(v.x), h1 = __float2half_rn(v.y);
        __half h2 = __float2half_rn(v.z), h3 = __float2half_rn(v.w);
        __half l0 = __float2half_rn(v.x - __half2float(h0));
        __half l1 = __float2half_rn(v.y - __half2float(h1));
        __half l2 = __float2half_rn(v.z - __half2float(h2));
        __half l3 = __float2half_rn(v.w - __half2float(h3));
        __half2* hp = (__half2*)(h + base + u * 4);
        hp[0] = __half2{h0, h1}; hp[1] = __half2{h2, h3};
        __half2* lp = (__half2*)(l + base + u * 4);
        lp[0] = __half2{l0, l1}; lp[1] = __half2{l2, l3};
    }
}

// ---------------- ptx helpers ----------------
#define LDSM4(R, addr) \
    asm volatile("ldmatrix.sync.aligned.m8n8.x4.shared.b16 {%0,%1,%2,%3},[%4];" \
        : "=r"((R)[0]), "=r"((R)[1]), "=r"((R)[2]), "=r"((R)[3]) : "r"(addr))
#define LDSM4T(R, addr) \
    asm volatile("ldmatrix.sync.aligned.m8n8.x4.trans.shared.b16 {%0,%1,%2,%3},[%4];" \
        : "=r"((R)[0]), "=r"((R)[1]), "=r"((R)[2]), "=r"((R)[3]) : "r"(addr))
#define MMA_F16(C, A, B) \
    asm volatile("mma.sync.aligned.m16n8k16.row.col.f32.f16.f16.f32 " \
        "{%0,%1,%2,%3},{%4,%5,%6,%7},{%8,%9},{%0,%1,%2,%3};" \
        : "+f"((C)[0]), "+f"((C)[1]), "+f"((C)[2]), "+f"((C)[3]) \
        : "r"((A)[0]), "r"((A)[1]), "r"((A)[2]), "r"((A)[3]), "r"((B)[0]), "r"((B)[1]))
#define MMA_B2(C, A, B0, B1) \
    asm volatile("mma.sync.aligned.m16n8k16.row.col.f32.bf16.bf16.f32 " \
        "{%0,%1,%2,%3},{%4,%5,%6,%7},{%8,%9},{%0,%1,%2,%3};" \
        : "+f"((C)[0]), "+f"((C)[1]), "+f"((C)[2]), "+f"((C)[3]) \
        : "r"((A)[0]), "r"((A)[1]), "r"((A)[2]), "r"((A)[3]), "r"(B0), "r"(B1))

__device__ __forceinline__ void cp16(const void* dst, const void* src) {
    unsigned d = (unsigned)__cvta_generic_to_shared(dst);
    asm volatile("cp.async.cg.shared.global [%0],[%1],16;" :: "r"(d), "l"(src));
}
#define CP_COMMIT() asm volatile("cp.async.commit_group;")
#define CP_WAIT0()  asm volatile("cp.async.wait_group 0;")
#define CP_WAIT1()  asm volatile("cp.async.wait_group 1;")

// ---------------- fp16x2 split-precision GEMM (3-stage cp.async) ---------
// C[M,N] = A16[M,K] @ (Bh+Bl)[K,N] (+bias). 2 MMA terms, fp32 accum.
#define A_LD 40
#define B_LD 136
#define SA_ELEMS (128 * A_LD)
#define SB_ELEMS (32 * B_LD)
#define GSTAGE_ELEMS (SA_ELEMS + 2 * SB_ELEMS)
#define GEMM_SMEM_BYTES (GSTAGE_ELEMS * 3 * 2)

__global__ __launch_bounds__(256, 1) void gemm_fp16x2_kernel(
    const __half* __restrict__ A,
    const __half* __restrict__ Bh, const __half* __restrict__ Bl,
    const float* __restrict__ bias,
    float* __restrict__ Cf,
    __nv_bfloat16* __restrict__ Ch, __nv_bfloat16* __restrict__ Cl,
    __half* __restrict__ C16,
    int M, int N, int K)
{
    extern __shared__ __half dsm[];

    const int tid  = threadIdx.x;
    const int lane = tid & 31;
    const int wid  = tid >> 5;
    const int wm   = wid & 3;
    const int wn   = wid >> 2;
    const int bm   = blockIdx.y * 128;
    const int bn   = blockIdx.x * 128;

    const int ar = tid >> 1;            // 0..127
    const int ac = (tid & 1) * 16;      // 0 or 16
    const int br = tid >> 4;            // 0..15
    const int bc = (tid & 15) * 8;      // 0..120

    float c[2][8][4];
#pragma unroll
    for (int mi = 0; mi < 2; mi++)
#pragma unroll
        for (int ni = 0; ni < 8; ni++)
#pragma unroll
            for (int r = 0; r < 4; r++) c[mi][ni][r] = 0.f;

    const int iters = K >> 5;

    auto load_stage = [&](int s, int it) {
        int k0 = it << 5;
        __half* st  = dsm + s * GSTAGE_ELEMS;
        __half* pA  = st;
        __half* pBh = st + SA_ELEMS;
        __half* pBl = pBh + SB_ELEMS;
        cp16(pA + ar * A_LD + ac,      A + (size_t)(bm + ar) * K + k0 + ac);
        cp16(pA + ar * A_LD + ac + 8,  A + (size_t)(bm + ar) * K + k0 + ac + 8);
        cp16(pBh + br * B_LD + bc,        Bh + (size_t)(k0 + br) * N + bn + bc);
        cp16(pBh + (br + 16) * B_LD + bc, Bh + (size_t)(k0 + br + 16) * N + bn + bc);
        cp16(pBl + br * B_LD + bc,        Bl + (size_t)(k0 + br) * N + bn + bc);
        cp16(pBl + (br + 16) * B_LD + bc, Bl + (size_t)(k0 + br + 16) * N + bn + bc);
    };

    load_stage(0, 0); CP_COMMIT();
    load_stage(1, 1); CP_COMMIT();

    for (int it = 0; it < iters; it++) {
        if (it == iters - 1) { CP_WAIT0(); } else { CP_WAIT1(); }
        __syncthreads();
        if (it + 2 < iters) { load_stage((it + 2) % 3, it + 2); CP_COMMIT(); }

        const __half* st = dsm + (it % 3) * GSTAGE_ELEMS;
        const unsigned sA_b  = (unsigned)__cvta_generic_to_shared(st);
        const unsigned sBh_b = sA_b + SA_ELEMS * 2;
        const unsigned sBl_b = sBh_b + SB_ELEMS * 2;

#pragma unroll
        for (int kh = 0; kh < 2; kh++) {
            unsigned af[2][4];
#pragma unroll
            for (int mi = 0; mi < 2; mi++) {
                unsigned off = (unsigned)(((wm * 32 + mi * 16 + (lane & 15)) * A_LD
                                           + kh * 16 + ((lane >> 4) << 3)) * 2);
                LDSM4(af[mi], sA_b + off);
            }
#pragma unroll
            for (int p = 0; p < 4; p++) {
                unsigned bh[4], bl[4];
                unsigned off = (unsigned)(((kh * 16 + (lane & 15)) * B_LD
                                           + wn * 64 + p * 16 + ((lane >> 4) << 3)) * 2);
                LDSM4T(bh, sBh_b + off);
                LDSM4T(bl, sBl_b + off);
#pragma unroll
                for (int mi = 0; mi < 2; mi++) {
                    MMA_F16(c[mi][2 * p],     af[mi], bh);
                    MMA_F16(c[mi][2 * p + 1], af[mi], bh + 2);
                    MMA_F16(c[mi][2 * p],     af[mi], bl);
                    MMA_F16(c[mi][2 * p + 1], af[mi], bl + 2);
                }
            }
        }
    }

    const int row0 = bm + wm * 32 + (lane >> 2);
    const int col0 = bn + wn * 64 + (lane & 3) * 2;
#pragma unroll
    for (int mi = 0; mi < 2; mi++) {
#pragma unroll
        for (int ni = 0; ni < 8; ni++) {
            int r  = row0 + mi * 16;
            int cc = col0 + ni * 8;
            float b0 = bias ? bias[cc] : 0.f;
            float b1 = bias ? bias[cc + 1] : 0.f;
            float v0 = c[mi][ni][0] + b0, v1 = c[mi][ni][1] + b1;
            float v2 = c[mi][ni][2] + b0, v3 = c[mi][ni][3] + b1;
            if (Cf) {
                *(float2*)(Cf + (size_t)r * N + cc)       = float2{v0, v1};
                *(float2*)(Cf + (size_t)(r + 8) * N + cc) = float2{v2, v3};
            } else if (Ch) {
                __nv_bfloat162 h01 = __floats2bfloat162_rn(v0, v1);
                __nv_bfloat162 h23 = __floats2bfloat162_rn(v2, v3);
                __nv_bfloat162 l01 = __floats2bfloat162_rn(v0 - __bfloat162float(h01.x),
                                                           v1 - __bfloat162float(h01.y));
                __nv_bfloat162 l23 = __floats2bfloat162_rn(v2 - __bfloat162float(h23.x),
                                                           v3 - __bfloat162float(h23.y));
                *(__nv_bfloat162*)(Ch + (size_t)r * N + cc)       = h01;
                *(__nv_bfloat162*)(Cl + (size_t)r * N + cc)       = l01;
                *(__nv_bfloat162*)(Ch + (size_t)(r + 8) * N + cc) = h23;
                *(__nv_bfloat162*)(Cl + (size_t)(r + 8) * N + cc) = l23;
            } else {
                *(__half2*)(C16 + (size_t)r * N + cc)       = __floats2half2_rn(v0, v1);
                *(__half2*)(C16 + (size_t)(r + 8) * N + cc) = __floats2half2_rn(v2, v3);
            }
        }
    }
}

// ---------------- fused RMSNorm + RoPE -> bf16 hi/lo split ----------------
__global__ void rmsnorm_rope_split_kernel(
    const float* __restrict__ src,
    __nv_bfloat16* __restrict__ outh, __nv_bfloat16* __restrict__ outl,
    const float* __restrict__ w0, const float* __restrict__ w1, int split,
    const float* __restrict__ cos_t, const float* __restrict__ sin_t,
    float eps)
{
    const int row = blockIdx.x;
    const int h   = blockIdx.y;
    const int d   = threadIdx.x;

    const float* x = src + (size_t)row * INNER + h * HEAD_DIM;
    float v = x[d];
    float ss = v * v;
#pragma unroll
    for (int o = 16; o; o >>= 1) ss += __shfl_xor_sync(0xffffffffu, ss, o);
    __shared__ float red[4];
    if ((d & 31) == 0) red[d >> 5] = ss;
    __syncthreads();
    float tot = red[0] + red[1] + red[2] + red[3];
    float r = rsqrtf(tot * (1.0f / HEAD_DIM) + eps);

    const float* w = (row < split) ? w0 : w1;
    float y = v * r;
    if (w) y *= w[d];

    float other = __shfl_xor_sync(0xffffffffu, y, 1);
    float c = cos_t[(size_t)row * HEAD_DIM + d];
    float s = sin_t[(size_t)row * HEAD_DIM + d];
    float rot = (d & 1) ? other : -other;
    float out = y * c + rot * s;

    __nv_bfloat16 hv = __float2bfloat16(out);
    __nv_bfloat16 lv = __float2bfloat16(out - __bfloat162float(hv));
    size_t idx = (size_t)row * INNER + h * HEAD_DIM + d;
    outh[idx] = hv;
    outl[idx] = lv;
}

// ---------------- tensor-core flash attention (bf16x3, cp.async KV) ------
#define LDQ 136
#define Q_ELEMS (128 * LDQ)
#define KV_ELEMS (64 * LDQ)
#define KVSTAGE_ELEMS (4 * KV_ELEMS)
#define ATTN_SMEM_BYTES ((2 * Q_ELEMS + 2 * KVSTAGE_ELEMS) * 2)

__global__ __launch_bounds__(256, 1) void attn_bf16_kernel(
    const __nv_bfloat16* __restrict__ Qh, const __nv_bfloat16* __restrict__ Ql,
    const __nv_bfloat16* __restrict__ Kh, const __nv_bfloat16* __restrict__ Kl,
    const __nv_bfloat16* __restrict__ Vh, const __nv_bfloat16* __restrict__ Vl,
    __half* __restrict__ O16)
{
    extern __shared__ __nv_bfloat16 smb[];
    __nv_bfloat16* sQh = smb;
    __nv_bfloat16* sQl = sQh + Q_ELEMS;
    __nv_bfloat16* kvBase = sQl + Q_ELEMS;

    const int h    = blockIdx.y;
    const int q0   = blockIdx.x * 128;
    const int tid  = threadIdx.x;
    const int lane = tid & 31;
    const int w    = tid >> 5;
    const float scale = 0.08838834764831845f;

    const unsigned sQh_b = (unsigned)__cvta_generic_to_shared(sQh);
    const unsigned sQl_b = sQh_b + Q_ELEMS * 2;

    const int krow = tid >> 2;
    const int kcol = (tid & 3) * 32;

    auto load_kv = [&](int s, int kt) {
        __nv_bfloat16* st = kvBase + s * KVSTAGE_ELEMS;
        __nv_bfloat16* pKh = st;
        __nv_bfloat16* pKl = st + KV_ELEMS;
        __nv_bfloat16* pVh = st + 2 * KV_ELEMS;
        __nv_bfloat16* pVl = st + 3 * KV_ELEMS;
#pragma unroll
        for (int seg = 0; seg < 4; seg++) {
            int cc = kcol + seg * 8;
            size_t g = (size_t)(kt * 64 + krow) * INNER + h * HEAD_DIM + cc;
            cp16(pKh + krow * LDQ + cc, Kh + g);
            cp16(pKl + krow * LDQ + cc, Kl + g);
            cp16(pVh + krow * LDQ + cc, Vh + g);
            cp16(pVl + krow * LDQ + cc, Vl + g);
        }
    };

    load_kv(0, 0); CP_COMMIT();

    for (int i = tid; i < 128 * 16; i += 256) {
        int row = i >> 4;
        int c8  = (i & 15) * 8;
        size_t g = (size_t)(q0 + row) * INNER + h * HEAD_DIM + c8;
        *(uint4*)(sQh + row * LDQ + c8) = *(const uint4*)(Qh + g);
        *(uint4*)(sQl + row * LDQ + c8) = *(const uint4*)(Ql + g);
    }

    float o[16][4];
#pragma unroll
    for (int nt = 0; nt < 16; nt++)
#pragma unroll
        for (int r = 0; r < 4; r++) o[nt][r] = 0.f;
    float m_lo = -1e30f, m_hi = -1e30f, l_lo = 0.f, l_hi = 0.f;

    const int NT = SK / 64;
    for (int kt = 0; kt < NT; kt++) {
        CP_WAIT0();
        __syncthreads();
        if (kt + 1 < NT) { load_kv((kt + 1) & 1, kt + 1); CP_COMMIT(); }

        const __nv_bfloat16* st = kvBase + (kt & 1) * KVSTAGE_ELEMS;
        const unsigned sKh_b = (unsigned)__cvta_generic_to_shared(st);
        const unsigned sKl_b = sKh_b + KV_ELEMS * 2;
        const unsigned sVh_b = sKh_b + 2 * KV_ELEMS * 2;
        const unsigned sVl_b = sKh_b + 3 * KV_ELEMS * 2;

        float c[8][4];
#pragma unroll
        for (int n = 0; n < 8; n++)
#pragma unroll
            for (int r = 0; r < 4; r++) c[n][r] = 0.f;

#pragma unroll
        for (int kk = 0; kk < 8; kk++) {
            unsigned ah[4], al[4];
            unsigned qoff = (unsigned)(((w * 16 + (lane & 15)) * LDQ
                                        + kk * 16 + ((lane >> 4) << 3)) * 2);
            LDSM4(ah, sQh_b + qoff);
            LDSM4(al, sQl_b + qoff);
#pragma unroll
            for (int ng = 0; ng < 4; ng++) {
                unsigned bh[4], bl[4];
                unsigned koff = (unsigned)(((ng * 16 + (lane & 15)) * LDQ
                                            + kk * 16 + ((lane >> 4) << 3)) * 2);
                LDSM4(bh, sKh_b + koff);
                LDSM4(bl, sKl_b + koff);
                MMA_B2(c[2 * ng],     ah, bh[0], bh[2]);
                MMA_B2(c[2 * ng],     ah, bl[0], bl[2]);
                MMA_B2(c[2 * ng],     al, bh[0], bh[2]);
                MMA_B2(c[2 * ng + 1], ah, bh[1], bh[3]);
                MMA_B2(c[2 * ng + 1], ah, bl[1], bl[3]);
                MMA_B2(c[2 * ng + 1], al, bh[1], bh[3]);
            }
        }

        float tmx_lo = -1e30f, tmx_hi = -1e30f;
#pragma unroll
        for (int n = 0; n < 8; n++) {
            c[n][0] *= scale; c[n][1] *= scale; c[n][2] *= scale; c[n][3] *= scale;
            tmx_lo = fmaxf(tmx_lo, fmaxf(c[n][0], c[n][1]));
            tmx_hi = fmaxf(tmx_hi, fmaxf(c[n][2], c[n][3]));
        }
        tmx_lo = fmaxf(tmx_lo, __shfl_xor_sync(0xffffffffu, tmx_lo, 1));
        tmx_lo = fmaxf(tmx_lo, __shfl_xor_sync(0xffffffffu, tmx_lo, 2));
        tmx_hi = fmaxf(tmx_hi, __shfl_xor_sync(0xffffffffu, tmx_hi, 1));
        tmx_hi = fmaxf(tmx_hi, __shfl_xor_sync(0xffffffffu, tmx_hi, 2));

        float mn_lo = fmaxf(m_lo, tmx_lo);
        float mn_hi = fmaxf(m_hi, tmx_hi);
        float al_lo = __expf(m_lo - mn_lo);
        float al_hi = __expf(m_hi - mn_hi);
        m_lo = mn_lo; m_hi = mn_hi;

        unsigned ph[8][2], pl[8][2];
        float sum_lo = 0.f, sum_hi = 0.f;
#pragma unroll
        for (int n = 0; n < 8; n++) {
            float p0 = __expf(c[n][0] - m_lo);
            float p1 = __expf(c[n][1] - m_lo);
            float p2 = __expf(c[n][2] - m_hi);
            float p3 = __expf(c[n][3] - m_hi);
            sum_lo += p0 + p1;
            sum_hi += p2 + p3;
            __nv_bfloat162 h01 = __floats2bfloat162_rn(p0, p1);
            __nv_bfloat162 h23 = __floats2bfloat162_rn(p2, p3);
            __nv_bfloat162 l01 = __floats2bfloat162_rn(p0 - __bfloat162float(h01.x),
                                                       p1 - __bfloat162float(h01.y));
            __nv_bfloat162 l23 = __floats2bfloat162_rn(p2 - __bfloat162float(h23.x),
                                                       p3 - __bfloat162float(h23.y));
            ph[n][0] = *(unsigned*)&h01; ph[n][1] = *(unsigned*)&h23;
            pl[n][0] = *(unsigned*)&l01; pl[n][1] = *(unsigned*)&l23;
        }
        sum_lo += __shfl_xor_sync(0xffffffffu, sum_lo, 1);
        sum_lo += __shfl_xor_sync(0xffffffffu, sum_lo, 2);
        sum_hi += __shfl_xor_sync(0xffffffffu, sum_hi, 1);
        sum_hi += __shfl_xor_sync(0xffffffffu, sum_hi, 2);
        l_lo = l_lo * al_lo + sum_lo;
        l_hi = l_hi * al_hi + sum_hi;

#pragma unroll
        for (int nt = 0; nt < 16; nt++) {
            o[nt][0] *= al_lo; o[nt][1] *= al_lo;
            o[nt][2] *= al_hi; o[nt][3] *= al_hi;
        }

#pragma unroll
        for (int j = 0; j < 4; j++) {
            unsigned Ah_[4] = {ph[2 * j][0], ph[2 * j][1], ph[2 * j + 1][0], ph[2 * j + 1][1]};
            unsigned Al_[4] = {pl[2 * j][0], pl[2 * j][1], pl[2 * j + 1][0], pl[2 * j + 1][1]};
#pragma unroll
            for (int dp = 0; dp < 8; dp++) {
                unsigned vh4[4], vl4[4];
                unsigned voff = (unsigned)(((j * 16 + (lane & 15)) * LDQ
                                            + dp * 16 + ((lane >> 4) << 3)) * 2);
                LDSM4T(vh4, sVh_b + voff);
                LDSM4T(vl4, sVl_b + voff);
                MMA_B2(o[2 * dp],     Ah_, vh4[0], vh4[1]);
                MMA_B2(o[2 * dp],     Ah_, vl4[0], vl4[1]);
                MMA_B2(o[2 * dp],     Al_, vh4[0], vh4[1]);
                MMA_B2(o[2 * dp + 1], Ah_, vh4[2], vh4[3]);
                MMA_B2(o[2 * dp + 1], Ah_, vl4[2], vl4[3]);
                MMA_B2(o[2 * dp + 1], Al_, vh4[2], vh4[3]);
            }
        }
        __syncthreads();
    }

    float inv_lo = 1.0f / l_lo;
    float inv_hi = 1.0f / l_hi;
    const int row_lo = q0 + w * 16 + (lane >> 2);
    const int row_hi = row_lo + 8;
    const int cbase  = h * HEAD_DIM + (lane & 3) * 2;
#pragma unroll
    for (int nt = 0; nt < 16; nt++) {
        int d = cbase + nt * 8;
        *(__half2*)(O16 + (size_t)row_lo * INNER + d) =
            __floats2half2_rn(o[nt][0] * inv_lo, o[nt][1] * inv_lo);
        *(__half2*)(O16 + (size_t)row_hi * INNER + d) =
            __floats2half2_rn(o[nt][2] * inv_hi, o[nt][3] * inv_hi);
    }
}

// ---------------- launch ----------------
extern "C" void kernel_launch(void* const* d_in, const int* in_sizes, int n_in,
                              void* d_out, int out_size)
{
    (void)in_sizes; (void)n_in; (void)out_size;
    const float* hid   = (const float*)d_in[0];
    const float* enc   = (const float*)d_in[1];
    const float* ref   = (const float*)d_in[2];
    const float* rcos  = (const float*)d_in[3];
    const float* rsin  = (const float*)d_in[4];
    const float* ccos  = (const float*)d_in[5];
    const float* csin  = (const float*)d_in[6];
    const float* Wq    = (const float*)d_in[7];
    const float* bq    = (const float*)d_in[8];
    const float* Wk    = (const float*)d_in[9];
    const float* bk    = (const float*)d_in[10];
    const float* Wv    = (const float*)d_in[11];
    const float* bv    = (const float*)d_in[12];
    const float* Waq   = (const float*)d_in[13];
    const float* baq   = (const float*)d_in[14];
    const float* Wak   = (const float*)d_in[15];
    const float* bak   = (const float*)d_in[16];
    const float* Wav   = (const float*)d_in[17];
    const float* bav   = (const float*)d_in[18];
    const float* Wout  = (const float*)d_in[19];
    const float* bout  = (const float*)d_in[20];
    const float* Wadd  = (const float*)d_in[21];
    const float* badd  = (const float*)d_in[22];
    const float* nq_w  = (const float*)d_in[23];
    const float* nk_w  = (const float*)d_in[24];
    const float* naq_w = (const float*)d_in[25];
    const float* nak_w = (const float*)d_in[26];
    const float* lkd   = (const float*)d_in[27];
    const float* lku   = (const float*)d_in[28];
    const float* lvd   = (const float*)d_in[29];
    const float* lvu   = (const float*)d_in[30];

    float *q, *k;
    cudaGetSymbolAddress((void**)&q, g_q);
    cudaGetSymbolAddress((void**)&k, g_k);

    __half *Wh, *Wl, *Uh, *Ul, *x16, *t16, *o16;
    __nv_bfloat16 *qh, *ql, *kh, *kl, *vh, *vl;
    cudaGetSymbolAddress((void**)&Wh, g_W16h);
    cudaGetSymbolAddress((void**)&Wl, g_W16l);
    cudaGetSymbolAddress((void**)&Uh, g_U16h);
    cudaGetSymbolAddress((void**)&Ul, g_U16l);
    cudaGetSymbolAddress((void**)&x16, g_x16);
    cudaGetSymbolAddress((void**)&t16, g_t16);
    cudaGetSymbolAddress((void**)&o16, g_o16);
    cudaGetSymbolAddress((void**)&qh, g_qh);
    cudaGetSymbolAddress((void**)&ql, g_ql);
    cudaGetSymbolAddress((void**)&kh, g_kh);
    cudaGetSymbolAddress((void**)&kl, g_kl);
    cudaGetSymbolAddress((void**)&vh, g_vh);
    cudaGetSymbolAddress((void**)&vl, g_vl);

    cudaFuncSetAttribute(gemm_fp16x2_kernel, cudaFuncAttributeMaxDynamicSharedMemorySize,
                         GEMM_SMEM_BYTES);
    cudaFuncSetAttribute(attn_bf16_kernel, cudaFuncAttributeMaxDynamicSharedMemorySize,
                         ATTN_SMEM_BYTES);

    auto cvt = [](const float* src, __half* dst, size_t n) {
        cvt16_kernel<<<(unsigned)(n >> 12), 256>>>(src, dst);
    };
    auto splitw = [](const float* src, __half* h, __half* l, size_t n) {
        splitw_kernel<<<(unsigned)(n >> 12), 256>>>(src, h, l);
    };
    auto gemmF = [](const __half* A, const __half* Bh, const __half* Bl,
                    const float* bi, float* C, int M, int N, int K) {
        dim3 grid(N / 128, M / 128);
        gemm_fp16x2_kernel<<<grid, 256, GEMM_SMEM_BYTES>>>(
            A, Bh, Bl, bi, C, nullptr, nullptr, nullptr, M, N, K);
    };
    auto gemmB = [](const __half* A, const __half* Bh, const __half* Bl,
                    const float* bi, __nv_bfloat16* Ch, __nv_bfloat16* Cl,
                    int M, int N, int K) {
        dim3 grid(N / 128, M / 128);
        gemm_fp16x2_kernel<<<grid, 256, GEMM_SMEM_BYTES>>>(
            A, Bh, Bl, bi, nullptr, Ch, Cl, nullptr, M, N, K);
    };
    auto gemmH = [](const __half* A, const __half* Bh, const __half* Bl,
                    const float* bi, __half* C16, int M, int N, int K) {
        dim3 grid(N / 128, M / 128);
        gemm_fp16x2_kernel<<<grid, 256, GEMM_SMEM_BYTES>>>(
            A, Bh, Bl, bi, nullptr, nullptr, nullptr, C16, M, N, K);
    };

    const size_t WSZ = (size_t)INNER * INNER;
    const size_t USZ = (size_t)INNER * RANK;
    const size_t off_hid = 0;
    const size_t off_enc = (size_t)S_IMG * INNER;
    const size_t off_ref = (size_t)(S_IMG + S_TXT) * INNER;

    // L1-L5: deps for the big GEMM; L6 = big GEMM (profiled by ncu -s 5 -c 1)
    cvt(hid, x16 + off_hid, (size_t)S_IMG * INNER);                     // L1
    splitw(Wq, Wh + 1 * WSZ, Wl + 1 * WSZ, WSZ);                        // L2
    cvt(enc, x16 + off_enc, (size_t)S_TXT * INNER);                     // L3
    cvt(ref, x16 + off_ref, (size_t)S_REF * INNER);                     // L4
    splitw(Waq, Wh + 0 * WSZ, Wl + 0 * WSZ, WSZ);                       // L5
    gemmF(x16 + off_hid, Wh + 1 * WSZ, Wl + 1 * WSZ, bq,                // L6
          q + (size_t)S_TXT * INNER, S_IMG, INNER, INNER);

    splitw(Wak,  Wh + 2 * WSZ, Wl + 2 * WSZ, WSZ);
    splitw(Wk,   Wh + 3 * WSZ, Wl + 3 * WSZ, WSZ);
    splitw(Wav,  Wh + 4 * WSZ, Wl + 4 * WSZ, WSZ);
    splitw(Wv,   Wh + 5 * WSZ, Wl + 5 * WSZ, WSZ);
    splitw(Wout, Wh + 6 * WSZ, Wl + 6 * WSZ, WSZ);
    splitw(Wadd, Wh + 7 * WSZ, Wl + 7 * WSZ, WSZ);
    splitw(lkd,  Uh + 0 * USZ, Ul + 0 * USZ, USZ);
    splitw(lvd,  Uh + 1 * USZ, Ul + 1 * USZ, USZ);
    splitw(lku,  Uh + 2 * USZ, Ul + 2 * USZ, USZ);
    splitw(lvu,  Uh + 3 * USZ, Ul + 3 * USZ, USZ);

    gemmF(x16 + off_enc, Wh + 0 * WSZ, Wl + 0 * WSZ, baq, q,                         S_TXT, INNER, INNER);
    gemmF(x16 + off_enc, Wh + 2 * WSZ, Wl + 2 * WSZ, bak, k,                         S_TXT, INNER, INNER);
    gemmF(x16 + off_hid, Wh + 3 * WSZ, Wl + 3 * WSZ, bk,  k + (size_t)S_TXT * INNER, S_IMG, INNER, INNER);
    gemmB(x16 + off_enc, Wh + 4 * WSZ, Wl + 4 * WSZ, bav, vh, vl,                    S_TXT, INNER, INNER);
    gemmB(x16 + off_hid, Wh + 5 * WSZ, Wl + 5 * WSZ, bv,
          vh + (size_t)S_TXT * INNER, vl + (size_t)S_TXT * INNER,                    S_IMG, INNER, INNER);

    // LoRA ref branch
    gemmH(x16 + off_ref, Uh + 0 * USZ, Ul + 0 * USZ, nullptr, t16, S_REF, RANK, INNER);
    gemmF(t16, Uh + 2 * USZ, Ul + 2 * USZ, nullptr, k + (size_t)SQ * INNER, S_REF, INNER, RANK);
    gemmH(x16 + off_ref, Uh + 1 * USZ, Ul + 1 * USZ, nullptr, t16, S_REF, RANK, INNER);
    gemmB(t16, Uh + 3 * USZ, Ul + 3 * USZ, nullptr,
          vh + (size_t)SQ * INNER, vl + (size_t)SQ * INNER, S_REF, INNER, RANK);

    // RMSNorm + RoPE -> bf16 hi/lo attention inputs
    rmsnorm_rope_split_kernel<<<dim3(SQ, HEADS), 128>>>(q, qh, ql, naq_w, nq_w, S_TXT, rcos, rsin, 1e-6f);
    rmsnorm_rope_split_kernel<<<dim3(SQ, HEADS), 128>>>(k, kh, kl, nak_w, nk_w, S_TXT, rcos, rsin, 1e-6f);
    rmsnorm_rope_split_kernel<<<dim3(S_REF, HEADS), 128>>>(
        k + (size_t)SQ * INNER, kh + (size_t)SQ * INNER, kl + (size_t)SQ * INNER,
        nullptr, nullptr, 0, ccos, csin, 1e-5f);

    attn_bf16_kernel<<<dim3(SQ / 128, HEADS), 256, ATTN_SMEM_BYTES>>>(
        qh, ql, kh, kl, vh, vl, o16);

    float* outp = (float*)d_out;
    gemmF(o16 + (size_t)S_TXT * INNER, Wh + 6 * WSZ, Wl + 6 * WSZ, bout,
          outp, S_IMG, INNER, INNER);
    gemmF(o16, Wh + 7 * WSZ, Wl + 7 * WSZ, badd,
          outp + (size_t)S_IMG * INNER, S_TXT, INNER, INNER);
}

// round 9
// speedup vs baseline: 1.2837x; 1.0962x over previous
#include <cuda_runtime.h>
#include <cuda_bf16.h>
#include <cuda_fp16.h>
#include <cstdint>
#include <cstddef>

#define HEADS 24
#define HEAD_DIM 128
#define INNER 3072
#define RANK 1024
#define S_IMG 2048
#define S_TXT 512
#define S_REF 2048
#define SQ (S_TXT + S_IMG)          // 2560
#define SK (S_TXT + S_IMG + S_REF)  // 4608

// ---------------- scratch (device globals; no allocation) ----------------
__device__ float g_q[(size_t)SQ * INNER];
__device__ float g_k[(size_t)SK * INNER];

__device__ __half g_W16h[(size_t)8 * INNER * INNER];
__device__ __half g_W16l[(size_t)8 * INNER * INNER];
__device__ __half g_U16h[(size_t)4 * INNER * RANK];
__device__ __half g_U16l[(size_t)4 * INNER * RANK];
__device__ __half g_x16[(size_t)(S_IMG + S_TXT + S_REF) * INNER];
__device__ __half g_t16[(size_t)S_REF * RANK];
__device__ __half g_o16[(size_t)SQ * INNER];
__device__ __half g_q16[(size_t)SQ * INNER];
__device__ __half g_kh[(size_t)SK * INNER];
__device__ __half g_kl[(size_t)SK * INNER];
__device__ __half g_vh[(size_t)SK * INNER];
__device__ __half g_vl[(size_t)SK * INNER];

// ---------------- fp32 -> fp16 convert (16 elems/thread) ----------------
__global__ void cvt16_kernel(const float* __restrict__ x, __half* __restrict__ y)
{
    size_t base = ((size_t)blockIdx.x * 256 + threadIdx.x) * 16;
#pragma unroll
    for (int u = 0; u < 4; u++) {
        float4 v = *(const float4*)(x + base + u * 4);
        __half2* yp = (__half2*)(y + base + u * 4);
        yp[0] = __floats2half2_rn(v.x, v.y);
        yp[1] = __floats2half2_rn(v.z, v.w);
    }
}

// ---------------- fp32 -> fp16 hi/lo split (weights) ----------------
__global__ void splitw_kernel(const float* __restrict__ x,
                              __half* __restrict__ h, __half* __restrict__ l)
{
    size_t base = ((size_t)blockIdx.x * 256 + threadIdx.x) * 16;
#pragma unroll
    for (int u = 0; u < 4; u++) {
        float4 v = *(const float4*)(x + base + u * 4);
        __half h0 = __float2half_rn(v.x), h1 = __float2half_rn(v.y);
        __half h2 = __float2half_rn(v.z), h3 = __float2half_rn(v.w);
        __half l0 = __float2half_rn(v.x - __half2float(h0));
        __half l1 = __float2half_rn(v.y - __half2float(h1));
        __half l2 = __float2half_rn(v.z - __half2float(h2));
        __half l3 = __float2half_rn(v.w - __half2float(h3));
        __half2* hp = (__half2*)(h + base + u * 4);
        hp[0] = __half2{h0, h1}; hp[1] = __half2{h2, h3};
        __half2* lp = (__half2*)(l + base + u * 4);
        lp[0] = __half2{l0, l1}; lp[1] = __half2{l2, l3};
    }
}

// ---------------- ptx helpers ----------------
#define LDSM4(R, addr) \
    asm volatile("ldmatrix.sync.aligned.m8n8.x4.shared.b16 {%0,%1,%2,%3},[%4];" \
        : "=r"((R)[0]), "=r"((R)[1]), "=r"((R)[2]), "=r"((R)[3]) : "r"(addr))
#define LDSM4T(R, addr) \
    asm volatile("ldmatrix.sync.aligned.m8n8.x4.trans.shared.b16 {%0,%1,%2,%3},[%4];" \
        : "=r"((R)[0]), "=r"((R)[1]), "=r"((R)[2]), "=r"((R)[3]) : "r"(addr))
#define MMA_F16(C, A, B) \
    asm volatile("mma.sync.aligned.m16n8k16.row.col.f32.f16.f16.f32 " \
        "{%0,%1,%2,%3},{%4,%5,%6,%7},{%8,%9},{%0,%1,%2,%3};" \
        : "+f"((C)[0]), "+f"((C)[1]), "+f"((C)[2]), "+f"((C)[3]) \
        : "r"((A)[0]), "r"((A)[1]), "r"((A)[2]), "r"((A)[3]), "r"((B)[0]), "r"((B)[1]))
#define MMA_F16_B2(C, A, B0, B1) \
    asm volatile("mma.sync.aligned.m16n8k16.row.col.f32.f16.f16.f32 " \
        "{%0,%1,%2,%3},{%4,%5,%6,%7},{%8,%9},{%0,%1,%2,%3};" \
        : "+f"((C)[0]), "+f"((C)[1]), "+f"((C)[2]), "+f"((C)[3]) \
        : "r"((A)[0]), "r"((A)[1]), "r"((A)[2]), "r"((A)[3]), "r"(B0), "r"(B1))

__device__ __forceinline__ void cp16(const void* dst, const void* src) {
    unsigned d = (unsigned)__cvta_generic_to_shared(dst);
    asm volatile("cp.async.cg.shared.global [%0],[%1],16;" :: "r"(d), "l"(src));
}
#define CP_COMMIT() asm volatile("cp.async.commit_group;")
#define CP_WAIT0()  asm volatile("cp.async.wait_group 0;")
#define CP_WAIT1()  asm volatile("cp.async.wait_group 1;")

// ---------------- fp16x2 split-precision GEMM (3-stage cp.async) ---------
#define A_LD 40
#define B_LD 136
#define SA_ELEMS (128 * A_LD)
#define SB_ELEMS (32 * B_LD)
#define GSTAGE_ELEMS (SA_ELEMS + 2 * SB_ELEMS)
#define GEMM_SMEM_BYTES (GSTAGE_ELEMS * 3 * 2)

__global__ __launch_bounds__(256, 1) void gemm_fp16x2_kernel(
    const __half* __restrict__ A,
    const __half* __restrict__ Bh, const __half* __restrict__ Bl,
    const float* __restrict__ bias,
    float* __restrict__ Cf,
    __half* __restrict__ Ch, __half* __restrict__ Cl,
    __half* __restrict__ C16,
    int M, int N, int K)
{
    extern __shared__ __half dsm[];

    const int tid  = threadIdx.x;
    const int lane = tid & 31;
    const int wid  = tid >> 5;
    const int wm   = wid & 3;
    const int wn   = wid >> 2;
    const int bm   = blockIdx.y * 128;
    const int bn   = blockIdx.x * 128;

    const int ar = tid >> 1;
    const int ac = (tid & 1) * 16;
    const int br = tid >> 4;
    const int bc = (tid & 15) * 8;

    float c[2][8][4];
#pragma unroll
    for (int mi = 0; mi < 2; mi++)
#pragma unroll
        for (int ni = 0; ni < 8; ni++)
#pragma unroll
            for (int r = 0; r < 4; r++) c[mi][ni][r] = 0.f;

    const int iters = K >> 5;

    auto load_stage = [&](int s, int it) {
        int k0 = it << 5;
        __half* st  = dsm + s * GSTAGE_ELEMS;
        __half* pA  = st;
        __half* pBh = st + SA_ELEMS;
        __half* pBl = pBh + SB_ELEMS;
        cp16(pA + ar * A_LD + ac,      A + (size_t)(bm + ar) * K + k0 + ac);
        cp16(pA + ar * A_LD + ac + 8,  A + (size_t)(bm + ar) * K + k0 + ac + 8);
        cp16(pBh + br * B_LD + bc,        Bh + (size_t)(k0 + br) * N + bn + bc);
        cp16(pBh + (br + 16) * B_LD + bc, Bh + (size_t)(k0 + br + 16) * N + bn + bc);
        cp16(pBl + br * B_LD + bc,        Bl + (size_t)(k0 + br) * N + bn + bc);
        cp16(pBl + (br + 16) * B_LD + bc, Bl + (size_t)(k0 + br + 16) * N + bn + bc);
    };

    load_stage(0, 0); CP_COMMIT();
    load_stage(1, 1); CP_COMMIT();

    for (int it = 0; it < iters; it++) {
        if (it == iters - 1) { CP_WAIT0(); } else { CP_WAIT1(); }
        __syncthreads();
        if (it + 2 < iters) { load_stage((it + 2) % 3, it + 2); CP_COMMIT(); }

        const __half* st = dsm + (it % 3) * GSTAGE_ELEMS;
        const unsigned sA_b  = (unsigned)__cvta_generic_to_shared(st);
        const unsigned sBh_b = sA_b + SA_ELEMS * 2;
        const unsigned sBl_b = sBh_b + SB_ELEMS * 2;

#pragma unroll
        for (int kh = 0; kh < 2; kh++) {
            unsigned af[2][4];
#pragma unroll
            for (int mi = 0; mi < 2; mi++) {
                unsigned off = (unsigned)(((wm * 32 + mi * 16 + (lane & 15)) * A_LD
                                           + kh * 16 + ((lane >> 4) << 3)) * 2);
                LDSM4(af[mi], sA_b + off);
            }
#pragma unroll
            for (int p = 0; p < 4; p++) {
                unsigned bh[4], bl[4];
                unsigned off = (unsigned)(((kh * 16 + (lane & 15)) * B_LD
                                           + wn * 64 + p * 16 + ((lane >> 4) << 3)) * 2);
                LDSM4T(bh, sBh_b + off);
                LDSM4T(bl, sBl_b + off);
#pragma unroll
                for (int mi = 0; mi < 2; mi++) {
                    MMA_F16(c[mi][2 * p],     af[mi], bh);
                    MMA_F16(c[mi][2 * p + 1], af[mi], bh + 2);
                    MMA_F16(c[mi][2 * p],     af[mi], bl);
                    MMA_F16(c[mi][2 * p + 1], af[mi], bl + 2);
                }
            }
        }
    }

    const int row0 = bm + wm * 32 + (lane >> 2);
    const int col0 = bn + wn * 64 + (lane & 3) * 2;
#pragma unroll
    for (int mi = 0; mi < 2; mi++) {
#pragma unroll
        for (int ni = 0; ni < 8; ni++) {
            int r  = row0 + mi * 16;
            int cc = col0 + ni * 8;
            float b0 = bias ? bias[cc] : 0.f;
            float b1 = bias ? bias[cc + 1] : 0.f;
            float v0 = c[mi][ni][0] + b0, v1 = c[mi][ni][1] + b1;
            float v2 = c[mi][ni][2] + b0, v3 = c[mi][ni][3] + b1;
            if (Cf) {
                *(float2*)(Cf + (size_t)r * N + cc)       = float2{v0, v1};
                *(float2*)(Cf + (size_t)(r + 8) * N + cc) = float2{v2, v3};
            } else if (Ch) {
                __half2 h01 = __floats2half2_rn(v0, v1);
                __half2 h23 = __floats2half2_rn(v2, v3);
                __half2 l01 = __floats2half2_rn(v0 - __half2float(h01.x),
                                                v1 - __half2float(h01.y));
                __half2 l23 = __floats2half2_rn(v2 - __half2float(h23.x),
                                                v3 - __half2float(h23.y));
                *(__half2*)(Ch + (size_t)r * N + cc)       = h01;
                *(__half2*)(Cl + (size_t)r * N + cc)       = l01;
                *(__half2*)(Ch + (size_t)(r + 8) * N + cc) = h23;
                *(__half2*)(Cl + (size_t)(r + 8) * N + cc) = l23;
            } else {
                *(__half2*)(C16 + (size_t)r * N + cc)       = __floats2half2_rn(v0, v1);
                *(__half2*)(C16 + (size_t)(r + 8) * N + cc) = __floats2half2_rn(v2, v3);
            }
        }
    }
}

// ------ fused RMSNorm + RoPE -> single fp16 (Q) or fp16 hi/lo (K) --------
__global__ void rmsnorm_rope_out_kernel(
    const float* __restrict__ src,
    __half* __restrict__ outh, __half* __restrict__ outl,   // outl==nullptr -> single
    const float* __restrict__ w0, const float* __restrict__ w1, int split,
    const float* __restrict__ cos_t, const float* __restrict__ sin_t,
    float eps)
{
    const int row = blockIdx.x;
    const int h   = blockIdx.y;
    const int d   = threadIdx.x;

    const float* x = src + (size_t)row * INNER + h * HEAD_DIM;
    float v = x[d];
    float ss = v * v;
#pragma unroll
    for (int o = 16; o; o >>= 1) ss += __shfl_xor_sync(0xffffffffu, ss, o);
    __shared__ float red[4];
    if ((d & 31) == 0) red[d >> 5] = ss;
    __syncthreads();
    float tot = red[0] + red[1] + red[2] + red[3];
    float r = rsqrtf(tot * (1.0f / HEAD_DIM) + eps);

    const float* w = (row < split) ? w0 : w1;
    float y = v * r;
    if (w) y *= w[d];

    float other = __shfl_xor_sync(0xffffffffu, y, 1);
    float c = cos_t[(size_t)row * HEAD_DIM + d];
    float s = sin_t[(size_t)row * HEAD_DIM + d];
    float rot = (d & 1) ? other : -other;
    float out = y * c + rot * s;

    size_t idx = (size_t)row * INNER + h * HEAD_DIM + d;
    __half hv = __float2half_rn(out);
    outh[idx] = hv;
    if (outl) outl[idx] = __float2half_rn(out - __half2float(hv));
}

// ---------------- tensor-core flash attention (fp16x2, cp.async KV) ------
#define LDQ 136
#define Q_ELEMS (128 * LDQ)
#define KV_ELEMS (64 * LDQ)
#define KVSTAGE_ELEMS (4 * KV_ELEMS)
#define ATTN_SMEM_BYTES ((Q_ELEMS + 2 * KVSTAGE_ELEMS) * 2)

__global__ __launch_bounds__(256, 1) void attn_fp16_kernel(
    const __half* __restrict__ Q16,
    const __half* __restrict__ Kh, const __half* __restrict__ Kl,
    const __half* __restrict__ Vh, const __half* __restrict__ Vl,
    __half* __restrict__ O16)
{
    extern __shared__ __half smh[];
    __half* sQ = smh;
    __half* kvBase = sQ + Q_ELEMS;

    const int h    = blockIdx.y;
    const int q0   = blockIdx.x * 128;
    const int tid  = threadIdx.x;
    const int lane = tid & 31;
    const int w    = tid >> 5;
    const float scale = 0.08838834764831845f;

    const unsigned sQ_b = (unsigned)__cvta_generic_to_shared(sQ);

    const int krow = tid >> 2;
    const int kcol = (tid & 3) * 32;

    auto load_kv = [&](int s, int kt) {
        __half* st  = kvBase + s * KVSTAGE_ELEMS;
        __half* pKh = st;
        __half* pKl = st + KV_ELEMS;
        __half* pVh = st + 2 * KV_ELEMS;
        __half* pVl = st + 3 * KV_ELEMS;
#pragma unroll
        for (int seg = 0; seg < 4; seg++) {
            int cc = kcol + seg * 8;
            size_t g = (size_t)(kt * 64 + krow) * INNER + h * HEAD_DIM + cc;
            cp16(pKh + krow * LDQ + cc, Kh + g);
            cp16(pKl + krow * LDQ + cc, Kl + g);
            cp16(pVh + krow * LDQ + cc, Vh + g);
            cp16(pVl + krow * LDQ + cc, Vl + g);
        }
    };

    load_kv(0, 0); CP_COMMIT();

    for (int i = tid; i < 128 * 16; i += 256) {
        int row = i >> 4;
        int c8  = (i & 15) * 8;
        size_t g = (size_t)(q0 + row) * INNER + h * HEAD_DIM + c8;
        *(uint4*)(sQ + row * LDQ + c8) = *(const uint4*)(Q16 + g);
    }

    float o[16][4];
#pragma unroll
    for (int nt = 0; nt < 16; nt++)
#pragma unroll
        for (int r = 0; r < 4; r++) o[nt][r] = 0.f;
    float m_lo = -1e30f, m_hi = -1e30f, l_lo = 0.f, l_hi = 0.f;

    const int NT = SK / 64;
    for (int kt = 0; kt < NT; kt++) {
        CP_WAIT0();
        __syncthreads();
        if (kt + 1 < NT) { load_kv((kt + 1) & 1, kt + 1); CP_COMMIT(); }

        const __half* st = kvBase + (kt & 1) * KVSTAGE_ELEMS;
        const unsigned sKh_b = (unsigned)__cvta_generic_to_shared(st);
        const unsigned sKl_b = sKh_b + KV_ELEMS * 2;
        const unsigned sVh_b = sKh_b + 2 * KV_ELEMS * 2;
        const unsigned sVl_b = sKh_b + 3 * KV_ELEMS * 2;

        float c[8][4];
#pragma unroll
        for (int n = 0; n < 8; n++)
#pragma unroll
            for (int r = 0; r < 4; r++) c[n][r] = 0.f;

#pragma unroll
        for (int kk = 0; kk < 8; kk++) {
            unsigned aq[4];
            unsigned qoff = (unsigned)(((w * 16 + (lane & 15)) * LDQ
                                        + kk * 16 + ((lane >> 4) << 3)) * 2);
            LDSM4(aq, sQ_b + qoff);
#pragma unroll
            for (int ng = 0; ng < 4; ng++) {
                unsigned bh[4], bl[4];
                unsigned koff = (unsigned)(((ng * 16 + (lane & 15)) * LDQ
                                            + kk * 16 + ((lane >> 4) << 3)) * 2);
                LDSM4(bh, sKh_b + koff);
                LDSM4(bl, sKl_b + koff);
                MMA_F16_B2(c[2 * ng],     aq, bh[0], bh[2]);
                MMA_F16_B2(c[2 * ng],     aq, bl[0], bl[2]);
                MMA_F16_B2(c[2 * ng + 1], aq, bh[1], bh[3]);
                MMA_F16_B2(c[2 * ng + 1], aq, bl[1], bl[3]);
            }
        }

        float tmx_lo = -1e30f, tmx_hi = -1e30f;
#pragma unroll
        for (int n = 0; n < 8; n++) {
            c[n][0] *= scale; c[n][1] *= scale; c[n][2] *= scale; c[n][3] *= scale;
            tmx_lo = fmaxf(tmx_lo, fmaxf(c[n][0], c[n][1]));
            tmx_hi = fmaxf(tmx_hi, fmaxf(c[n][2], c[n][3]));
        }
        tmx_lo = fmaxf(tmx_lo, __shfl_xor_sync(0xffffffffu, tmx_lo, 1));
        tmx_lo = fmaxf(tmx_lo, __shfl_xor_sync(0xffffffffu, tmx_lo, 2));
        tmx_hi = fmaxf(tmx_hi, __shfl_xor_sync(0xffffffffu, tmx_hi, 1));
        tmx_hi = fmaxf(tmx_hi, __shfl_xor_sync(0xffffffffu, tmx_hi, 2));

        float mn_lo = fmaxf(m_lo, tmx_lo);
        float mn_hi = fmaxf(m_hi, tmx_hi);
        float al_lo = __expf(m_lo - mn_lo);
        float al_hi = __expf(m_hi - mn_hi);
        m_lo = mn_lo; m_hi = mn_hi;

        unsigned ph[8][2];
        float sum_lo = 0.f, sum_hi = 0.f;
#pragma unroll
        for (int n = 0; n < 8; n++) {
            float p0 = __expf(c[n][0] - m_lo);
            float p1 = __expf(c[n][1] - m_lo);
            float p2 = __expf(c[n][2] - m_hi);
            float p3 = __expf(c[n][3] - m_hi);
            sum_lo += p0 + p1;
            sum_hi += p2 + p3;
            __half2 h01 = __floats2half2_rn(p0, p1);
            __half2 h23 = __floats2half2_rn(p2, p3);
            ph[n][0] = *(unsigned*)&h01; ph[n][1] = *(unsigned*)&h23;
        }
        sum_lo += __shfl_xor_sync(0xffffffffu, sum_lo, 1);
        sum_lo += __shfl_xor_sync(0xffffffffu, sum_lo, 2);
        sum_hi += __shfl_xor_sync(0xffffffffu, sum_hi, 1);
        sum_hi += __shfl_xor_sync(0xffffffffu, sum_hi, 2);
        l_lo = l_lo * al_lo + sum_lo;
        l_hi = l_hi * al_hi + sum_hi;

#pragma unroll
        for (int nt = 0; nt < 16; nt++) {
            o[nt][0] *= al_lo; o[nt][1] *= al_lo;
            o[nt][2] *= al_hi; o[nt][3] *= al_hi;
        }

#pragma unroll
        for (int j = 0; j < 4; j++) {
            unsigned Ap[4] = {ph[2 * j][0], ph[2 * j][1], ph[2 * j + 1][0], ph[2 * j + 1][1]};
#pragma unroll
            for (int dp = 0; dp < 8; dp++) {
                unsigned vh4[4], vl4[4];
                unsigned voff = (unsigned)(((j * 16 + (lane & 15)) * LDQ
                                            + dp * 16 + ((lane >> 4) << 3)) * 2);
                LDSM4T(vh4, sVh_b + voff);
                LDSM4T(vl4, sVl_b + voff);
                MMA_F16_B2(o[2 * dp],     Ap, vh4[0], vh4[1]);
                MMA_F16_B2(o[2 * dp],     Ap, vl4[0], vl4[1]);
                MMA_F16_B2(o[2 * dp + 1], Ap, vh4[2], vh4[3]);
                MMA_F16_B2(o[2 * dp + 1], Ap, vl4[2], vl4[3]);
            }
        }
        __syncthreads();
    }

    float inv_lo = 1.0f / l_lo;
    float inv_hi = 1.0f / l_hi;
    const int row_lo = q0 + w * 16 + (lane >> 2);
    const int row_hi = row_lo + 8;
    const int cbase  = h * HEAD_DIM + (lane & 3) * 2;
#pragma unroll
    for (int nt = 0; nt < 16; nt++) {
        int d = cbase + nt * 8;
        *(__half2*)(O16 + (size_t)row_lo * INNER + d) =
            __floats2half2_rn(o[nt][0] * inv_lo, o[nt][1] * inv_lo);
        *(__half2*)(O16 + (size_t)row_hi * INNER + d) =
            __floats2half2_rn(o[nt][2] * inv_hi, o[nt][3] * inv_hi);
    }
}

// ---------------- launch ----------------
extern "C" void kernel_launch(void* const* d_in, const int* in_sizes, int n_in,
                              void* d_out, int out_size)
{
    (void)in_sizes; (void)n_in; (void)out_size;
    const float* hid   = (const float*)d_in[0];
    const float* enc   = (const float*)d_in[1];
    const float* ref   = (const float*)d_in[2];
    const float* rcos  = (const float*)d_in[3];
    const float* rsin  = (const float*)d_in[4];
    const float* ccos  = (const float*)d_in[5];
    const float* csin  = (const float*)d_in[6];
    const float* Wq    = (const float*)d_in[7];
    const float* bq    = (const float*)d_in[8];
    const float* Wk    = (const float*)d_in[9];
    const float* bk    = (const float*)d_in[10];
    const float* Wv    = (const float*)d_in[11];
    const float* bv    = (const float*)d_in[12];
    const float* Waq   = (const float*)d_in[13];
    const float* baq   = (const float*)d_in[14];
    const float* Wak   = (const float*)d_in[15];
    const float* bak   = (const float*)d_in[16];
    const float* Wav   = (const float*)d_in[17];
    const float* bav   = (const float*)d_in[18];
    const float* Wout  = (const float*)d_in[19];
    const float* bout  = (const float*)d_in[20];
    const float* Wadd  = (const float*)d_in[21];
    const float* badd  = (const float*)d_in[22];
    const float* nq_w  = (const float*)d_in[23];
    const float* nk_w  = (const float*)d_in[24];
    const float* naq_w = (const float*)d_in[25];
    const float* nak_w = (const float*)d_in[26];
    const float* lkd   = (const float*)d_in[27];
    const float* lku   = (const float*)d_in[28];
    const float* lvd   = (const float*)d_in[29];
    const float* lvu   = (const float*)d_in[30];

    float *q, *k;
    cudaGetSymbolAddress((void**)&q, g_q);
    cudaGetSymbolAddress((void**)&k, g_k);

    __half *Wh, *Wl, *Uh, *Ul, *x16, *t16, *o16, *q16, *kh, *kl, *vh, *vl;
    cudaGetSymbolAddress((void**)&Wh, g_W16h);
    cudaGetSymbolAddress((void**)&Wl, g_W16l);
    cudaGetSymbolAddress((void**)&Uh, g_U16h);
    cudaGetSymbolAddress((void**)&Ul, g_U16l);
    cudaGetSymbolAddress((void**)&x16, g_x16);
    cudaGetSymbolAddress((void**)&t16, g_t16);
    cudaGetSymbolAddress((void**)&o16, g_o16);
    cudaGetSymbolAddress((void**)&q16, g_q16);
    cudaGetSymbolAddress((void**)&kh, g_kh);
    cudaGetSymbolAddress((void**)&kl, g_kl);
    cudaGetSymbolAddress((void**)&vh, g_vh);
    cudaGetSymbolAddress((void**)&vl, g_vl);

    cudaFuncSetAttribute(gemm_fp16x2_kernel, cudaFuncAttributeMaxDynamicSharedMemorySize,
                         GEMM_SMEM_BYTES);
    cudaFuncSetAttribute(attn_fp16_kernel, cudaFuncAttributeMaxDynamicSharedMemorySize,
                         ATTN_SMEM_BYTES);

    auto cvt = [](const float* src, __half* dst, size_t n) {
        cvt16_kernel<<<(unsigned)(n >> 12), 256>>>(src, dst);
    };
    auto splitw = [](const float* src, __half* h, __half* l, size_t n) {
        splitw_kernel<<<(unsigned)(n >> 12), 256>>>(src, h, l);
    };
    auto gemmF = [](const __half* A, const __half* Bh, const __half* Bl,
                    const float* bi, float* C, int M, int N, int K) {
        dim3 grid(N / 128, M / 128);
        gemm_fp16x2_kernel<<<grid, 256, GEMM_SMEM_BYTES>>>(
            A, Bh, Bl, bi, C, nullptr, nullptr, nullptr, M, N, K);
    };
    auto gemmB = [](const __half* A, const __half* Bh, const __half* Bl,
                    const float* bi, __half* Ch, __half* Cl, int M, int N, int K) {
        dim3 grid(N / 128, M / 128);
        gemm_fp16x2_kernel<<<grid, 256, GEMM_SMEM_BYTES>>>(
            A, Bh, Bl, bi, nullptr, Ch, Cl, nullptr, M, N, K);
    };
    auto gemmH = [](const __half* A, const __half* Bh, const __half* Bl,
                    const float* bi, __half* C16, int M, int N, int K) {
        dim3 grid(N / 128, M / 128);
        gemm_fp16x2_kernel<<<grid, 256, GEMM_SMEM_BYTES>>>(
            A, Bh, Bl, bi, nullptr, nullptr, nullptr, C16, M, N, K);
    };

    const size_t WSZ = (size_t)INNER * INNER;
    const size_t USZ = (size_t)INNER * RANK;
    const size_t off_hid = 0;
    const size_t off_enc = (size_t)S_IMG * INNER;
    const size_t off_ref = (size_t)(S_IMG + S_TXT) * INNER;

    // L1-L5: deps for the big GEMM; L6 = big GEMM (profiled by ncu -s 5 -c 1)
    cvt(hid, x16 + off_hid, (size_t)S_IMG * INNER);                     // L1
    splitw(Wq, Wh + 1 * WSZ, Wl + 1 * WSZ, WSZ);                        // L2
    cvt(enc, x16 + off_enc, (size_t)S_TXT * INNER);                     // L3
    cvt(ref, x16 + off_ref, (size_t)S_REF * INNER);                     // L4
    splitw(Waq, Wh + 0 * WSZ, Wl + 0 * WSZ, WSZ);                       // L5
    gemmF(x16 + off_hid, Wh + 1 * WSZ, Wl + 1 * WSZ, bq,                // L6
          q + (size_t)S_TXT * INNER, S_IMG, INNER, INNER);

    splitw(Wak,  Wh + 2 * WSZ, Wl + 2 * WSZ, WSZ);
    splitw(Wk,   Wh + 3 * WSZ, Wl + 3 * WSZ, WSZ);
    splitw(Wav,  Wh + 4 * WSZ, Wl + 4 * WSZ, WSZ);
    splitw(Wv,   Wh + 5 * WSZ, Wl + 5 * WSZ, WSZ);
    splitw(Wout, Wh + 6 * WSZ, Wl + 6 * WSZ, WSZ);
    splitw(Wadd, Wh + 7 * WSZ, Wl + 7 * WSZ, WSZ);
    splitw(lkd,  Uh + 0 * USZ, Ul + 0 * USZ, USZ);
    splitw(lvd,  Uh + 1 * USZ, Ul + 1 * USZ, USZ);
    splitw(lku,  Uh + 2 * USZ, Ul + 2 * USZ, USZ);
    splitw(lvu,  Uh + 3 * USZ, Ul + 3 * USZ, USZ);

    gemmF(x16 + off_enc, Wh + 0 * WSZ, Wl + 0 * WSZ, baq, q,                         S_TXT, INNER, INNER);
    gemmF(x16 + off_enc, Wh + 2 * WSZ, Wl + 2 * WSZ, bak, k,                         S_TXT, INNER, INNER);
    gemmF(x16 + off_hid, Wh + 3 * WSZ, Wl + 3 * WSZ, bk,  k + (size_t)S_TXT * INNER, S_IMG, INNER, INNER);
    gemmB(x16 + off_enc, Wh + 4 * WSZ, Wl + 4 * WSZ, bav, vh, vl,                    S_TXT, INNER, INNER);
    gemmB(x16 + off_hid, Wh + 5 * WSZ, Wl + 5 * WSZ, bv,
          vh + (size_t)S_TXT * INNER, vl + (size_t)S_TXT * INNER,                    S_IMG, INNER, INNER);

    // LoRA ref branch
    gemmH(x16 + off_ref, Uh + 0 * USZ, Ul + 0 * USZ, nullptr, t16, S_REF, RANK, INNER);
    gemmF(t16, Uh + 2 * USZ, Ul + 2 * USZ, nullptr, k + (size_t)SQ * INNER, S_REF, INNER, RANK);
    gemmH(x16 + off_ref, Uh + 1 * USZ, Ul + 1 * USZ, nullptr, t16, S_REF, RANK, INNER);
    gemmB(t16, Uh + 3 * USZ, Ul + 3 * USZ, nullptr,
          vh + (size_t)SQ * INNER, vl + (size_t)SQ * INNER, S_REF, INNER, RANK);

    // RMSNorm + RoPE: Q -> single fp16, K -> fp16 hi/lo
    rmsnorm_rope_out_kernel<<<dim3(SQ, HEADS), 128>>>(
        q, q16, nullptr, naq_w, nq_w, S_TXT, rcos, rsin, 1e-6f);
    rmsnorm_rope_out_kernel<<<dim3(SQ, HEADS), 128>>>(
        k, kh, kl, nak_w, nk_w, S_TXT, rcos, rsin, 1e-6f);
    rmsnorm_rope_out_kernel<<<dim3(S_REF, HEADS), 128>>>(
        k + (size_t)SQ * INNER, kh + (size_t)SQ * INNER, kl + (size_t)SQ * INNER,
        nullptr, nullptr, 0, ccos, csin, 1e-5f);

    attn_fp16_kernel<<<dim3(SQ / 128, HEADS), 256, ATTN_SMEM_BYTES>>>(
        q16, kh, kl, vh, vl, o16);

    float* outp = (float*)d_out;
    gemmF(o16 + (size_t)S_TXT * INNER, Wh + 6 * WSZ, Wl + 6 * WSZ, bout,
          outp, S_IMG, INNER, INNER);
    gemmF(o16, Wh + 7 * WSZ, Wl + 7 * WSZ, badd,
          outp + (size_t)S_IMG * INNER, S_TXT, INNER, INNER);
}

// round 10
// speedup vs baseline: 1.5268x; 1.1894x over previous
#include <cuda_runtime.h>
#include <cuda_bf16.h>
#include <cuda_fp16.h>
#include <cstdint>
#include <cstddef>

#define HEADS 24
#define HEAD_DIM 128
#define INNER 3072
#define RANK 1024
#define S_IMG 2048
#define S_TXT 512
#define S_REF 2048
#define SQ (S_TXT + S_IMG)          // 2560
#define SK (S_TXT + S_IMG + S_REF)  // 4608

// ---------------- scratch (device globals; no allocation) ----------------
__device__ float g_q[(size_t)SQ * INNER];
__device__ float g_k[(size_t)SK * INNER];

__device__ __half g_W16h[(size_t)8 * INNER * INNER];
__device__ __half g_W16l[(size_t)2 * INNER * INNER];   // lo only for Wout,Wadd
__device__ __half g_U16h[(size_t)4 * INNER * RANK];
__device__ __half g_x16[(size_t)(S_IMG + S_TXT + S_REF) * INNER];
__device__ __half g_t16[(size_t)S_REF * RANK];
__device__ __half g_o16[(size_t)SQ * INNER];
__device__ __half g_q16[(size_t)SQ * INNER];
__device__ __half g_kh[(size_t)SK * INNER];
__device__ __half g_kl[(size_t)SK * INNER];
__device__ __half g_vh[(size_t)SK * INNER];
__device__ __half g_vl[(size_t)SK * INNER];

// ---------------- fp32 -> fp16 convert (16 elems/thread) ----------------
__global__ void cvt16_kernel(const float* __restrict__ x, __half* __restrict__ y)
{
    size_t base = ((size_t)blockIdx.x * 256 + threadIdx.x) * 16;
#pragma unroll
    for (int u = 0; u < 4; u++) {
        float4 v = *(const float4*)(x + base + u * 4);
        __half2* yp = (__half2*)(y + base + u * 4);
        yp[0] = __floats2half2_rn(v.x, v.y);
        yp[1] = __floats2half2_rn(v.z, v.w);
    }
}

// ---------------- fp32 -> fp16 hi/lo split (weights) ----------------
__global__ void splitw_kernel(const float* __restrict__ x,
                              __half* __restrict__ h, __half* __restrict__ l)
{
    size_t base = ((size_t)blockIdx.x * 256 + threadIdx.x) * 16;
#pragma unroll
    for (int u = 0; u < 4; u++) {
        float4 v = *(const float4*)(x + base + u * 4);
        __half h0 = __float2half_rn(v.x), h1 = __float2half_rn(v.y);
        __half h2 = __float2half_rn(v.z), h3 = __float2half_rn(v.w);
        __half l0 = __float2half_rn(v.x - __half2float(h0));
        __half l1 = __float2half_rn(v.y - __half2float(h1));
        __half l2 = __float2half_rn(v.z - __half2float(h2));
        __half l3 = __float2half_rn(v.w - __half2float(h3));
        __half2* hp = (__half2*)(h + base + u * 4);
        hp[0] = __half2{h0, h1}; hp[1] = __half2{h2, h3};
        __half2* lp = (__half2*)(l + base + u * 4);
        lp[0] = __half2{l0, l1}; lp[1] = __half2{l2, l3};
    }
}

// ---------------- ptx helpers ----------------
#define LDSM4(R, addr) \
    asm volatile("ldmatrix.sync.aligned.m8n8.x4.shared.b16 {%0,%1,%2,%3},[%4];" \
        : "=r"((R)[0]), "=r"((R)[1]), "=r"((R)[2]), "=r"((R)[3]) : "r"(addr))
#define LDSM4T(R, addr) \
    asm volatile("ldmatrix.sync.aligned.m8n8.x4.trans.shared.b16 {%0,%1,%2,%3},[%4];" \
        : "=r"((R)[0]), "=r"((R)[1]), "=r"((R)[2]), "=r"((R)[3]) : "r"(addr))
#define MMA_F16(C, A, B) \
    asm volatile("mma.sync.aligned.m16n8k16.row.col.f32.f16.f16.f32 " \
        "{%0,%1,%2,%3},{%4,%5,%6,%7},{%8,%9},{%0,%1,%2,%3};" \
        : "+f"((C)[0]), "+f"((C)[1]), "+f"((C)[2]), "+f"((C)[3]) \
        : "r"((A)[0]), "r"((A)[1]), "r"((A)[2]), "r"((A)[3]), "r"((B)[0]), "r"((B)[1]))
#define MMA_F16_B2(C, A, B0, B1) \
    asm volatile("mma.sync.aligned.m16n8k16.row.col.f32.f16.f16.f32 " \
        "{%0,%1,%2,%3},{%4,%5,%6,%7},{%8,%9},{%0,%1,%2,%3};" \
        : "+f"((C)[0]), "+f"((C)[1]), "+f"((C)[2]), "+f"((C)[3]) \
        : "r"((A)[0]), "r"((A)[1]), "r"((A)[2]), "r"((A)[3]), "r"(B0), "r"(B1))

__device__ __forceinline__ void cp16(const void* dst, const void* src) {
    unsigned d = (unsigned)__cvta_generic_to_shared(dst);
    asm volatile("cp.async.cg.shared.global [%0],[%1],16;" :: "r"(d), "l"(src));
}
#define CP_COMMIT() asm volatile("cp.async.commit_group;")
#define CP_WAIT0()  asm volatile("cp.async.wait_group 0;")
#define CP_WAIT1()  asm volatile("cp.async.wait_group 1;")

// ---------------- fp16 GEMM, NB = B-operand term count (1 or 2) ----------
#define A_LD 40
#define B_LD 136
#define SA_ELEMS (128 * A_LD)
#define SB_ELEMS (32 * B_LD)
#define GSTAGE(NB) (SA_ELEMS + (NB) * SB_ELEMS)
#define GEMM_SMEM(NB) (GSTAGE(NB) * 3 * 2)

template<int NB>
__global__ __launch_bounds__(256, 1) void gemm_fp16_kernel(
    const __half* __restrict__ A,
    const __half* __restrict__ Bh, const __half* __restrict__ Bl,
    const float* __restrict__ bias,
    float* __restrict__ Cf,
    __half* __restrict__ Ch, __half* __restrict__ Cl,
    __half* __restrict__ C16,
    int M, int N, int K)
{
    extern __shared__ __half dsm[];
    constexpr int GST = GSTAGE(NB);

    const int tid  = threadIdx.x;
    const int lane = tid & 31;
    const int wid  = tid >> 5;
    const int wm   = wid & 3;
    const int wn   = wid >> 2;
    const int bm   = blockIdx.y * 128;
    const int bn   = blockIdx.x * 128;

    const int ar = tid >> 1;
    const int ac = (tid & 1) * 16;
    const int br = tid >> 4;
    const int bc = (tid & 15) * 8;

    float c[2][8][4];
#pragma unroll
    for (int mi = 0; mi < 2; mi++)
#pragma unroll
        for (int ni = 0; ni < 8; ni++)
#pragma unroll
            for (int r = 0; r < 4; r++) c[mi][ni][r] = 0.f;

    const int iters = K >> 5;

    auto load_stage = [&](int s, int it) {
        int k0 = it << 5;
        __half* st  = dsm + s * GST;
        __half* pA  = st;
        __half* pBh = st + SA_ELEMS;
        cp16(pA + ar * A_LD + ac,      A + (size_t)(bm + ar) * K + k0 + ac);
        cp16(pA + ar * A_LD + ac + 8,  A + (size_t)(bm + ar) * K + k0 + ac + 8);
        cp16(pBh + br * B_LD + bc,        Bh + (size_t)(k0 + br) * N + bn + bc);
        cp16(pBh + (br + 16) * B_LD + bc, Bh + (size_t)(k0 + br + 16) * N + bn + bc);
        if (NB == 2) {
            __half* pBl = pBh + SB_ELEMS;
            cp16(pBl + br * B_LD + bc,        Bl + (size_t)(k0 + br) * N + bn + bc);
            cp16(pBl + (br + 16) * B_LD + bc, Bl + (size_t)(k0 + br + 16) * N + bn + bc);
        }
    };

    load_stage(0, 0); CP_COMMIT();
    load_stage(1, 1); CP_COMMIT();

    for (int it = 0; it < iters; it++) {
        if (it == iters - 1) { CP_WAIT0(); } else { CP_WAIT1(); }
        __syncthreads();
        if (it + 2 < iters) { load_stage((it + 2) % 3, it + 2); CP_COMMIT(); }

        const __half* st = dsm + (it % 3) * GST;
        const unsigned sA_b  = (unsigned)__cvta_generic_to_shared(st);
        const unsigned sBh_b = sA_b + SA_ELEMS * 2;
        const unsigned sBl_b = sBh_b + SB_ELEMS * 2;

#pragma unroll
        for (int kh = 0; kh < 2; kh++) {
            unsigned af[2][4];
#pragma unroll
            for (int mi = 0; mi < 2; mi++) {
                unsigned off = (unsigned)(((wm * 32 + mi * 16 + (lane & 15)) * A_LD
                                           + kh * 16 + ((lane >> 4) << 3)) * 2);
                LDSM4(af[mi], sA_b + off);
            }
#pragma unroll
            for (int p = 0; p < 4; p++) {
                unsigned bh[4];
                unsigned off = (unsigned)(((kh * 16 + (lane & 15)) * B_LD
                                           + wn * 64 + p * 16 + ((lane >> 4) << 3)) * 2);
                LDSM4T(bh, sBh_b + off);
#pragma unroll
                for (int mi = 0; mi < 2; mi++) {
                    MMA_F16(c[mi][2 * p],     af[mi], bh);
                    MMA_F16(c[mi][2 * p + 1], af[mi], bh + 2);
                }
                if (NB == 2) {
                    unsigned bl[4];
                    LDSM4T(bl, sBl_b + off);
#pragma unroll
                    for (int mi = 0; mi < 2; mi++) {
                        MMA_F16(c[mi][2 * p],     af[mi], bl);
                        MMA_F16(c[mi][2 * p + 1], af[mi], bl + 2);
                    }
                }
            }
        }
    }

    const int row0 = bm + wm * 32 + (lane >> 2);
    const int col0 = bn + wn * 64 + (lane & 3) * 2;
#pragma unroll
    for (int mi = 0; mi < 2; mi++) {
#pragma unroll
        for (int ni = 0; ni < 8; ni++) {
            int r  = row0 + mi * 16;
            int cc = col0 + ni * 8;
            float b0 = bias ? bias[cc] : 0.f;
            float b1 = bias ? bias[cc + 1] : 0.f;
            float v0 = c[mi][ni][0] + b0, v1 = c[mi][ni][1] + b1;
            float v2 = c[mi][ni][2] + b0, v3 = c[mi][ni][3] + b1;
            if (Cf) {
                *(float2*)(Cf + (size_t)r * N + cc)       = float2{v0, v1};
                *(float2*)(Cf + (size_t)(r + 8) * N + cc) = float2{v2, v3};
            } else if (Ch) {
                __half2 h01 = __floats2half2_rn(v0, v1);
                __half2 h23 = __floats2half2_rn(v2, v3);
                __half2 l01 = __floats2half2_rn(v0 - __half2float(h01.x),
                                                v1 - __half2float(h01.y));
                __half2 l23 = __floats2half2_rn(v2 - __half2float(h23.x),
                                                v3 - __half2float(h23.y));
                *(__half2*)(Ch + (size_t)r * N + cc)       = h01;
                *(__half2*)(Cl + (size_t)r * N + cc)       = l01;
                *(__half2*)(Ch + (size_t)(r + 8) * N + cc) = h23;
                *(__half2*)(Cl + (size_t)(r + 8) * N + cc) = l23;
            } else {
                *(__half2*)(C16 + (size_t)r * N + cc)       = __floats2half2_rn(v0, v1);
                *(__half2*)(C16 + (size_t)(r + 8) * N + cc) = __floats2half2_rn(v2, v3);
            }
        }
    }
}

// ------ fused RMSNorm + RoPE -> single fp16 (Q) or fp16 hi/lo (K) --------
__global__ void rmsnorm_rope_out_kernel(
    const float* __restrict__ src,
    __half* __restrict__ outh, __half* __restrict__ outl,
    const float* __restrict__ w0, const float* __restrict__ w1, int split,
    const float* __restrict__ cos_t, const float* __restrict__ sin_t,
    float eps)
{
    const int row = blockIdx.x;
    const int h   = blockIdx.y;
    const int d   = threadIdx.x;

    const float* x = src + (size_t)row * INNER + h * HEAD_DIM;
    float v = x[d];
    float ss = v * v;
#pragma unroll
    for (int o = 16; o; o >>= 1) ss += __shfl_xor_sync(0xffffffffu, ss, o);
    __shared__ float red[4];
    if ((d & 31) == 0) red[d >> 5] = ss;
    __syncthreads();
    float tot = red[0] + red[1] + red[2] + red[3];
    float r = rsqrtf(tot * (1.0f / HEAD_DIM) + eps);

    const float* w = (row < split) ? w0 : w1;
    float y = v * r;
    if (w) y *= w[d];

    float other = __shfl_xor_sync(0xffffffffu, y, 1);
    float c = cos_t[(size_t)row * HEAD_DIM + d];
    float s = sin_t[(size_t)row * HEAD_DIM + d];
    float rot = (d & 1) ? other : -other;
    float out = y * c + rot * s;

    size_t idx = (size_t)row * INNER + h * HEAD_DIM + d;
    __half hv = __float2half_rn(out);
    outh[idx] = hv;
    if (outl) outl[idx] = __float2half_rn(out - __half2float(hv));
}

// ---------------- tensor-core flash attention (fp16x2, cp.async KV) ------
#define LDQ 136
#define Q_ELEMS (128 * LDQ)
#define KV_ELEMS (64 * LDQ)
#define KVSTAGE_ELEMS (4 * KV_ELEMS)
#define ATTN_SMEM_BYTES ((Q_ELEMS + 2 * KVSTAGE_ELEMS) * 2)

__global__ __launch_bounds__(256, 1) void attn_fp16_kernel(
    const __half* __restrict__ Q16,
    const __half* __restrict__ Kh, const __half* __restrict__ Kl,
    const __half* __restrict__ Vh, const __half* __restrict__ Vl,
    __half* __restrict__ O16)
{
    extern __shared__ __half smh[];
    __half* sQ = smh;
    __half* kvBase = sQ + Q_ELEMS;

    const int h    = blockIdx.y;
    const int q0   = blockIdx.x * 128;
    const int tid  = threadIdx.x;
    const int lane = tid & 31;
    const int w    = tid >> 5;
    const float scale = 0.08838834764831845f;

    const unsigned sQ_b = (unsigned)__cvta_generic_to_shared(sQ);

    const int krow = tid >> 2;
    const int kcol = (tid & 3) * 32;

    auto load_kv = [&](int s, int kt) {
        __half* st  = kvBase + s * KVSTAGE_ELEMS;
        __half* pKh = st;
        __half* pKl = st + KV_ELEMS;
        __half* pVh = st + 2 * KV_ELEMS;
        __half* pVl = st + 3 * KV_ELEMS;
#pragma unroll
        for (int seg = 0; seg < 4; seg++) {
            int cc = kcol + seg * 8;
            size_t g = (size_t)(kt * 64 + krow) * INNER + h * HEAD_DIM + cc;
            cp16(pKh + krow * LDQ + cc, Kh + g);
            cp16(pKl + krow * LDQ + cc, Kl + g);
            cp16(pVh + krow * LDQ + cc, Vh + g);
            cp16(pVl + krow * LDQ + cc, Vl + g);
        }
    };

    load_kv(0, 0); CP_COMMIT();

    for (int i = tid; i < 128 * 16; i += 256) {
        int row = i >> 4;
        int c8  = (i & 15) * 8;
        size_t g = (size_t)(q0 + row) * INNER + h * HEAD_DIM + c8;
        *(uint4*)(sQ + row * LDQ + c8) = *(const uint4*)(Q16 + g);
    }

    float o[16][4];
#pragma unroll
    for (int nt = 0; nt < 16; nt++)
#pragma unroll
        for (int r = 0; r < 4; r++) o[nt][r] = 0.f;
    float m_lo = -1e30f, m_hi = -1e30f, l_lo = 0.f, l_hi = 0.f;

    const int NT = SK / 64;
    for (int kt = 0; kt < NT; kt++) {
        CP_WAIT0();
        __syncthreads();
        if (kt + 1 < NT) { load_kv((kt + 1) & 1, kt + 1); CP_COMMIT(); }

        const __half* st = kvBase + (kt & 1) * KVSTAGE_ELEMS;
        const unsigned sKh_b = (unsigned)__cvta_generic_to_shared(st);
        const unsigned sKl_b = sKh_b + KV_ELEMS * 2;
        const unsigned sVh_b = sKh_b + 2 * KV_ELEMS * 2;
        const unsigned sVl_b = sKh_b + 3 * KV_ELEMS * 2;

        float c[8][4];
#pragma unroll
        for (int n = 0; n < 8; n++)
#pragma unroll
            for (int r = 0; r < 4; r++) c[n][r] = 0.f;

#pragma unroll
        for (int kk = 0; kk < 8; kk++) {
            unsigned aq[4];
            unsigned qoff = (unsigned)(((w * 16 + (lane & 15)) * LDQ
                                        + kk * 16 + ((lane >> 4) << 3)) * 2);
            LDSM4(aq, sQ_b + qoff);
#pragma unroll
            for (int ng = 0; ng < 4; ng++) {
                unsigned bh[4], bl[4];
                unsigned koff = (unsigned)(((ng * 16 + (lane & 15)) * LDQ
                                            + kk * 16 + ((lane >> 4) << 3)) * 2);
                LDSM4(bh, sKh_b + koff);
                LDSM4(bl, sKl_b + koff);
                MMA_F16_B2(c[2 * ng],     aq, bh[0], bh[2]);
                MMA_F16_B2(c[2 * ng],     aq, bl[0], bl[2]);
                MMA_F16_B2(c[2 * ng + 1], aq, bh[1], bh[3]);
                MMA_F16_B2(c[2 * ng + 1], aq, bl[1], bl[3]);
            }
        }

        float tmx_lo = -1e30f, tmx_hi = -1e30f;
#pragma unroll
        for (int n = 0; n < 8; n++) {
            c[n][0] *= scale; c[n][1] *= scale; c[n][2] *= scale; c[n][3] *= scale;
            tmx_lo = fmaxf(tmx_lo, fmaxf(c[n][0], c[n][1]));
            tmx_hi = fmaxf(tmx_hi, fmaxf(c[n][2], c[n][3]));
        }
        tmx_lo = fmaxf(tmx_lo, __shfl_xor_sync(0xffffffffu, tmx_lo, 1));
        tmx_lo = fmaxf(tmx_lo, __shfl_xor_sync(0xffffffffu, tmx_lo, 2));
        tmx_hi = fmaxf(tmx_hi, __shfl_xor_sync(0xffffffffu, tmx_hi, 1));
        tmx_hi = fmaxf(tmx_hi, __shfl_xor_sync(0xffffffffu, tmx_hi, 2));

        float mn_lo = fmaxf(m_lo, tmx_lo);
        float mn_hi = fmaxf(m_hi, tmx_hi);
        float al_lo = __expf(m_lo - mn_lo);
        float al_hi = __expf(m_hi - mn_hi);
        m_lo = mn_lo; m_hi = mn_hi;

        unsigned ph[8][2];
        float sum_lo = 0.f, sum_hi = 0.f;
#pragma unroll
        for (int n = 0; n < 8; n++) {
            float p0 = __expf(c[n][0] - m_lo);
            float p1 = __expf(c[n][1] - m_lo);
            float p2 = __expf(c[n][2] - m_hi);
            float p3 = __expf(c[n][3] - m_hi);
            sum_lo += p0 + p1;
            sum_hi += p2 + p3;
            __half2 h01 = __floats2half2_rn(p0, p1);
            __half2 h23 = __floats2half2_rn(p2, p3);
            ph[n][0] = *(unsigned*)&h01; ph[n][1] = *(unsigned*)&h23;
        }
        sum_lo += __shfl_xor_sync(0xffffffffu, sum_lo, 1);
        sum_lo += __shfl_xor_sync(0xffffffffu, sum_lo, 2);
        sum_hi += __shfl_xor_sync(0xffffffffu, sum_hi, 1);
        sum_hi += __shfl_xor_sync(0xffffffffu, sum_hi, 2);
        l_lo = l_lo * al_lo + sum_lo;
        l_hi = l_hi * al_hi + sum_hi;

#pragma unroll
        for (int nt = 0; nt < 16; nt++) {
            o[nt][0] *= al_lo; o[nt][1] *= al_lo;
            o[nt][2] *= al_hi; o[nt][3] *= al_hi;
        }

#pragma unroll
        for (int j = 0; j < 4; j++) {
            unsigned Ap[4] = {ph[2 * j][0], ph[2 * j][1], ph[2 * j + 1][0], ph[2 * j + 1][1]};
#pragma unroll
            for (int dp = 0; dp < 8; dp++) {
                unsigned vh4[4], vl4[4];
                unsigned voff = (unsigned)(((j * 16 + (lane & 15)) * LDQ
                                            + dp * 16 + ((lane >> 4) << 3)) * 2);
                LDSM4T(vh4, sVh_b + voff);
                LDSM4T(vl4, sVl_b + voff);
                MMA_F16_B2(o[2 * dp],     Ap, vh4[0], vh4[1]);
                MMA_F16_B2(o[2 * dp],     Ap, vl4[0], vl4[1]);
                MMA_F16_B2(o[2 * dp + 1], Ap, vh4[2], vh4[3]);
                MMA_F16_B2(o[2 * dp + 1], Ap, vl4[2], vl4[3]);
            }
        }
        __syncthreads();
    }

    float inv_lo = 1.0f / l_lo;
    float inv_hi = 1.0f / l_hi;
    const int row_lo = q0 + w * 16 + (lane >> 2);
    const int row_hi = row_lo + 8;
    const int cbase  = h * HEAD_DIM + (lane & 3) * 2;
#pragma unroll
    for (int nt = 0; nt < 16; nt++) {
        int d = cbase + nt * 8;
        *(__half2*)(O16 + (size_t)row_lo * INNER + d) =
            __floats2half2_rn(o[nt][0] * inv_lo, o[nt][1] * inv_lo);
        *(__half2*)(O16 + (size_t)row_hi * INNER + d) =
            __floats2half2_rn(o[nt][2] * inv_hi, o[nt][3] * inv_hi);
    }
}

// ---------------- launch ----------------
extern "C" void kernel_launch(void* const* d_in, const int* in_sizes, int n_in,
                              void* d_out, int out_size)
{
    (void)in_sizes; (void)n_in; (void)out_size;
    const float* hid   = (const float*)d_in[0];
    const float* enc   = (const float*)d_in[1];
    const float* ref   = (const float*)d_in[2];
    const float* rcos  = (const float*)d_in[3];
    const float* rsin  = (const float*)d_in[4];
    const float* ccos  = (const float*)d_in[5];
    const float* csin  = (const float*)d_in[6];
    const float* Wq    = (const float*)d_in[7];
    const float* bq    = (const float*)d_in[8];
    const float* Wk    = (const float*)d_in[9];
    const float* bk    = (const float*)d_in[10];
    const float* Wv    = (const float*)d_in[11];
    const float* bv    = (const float*)d_in[12];
    const float* Waq   = (const float*)d_in[13];
    const float* baq   = (const float*)d_in[14];
    const float* Wak   = (const float*)d_in[15];
    const float* bak   = (const float*)d_in[16];
    const float* Wav   = (const float*)d_in[17];
    const float* bav   = (const float*)d_in[18];
    const float* Wout  = (const float*)d_in[19];
    const float* bout  = (const float*)d_in[20];
    const float* Wadd  = (const float*)d_in[21];
    const float* badd  = (const float*)d_in[22];
    const float* nq_w  = (const float*)d_in[23];
    const float* nk_w  = (const float*)d_in[24];
    const float* naq_w = (const float*)d_in[25];
    const float* nak_w = (const float*)d_in[26];
    const float* lkd   = (const float*)d_in[27];
    const float* lku   = (const float*)d_in[28];
    const float* lvd   = (const float*)d_in[29];
    const float* lvu   = (const float*)d_in[30];

    float *q, *k;
    cudaGetSymbolAddress((void**)&q, g_q);
    cudaGetSymbolAddress((void**)&k, g_k);

    __half *Wh, *Wl, *Uh, *x16, *t16, *o16, *q16, *kh, *kl, *vh, *vl;
    cudaGetSymbolAddress((void**)&Wh, g_W16h);
    cudaGetSymbolAddress((void**)&Wl, g_W16l);
    cudaGetSymbolAddress((void**)&Uh, g_U16h);
    cudaGetSymbolAddress((void**)&x16, g_x16);
    cudaGetSymbolAddress((void**)&t16, g_t16);
    cudaGetSymbolAddress((void**)&o16, g_o16);
    cudaGetSymbolAddress((void**)&q16, g_q16);
    cudaGetSymbolAddress((void**)&kh, g_kh);
    cudaGetSymbolAddress((void**)&kl, g_kl);
    cudaGetSymbolAddress((void**)&vh, g_vh);
    cudaGetSymbolAddress((void**)&vl, g_vl);

    cudaFuncSetAttribute(gemm_fp16_kernel<1>, cudaFuncAttributeMaxDynamicSharedMemorySize,
                         GEMM_SMEM(1));
    cudaFuncSetAttribute(gemm_fp16_kernel<2>, cudaFuncAttributeMaxDynamicSharedMemorySize,
                         GEMM_SMEM(2));
    cudaFuncSetAttribute(attn_fp16_kernel, cudaFuncAttributeMaxDynamicSharedMemorySize,
                         ATTN_SMEM_BYTES);

    auto cvt = [](const float* src, __half* dst, size_t n) {
        cvt16_kernel<<<(unsigned)(n >> 12), 256>>>(src, dst);
    };
    auto splitw = [](const float* src, __half* h, __half* l, size_t n) {
        splitw_kernel<<<(unsigned)(n >> 12), 256>>>(src, h, l);
    };
    // 1-term GEMMs (single fp16 B)
    auto g1F = [](const __half* A, const __half* B, const float* bi, float* C,
                  int M, int N, int K) {
        gemm_fp16_kernel<1><<<dim3(N / 128, M / 128), 256, GEMM_SMEM(1)>>>(
            A, B, nullptr, bi, C, nullptr, nullptr, nullptr, M, N, K);
    };
    auto g1B = [](const __half* A, const __half* B, const float* bi,
                  __half* Ch, __half* Cl, int M, int N, int K) {
        gemm_fp16_kernel<1><<<dim3(N / 128, M / 128), 256, GEMM_SMEM(1)>>>(
            A, B, nullptr, bi, nullptr, Ch, Cl, nullptr, M, N, K);
    };
    auto g1H = [](const __half* A, const __half* B, const float* bi, __half* C16,
                  int M, int N, int K) {
        gemm_fp16_kernel<1><<<dim3(N / 128, M / 128), 256, GEMM_SMEM(1)>>>(
            A, B, nullptr, bi, nullptr, nullptr, nullptr, C16, M, N, K);
    };
    // 2-term GEMM (output projections)
    auto g2F = [](const __half* A, const __half* Bh, const __half* Bl,
                  const float* bi, float* C, int M, int N, int K) {
        gemm_fp16_kernel<2><<<dim3(N / 128, M / 128), 256, GEMM_SMEM(2)>>>(
            A, Bh, Bl, bi, C, nullptr, nullptr, nullptr, M, N, K);
    };

    const size_t WSZ = (size_t)INNER * INNER;
    const size_t USZ = (size_t)INNER * RANK;
    const size_t off_hid = 0;
    const size_t off_enc = (size_t)S_IMG * INNER;
    const size_t off_ref = (size_t)(S_IMG + S_TXT) * INNER;

    // L1-L5: deps for the big GEMM; L6 = big GEMM (profiled by ncu -s 5 -c 1)
    cvt(hid, x16 + off_hid, (size_t)S_IMG * INNER);                     // L1
    cvt(Wq, Wh + 1 * WSZ, WSZ);                                         // L2
    cvt(enc, x16 + off_enc, (size_t)S_TXT * INNER);                     // L3
    cvt(ref, x16 + off_ref, (size_t)S_REF * INNER);                     // L4
    cvt(Waq, Wh + 0 * WSZ, WSZ);                                        // L5
    g1F(x16 + off_hid, Wh + 1 * WSZ, bq,                                // L6
        q + (size_t)S_TXT * INNER, S_IMG, INNER, INNER);

    cvt(Wak, Wh + 2 * WSZ, WSZ);
    cvt(Wk,  Wh + 3 * WSZ, WSZ);
    cvt(Wav, Wh + 4 * WSZ, WSZ);
    cvt(Wv,  Wh + 5 * WSZ, WSZ);
    splitw(Wout, Wh + 6 * WSZ, Wl + 0 * WSZ, WSZ);
    splitw(Wadd, Wh + 7 * WSZ, Wl + 1 * WSZ, WSZ);
    cvt(lkd, Uh + 0 * USZ, USZ);
    cvt(lvd, Uh + 1 * USZ, USZ);
    cvt(lku, Uh + 2 * USZ, USZ);
    cvt(lvu, Uh + 3 * USZ, USZ);

    g1F(x16 + off_enc, Wh + 0 * WSZ, baq, q,                         S_TXT, INNER, INNER);
    g1F(x16 + off_enc, Wh + 2 * WSZ, bak, k,                         S_TXT, INNER, INNER);
    g1F(x16 + off_hid, Wh + 3 * WSZ, bk,  k + (size_t)S_TXT * INNER, S_IMG, INNER, INNER);
    g1B(x16 + off_enc, Wh + 4 * WSZ, bav, vh, vl,                    S_TXT, INNER, INNER);
    g1B(x16 + off_hid, Wh + 5 * WSZ, bv,
        vh + (size_t)S_TXT * INNER, vl + (size_t)S_TXT * INNER,      S_IMG, INNER, INNER);

    // LoRA ref branch
    g1H(x16 + off_ref, Uh + 0 * USZ, nullptr, t16, S_REF, RANK, INNER);
    g1F(t16, Uh + 2 * USZ, nullptr, k + (size_t)SQ * INNER, S_REF, INNER, RANK);
    g1H(x16 + off_ref, Uh + 1 * USZ, nullptr, t16, S_REF, RANK, INNER);
    g1B(t16, Uh + 3 * USZ, nullptr,
        vh + (size_t)SQ * INNER, vl + (size_t)SQ * INNER, S_REF, INNER, RANK);

    // RMSNorm + RoPE: Q -> single fp16, K -> fp16 hi/lo
    rmsnorm_rope_out_kernel<<<dim3(SQ, HEADS), 128>>>(
        q, q16, nullptr, naq_w, nq_w, S_TXT, rcos, rsin, 1e-6f);
    rmsnorm_rope_out_kernel<<<dim3(SQ, HEADS), 128>>>(
        k, kh, kl, nak_w, nk_w, S_TXT, rcos, rsin, 1e-6f);
    rmsnorm_rope_out_kernel<<<dim3(S_REF, HEADS), 128>>>(
        k + (size_t)SQ * INNER, kh + (size_t)SQ * INNER, kl + (size_t)SQ * INNER,
        nullptr, nullptr, 0, ccos, csin, 1e-5f);

    attn_fp16_kernel<<<dim3(SQ / 128, HEADS), 256, ATTN_SMEM_BYTES>>>(
        q16, kh, kl, vh, vl, o16);

    float* outp = (float*)d_out;
    g2F(o16 + (size_t)S_TXT * INNER, Wh + 6 * WSZ, Wl + 0 * WSZ, bout,
        outp, S_IMG, INNER, INNER);
    g2F(o16, Wh + 7 * WSZ, Wl + 1 * WSZ, badd,
        outp + (size_t)S_IMG * INNER, S_TXT, INNER, INNER);
}

// round 11
// speedup vs baseline: 1.8844x; 1.2342x over previous
#include <cuda_runtime.h>
#include <cuda_bf16.h>
#include <cuda_fp16.h>
#include <cstdint>
#include <cstddef>

#define HEADS 24
#define HEAD_DIM 128
#define INNER 3072
#define RANK 1024
#define S_IMG 2048
#define S_TXT 512
#define S_REF 2048
#define SQ (S_TXT + S_IMG)          // 2560
#define SK (S_TXT + S_IMG + S_REF)  // 4608

// ---------------- scratch (device globals; no allocation) ----------------
__device__ float g_q[(size_t)SQ * INNER];
__device__ float g_k[(size_t)SK * INNER];

__device__ __half g_W16h[(size_t)8 * INNER * INNER];
__device__ __half g_W16l[(size_t)2 * INNER * INNER];   // lo only for Wout,Wadd
__device__ __half g_U16h[(size_t)4 * INNER * RANK];
__device__ __half g_x16[(size_t)(S_IMG + S_TXT + S_REF) * INNER];
__device__ __half g_t16[(size_t)S_REF * RANK];
__device__ __half g_o16[(size_t)SQ * INNER];
__device__ __half g_q16[(size_t)SQ * INNER];
__device__ __half g_k16[(size_t)SK * INNER];
__device__ __half g_v16[(size_t)SK * INNER];

// ---------------- fp32 -> fp16 convert (16 elems/thread) ----------------
__global__ void cvt16_kernel(const float* __restrict__ x, __half* __restrict__ y)
{
    size_t base = ((size_t)blockIdx.x * 256 + threadIdx.x) * 16;
#pragma unroll
    for (int u = 0; u < 4; u++) {
        float4 v = *(const float4*)(x + base + u * 4);
        __half2* yp = (__half2*)(y + base + u * 4);
        yp[0] = __floats2half2_rn(v.x, v.y);
        yp[1] = __floats2half2_rn(v.z, v.w);
    }
}

// ---------------- fp32 -> fp16 hi/lo split (weights) ----------------
__global__ void splitw_kernel(const float* __restrict__ x,
                              __half* __restrict__ h, __half* __restrict__ l)
{
    size_t base = ((size_t)blockIdx.x * 256 + threadIdx.x) * 16;
#pragma unroll
    for (int u = 0; u < 4; u++) {
        float4 v = *(const float4*)(x + base + u * 4);
        __half h0 = __float2half_rn(v.x), h1 = __float2half_rn(v.y);
        __half h2 = __float2half_rn(v.z), h3 = __float2half_rn(v.w);
        __half l0 = __float2half_rn(v.x - __half2float(h0));
        __half l1 = __float2half_rn(v.y - __half2float(h1));
        __half l2 = __float2half_rn(v.z - __half2float(h2));
        __half l3 = __float2half_rn(v.w - __half2float(h3));
        __half2* hp = (__half2*)(h + base + u * 4);
        hp[0] = __half2{h0, h1}; hp[1] = __half2{h2, h3};
        __half2* lp = (__half2*)(l + base + u * 4);
        lp[0] = __half2{l0, l1}; lp[1] = __half2{l2, l3};
    }
}

// ---------------- ptx helpers ----------------
#define LDSM4(R, addr) \
    asm volatile("ldmatrix.sync.aligned.m8n8.x4.shared.b16 {%0,%1,%2,%3},[%4];" \
        : "=r"((R)[0]), "=r"((R)[1]), "=r"((R)[2]), "=r"((R)[3]) : "r"(addr))
#define LDSM4T(R, addr) \
    asm volatile("ldmatrix.sync.aligned.m8n8.x4.trans.shared.b16 {%0,%1,%2,%3},[%4];" \
        : "=r"((R)[0]), "=r"((R)[1]), "=r"((R)[2]), "=r"((R)[3]) : "r"(addr))
#define MMA_F16(C, A, B) \
    asm volatile("mma.sync.aligned.m16n8k16.row.col.f32.f16.f16.f32 " \
        "{%0,%1,%2,%3},{%4,%5,%6,%7},{%8,%9},{%0,%1,%2,%3};" \
        : "+f"((C)[0]), "+f"((C)[1]), "+f"((C)[2]), "+f"((C)[3]) \
        : "r"((A)[0]), "r"((A)[1]), "r"((A)[2]), "r"((A)[3]), "r"((B)[0]), "r"((B)[1]))
#define MMA_F16_B2(C, A, B0, B1) \
    asm volatile("mma.sync.aligned.m16n8k16.row.col.f32.f16.f16.f32 " \
        "{%0,%1,%2,%3},{%4,%5,%6,%7},{%8,%9},{%0,%1,%2,%3};" \
        : "+f"((C)[0]), "+f"((C)[1]), "+f"((C)[2]), "+f"((C)[3]) \
        : "r"((A)[0]), "r"((A)[1]), "r"((A)[2]), "r"((A)[3]), "r"(B0), "r"(B1))

__device__ __forceinline__ void cp16(const void* dst, const void* src) {
    unsigned d = (unsigned)__cvta_generic_to_shared(dst);
    asm volatile("cp.async.cg.shared.global [%0],[%1],16;" :: "r"(d), "l"(src));
}
#define CP_COMMIT() asm volatile("cp.async.commit_group;")
#define CP_WAIT0()  asm volatile("cp.async.wait_group 0;")
#define CP_WAIT1()  asm volatile("cp.async.wait_group 1;")

// ---------------- fp16 GEMM, NB = B-operand term count (1 or 2) ----------
#define A_LD 40
#define B_LD 136
#define SA_ELEMS (128 * A_LD)
#define SB_ELEMS (32 * B_LD)
#define GSTAGE(NB) (SA_ELEMS + (NB) * SB_ELEMS)
#define GEMM_SMEM(NB) (GSTAGE(NB) * 3 * 2)

template<int NB>
__global__ __launch_bounds__(256, 1) void gemm_fp16_kernel(
    const __half* __restrict__ A,
    const __half* __restrict__ Bh, const __half* __restrict__ Bl,
    const float* __restrict__ bias,
    float* __restrict__ Cf,
    __half* __restrict__ C16,
    int M, int N, int K)
{
    extern __shared__ __half dsm[];
    constexpr int GST = GSTAGE(NB);

    const int tid  = threadIdx.x;
    const int lane = tid & 31;
    const int wid  = tid >> 5;
    const int wm   = wid & 3;
    const int wn   = wid >> 2;
    const int bm   = blockIdx.y * 128;
    const int bn   = blockIdx.x * 128;

    const int ar = tid >> 1;
    const int ac = (tid & 1) * 16;
    const int br = tid >> 4;
    const int bc = (tid & 15) * 8;

    float c[2][8][4];
#pragma unroll
    for (int mi = 0; mi < 2; mi++)
#pragma unroll
        for (int ni = 0; ni < 8; ni++)
#pragma unroll
            for (int r = 0; r < 4; r++) c[mi][ni][r] = 0.f;

    const int iters = K >> 5;

    auto load_stage = [&](int s, int it) {
        int k0 = it << 5;
        __half* st  = dsm + s * GST;
        __half* pA  = st;
        __half* pBh = st + SA_ELEMS;
        cp16(pA + ar * A_LD + ac,      A + (size_t)(bm + ar) * K + k0 + ac);
        cp16(pA + ar * A_LD + ac + 8,  A + (size_t)(bm + ar) * K + k0 + ac + 8);
        cp16(pBh + br * B_LD + bc,        Bh + (size_t)(k0 + br) * N + bn + bc);
        cp16(pBh + (br + 16) * B_LD + bc, Bh + (size_t)(k0 + br + 16) * N + bn + bc);
        if (NB == 2) {
            __half* pBl = pBh + SB_ELEMS;
            cp16(pBl + br * B_LD + bc,        Bl + (size_t)(k0 + br) * N + bn + bc);
            cp16(pBl + (br + 16) * B_LD + bc, Bl + (size_t)(k0 + br + 16) * N + bn + bc);
        }
    };

    load_stage(0, 0); CP_COMMIT();
    load_stage(1, 1); CP_COMMIT();

    for (int it = 0; it < iters; it++) {
        if (it == iters - 1) { CP_WAIT0(); } else { CP_WAIT1(); }
        __syncthreads();
        if (it + 2 < iters) { load_stage((it + 2) % 3, it + 2); CP_COMMIT(); }

        const __half* st = dsm + (it % 3) * GST;
        const unsigned sA_b  = (unsigned)__cvta_generic_to_shared(st);
        const unsigned sBh_b = sA_b + SA_ELEMS * 2;
        const unsigned sBl_b = sBh_b + SB_ELEMS * 2;

#pragma unroll
        for (int kh = 0; kh < 2; kh++) {
            unsigned af[2][4];
#pragma unroll
            for (int mi = 0; mi < 2; mi++) {
                unsigned off = (unsigned)(((wm * 32 + mi * 16 + (lane & 15)) * A_LD
                                           + kh * 16 + ((lane >> 4) << 3)) * 2);
                LDSM4(af[mi], sA_b + off);
            }
#pragma unroll
            for (int p = 0; p < 4; p++) {
                unsigned bh[4];
                unsigned off = (unsigned)(((kh * 16 + (lane & 15)) * B_LD
                                           + wn * 64 + p * 16 + ((lane >> 4) << 3)) * 2);
                LDSM4T(bh, sBh_b + off);
#pragma unroll
                for (int mi = 0; mi < 2; mi++) {
                    MMA_F16(c[mi][2 * p],     af[mi], bh);
                    MMA_F16(c[mi][2 * p + 1], af[mi], bh + 2);
                }
                if (NB == 2) {
                    unsigned bl[4];
                    LDSM4T(bl, sBl_b + off);
#pragma unroll
                    for (int mi = 0; mi < 2; mi++) {
                        MMA_F16(c[mi][2 * p],     af[mi], bl);
                        MMA_F16(c[mi][2 * p + 1], af[mi], bl + 2);
                    }
                }
            }
        }
    }

    const int row0 = bm + wm * 32 + (lane >> 2);
    const int col0 = bn + wn * 64 + (lane & 3) * 2;
#pragma unroll
    for (int mi = 0; mi < 2; mi++) {
#pragma unroll
        for (int ni = 0; ni < 8; ni++) {
            int r  = row0 + mi * 16;
            int cc = col0 + ni * 8;
            float b0 = bias ? bias[cc] : 0.f;
            float b1 = bias ? bias[cc + 1] : 0.f;
            float v0 = c[mi][ni][0] + b0, v1 = c[mi][ni][1] + b1;
            float v2 = c[mi][ni][2] + b0, v3 = c[mi][ni][3] + b1;
            if (Cf) {
                *(float2*)(Cf + (size_t)r * N + cc)       = float2{v0, v1};
                *(float2*)(Cf + (size_t)(r + 8) * N + cc) = float2{v2, v3};
            } else {
                *(__half2*)(C16 + (size_t)r * N + cc)       = __floats2half2_rn(v0, v1);
                *(__half2*)(C16 + (size_t)(r + 8) * N + cc) = __floats2half2_rn(v2, v3);
            }
        }
    }
}

// ------ fused RMSNorm + RoPE -> single fp16 --------
__global__ void rmsnorm_rope_out_kernel(
    const float* __restrict__ src,
    __half* __restrict__ out16,
    const float* __restrict__ w0, const float* __restrict__ w1, int split,
    const float* __restrict__ cos_t, const float* __restrict__ sin_t,
    float eps)
{
    const int row = blockIdx.x;
    const int h   = blockIdx.y;
    const int d   = threadIdx.x;

    const float* x = src + (size_t)row * INNER + h * HEAD_DIM;
    float v = x[d];
    float ss = v * v;
#pragma unroll
    for (int o = 16; o; o >>= 1) ss += __shfl_xor_sync(0xffffffffu, ss, o);
    __shared__ float red[4];
    if ((d & 31) == 0) red[d >> 5] = ss;
    __syncthreads();
    float tot = red[0] + red[1] + red[2] + red[3];
    float r = rsqrtf(tot * (1.0f / HEAD_DIM) + eps);

    const float* w = (row < split) ? w0 : w1;
    float y = v * r;
    if (w) y *= w[d];

    float other = __shfl_xor_sync(0xffffffffu, y, 1);
    float c = cos_t[(size_t)row * HEAD_DIM + d];
    float s = sin_t[(size_t)row * HEAD_DIM + d];
    float rot = (d & 1) ? other : -other;
    float out = y * c + rot * s;

    out16[(size_t)row * INNER + h * HEAD_DIM + d] = __float2half_rn(out);
}

// ---------------- tensor-core flash attention (fp16, cp.async KV) --------
#define LDQ 136
#define Q_ELEMS (128 * LDQ)
#define KV_ELEMS (64 * LDQ)
#define KVSTAGE_ELEMS (2 * KV_ELEMS)   // K, V single fp16
#define ATTN_SMEM_BYTES ((Q_ELEMS + 2 * KVSTAGE_ELEMS) * 2)

__global__ __launch_bounds__(256, 1) void attn_fp16_kernel(
    const __half* __restrict__ Q16,
    const __half* __restrict__ K16,
    const __half* __restrict__ V16,
    __half* __restrict__ O16)
{
    extern __shared__ __half smh[];
    __half* sQ = smh;
    __half* kvBase = sQ + Q_ELEMS;

    const int h    = blockIdx.y;
    const int q0   = blockIdx.x * 128;
    const int tid  = threadIdx.x;
    const int lane = tid & 31;
    const int w    = tid >> 5;
    const float scale = 0.08838834764831845f;

    const unsigned sQ_b = (unsigned)__cvta_generic_to_shared(sQ);

    const int krow = tid >> 2;
    const int kcol = (tid & 3) * 32;

    auto load_kv = [&](int s, int kt) {
        __half* st = kvBase + s * KVSTAGE_ELEMS;
        __half* pK = st;
        __half* pV = st + KV_ELEMS;
#pragma unroll
        for (int seg = 0; seg < 4; seg++) {
            int cc = kcol + seg * 8;
            size_t g = (size_t)(kt * 64 + krow) * INNER + h * HEAD_DIM + cc;
            cp16(pK + krow * LDQ + cc, K16 + g);
            cp16(pV + krow * LDQ + cc, V16 + g);
        }
    };

    load_kv(0, 0); CP_COMMIT();

    for (int i = tid; i < 128 * 16; i += 256) {
        int row = i >> 4;
        int c8  = (i & 15) * 8;
        size_t g = (size_t)(q0 + row) * INNER + h * HEAD_DIM + c8;
        *(uint4*)(sQ + row * LDQ + c8) = *(const uint4*)(Q16 + g);
    }

    float o[16][4];
#pragma unroll
    for (int nt = 0; nt < 16; nt++)
#pragma unroll
        for (int r = 0; r < 4; r++) o[nt][r] = 0.f;
    float m_lo = -1e30f, m_hi = -1e30f, l_lo = 0.f, l_hi = 0.f;

    const int NT = SK / 64;
    for (int kt = 0; kt < NT; kt++) {
        CP_WAIT0();
        __syncthreads();
        if (kt + 1 < NT) { load_kv((kt + 1) & 1, kt + 1); CP_COMMIT(); }

        const __half* st = kvBase + (kt & 1) * KVSTAGE_ELEMS;
        const unsigned sK_b = (unsigned)__cvta_generic_to_shared(st);
        const unsigned sV_b = sK_b + KV_ELEMS * 2;

        float c[8][4];
#pragma unroll
        for (int n = 0; n < 8; n++)
#pragma unroll
            for (int r = 0; r < 4; r++) c[n][r] = 0.f;

#pragma unroll
        for (int kk = 0; kk < 8; kk++) {
            unsigned aq[4];
            unsigned qoff = (unsigned)(((w * 16 + (lane & 15)) * LDQ
                                        + kk * 16 + ((lane >> 4) << 3)) * 2);
            LDSM4(aq, sQ_b + qoff);
#pragma unroll
            for (int ng = 0; ng < 4; ng++) {
                unsigned bh[4];
                unsigned koff = (unsigned)(((ng * 16 + (lane & 15)) * LDQ
                                            + kk * 16 + ((lane >> 4) << 3)) * 2);
                LDSM4(bh, sK_b + koff);
                MMA_F16_B2(c[2 * ng],     aq, bh[0], bh[2]);
                MMA_F16_B2(c[2 * ng + 1], aq, bh[1], bh[3]);
            }
        }

        float tmx_lo = -1e30f, tmx_hi = -1e30f;
#pragma unroll
        for (int n = 0; n < 8; n++) {
            c[n][0] *= scale; c[n][1] *= scale; c[n][2] *= scale; c[n][3] *= scale;
            tmx_lo = fmaxf(tmx_lo, fmaxf(c[n][0], c[n][1]));
            tmx_hi = fmaxf(tmx_hi, fmaxf(c[n][2], c[n][3]));
        }
        tmx_lo = fmaxf(tmx_lo, __shfl_xor_sync(0xffffffffu, tmx_lo, 1));
        tmx_lo = fmaxf(tmx_lo, __shfl_xor_sync(0xffffffffu, tmx_lo, 2));
        tmx_hi = fmaxf(tmx_hi, __shfl_xor_sync(0xffffffffu, tmx_hi, 1));
        tmx_hi = fmaxf(tmx_hi, __shfl_xor_sync(0xffffffffu, tmx_hi, 2));

        float mn_lo = fmaxf(m_lo, tmx_lo);
        float mn_hi = fmaxf(m_hi, tmx_hi);
        float al_lo = __expf(m_lo - mn_lo);
        float al_hi = __expf(m_hi - mn_hi);
        m_lo = mn_lo; m_hi = mn_hi;

        unsigned ph[8][2];
        float sum_lo = 0.f, sum_hi = 0.f;
#pragma unroll
        for (int n = 0; n < 8; n++) {
            float p0 = __expf(c[n][0] - m_lo);
            float p1 = __expf(c[n][1] - m_lo);
            float p2 = __expf(c[n][2] - m_hi);
            float p3 = __expf(c[n][3] - m_hi);
            sum_lo += p0 + p1;
            sum_hi += p2 + p3;
            __half2 h01 = __floats2half2_rn(p0, p1);
            __half2 h23 = __floats2half2_rn(p2, p3);
            ph[n][0] = *(unsigned*)&h01; ph[n][1] = *(unsigned*)&h23;
        }
        sum_lo += __shfl_xor_sync(0xffffffffu, sum_lo, 1);
        sum_lo += __shfl_xor_sync(0xffffffffu, sum_lo, 2);
        sum_hi += __shfl_xor_sync(0xffffffffu, sum_hi, 1);
        sum_hi += __shfl_xor_sync(0xffffffffu, sum_hi, 2);
        l_lo = l_lo * al_lo + sum_lo;
        l_hi = l_hi * al_hi + sum_hi;

#pragma unroll
        for (int nt = 0; nt < 16; nt++) {
            o[nt][0] *= al_lo; o[nt][1] *= al_lo;
            o[nt][2] *= al_hi; o[nt][3] *= al_hi;
        }

#pragma unroll
        for (int j = 0; j < 4; j++) {
            unsigned Ap[4] = {ph[2 * j][0], ph[2 * j][1], ph[2 * j + 1][0], ph[2 * j + 1][1]};
#pragma unroll
            for (int dp = 0; dp < 8; dp++) {
                unsigned v4[4];
                unsigned voff = (unsigned)(((j * 16 + (lane & 15)) * LDQ
                                            + dp * 16 + ((lane >> 4) << 3)) * 2);
                LDSM4T(v4, sV_b + voff);
                MMA_F16_B2(o[2 * dp],     Ap, v4[0], v4[1]);
                MMA_F16_B2(o[2 * dp + 1], Ap, v4[2], v4[3]);
            }
        }
        __syncthreads();
    }

    float inv_lo = 1.0f / l_lo;
    float inv_hi = 1.0f / l_hi;
    const int row_lo = q0 + w * 16 + (lane >> 2);
    const int row_hi = row_lo + 8;
    const int cbase  = h * HEAD_DIM + (lane & 3) * 2;
#pragma unroll
    for (int nt = 0; nt < 16; nt++) {
        int d = cbase + nt * 8;
        *(__half2*)(O16 + (size_t)row_lo * INNER + d) =
            __floats2half2_rn(o[nt][0] * inv_lo, o[nt][1] * inv_lo);
        *(__half2*)(O16 + (size_t)row_hi * INNER + d) =
            __floats2half2_rn(o[nt][2] * inv_hi, o[nt][3] * inv_hi);
    }
}

// ---------------- launch ----------------
extern "C" void kernel_launch(void* const* d_in, const int* in_sizes, int n_in,
                              void* d_out, int out_size)
{
    (void)in_sizes; (void)n_in; (void)out_size;
    const float* hid   = (const float*)d_in[0];
    const float* enc   = (const float*)d_in[1];
    const float* ref   = (const float*)d_in[2];
    const float* rcos  = (const float*)d_in[3];
    const float* rsin  = (const float*)d_in[4];
    const float* ccos  = (const float*)d_in[5];
    const float* csin  = (const float*)d_in[6];
    const float* Wq    = (const float*)d_in[7];
    const float* bq    = (const float*)d_in[8];
    const float* Wk    = (const float*)d_in[9];
    const float* bk    = (const float*)d_in[10];
    const float* Wv    = (const float*)d_in[11];
    const float* bv    = (const float*)d_in[12];
    const float* Waq   = (const float*)d_in[13];
    const float* baq   = (const float*)d_in[14];
    const float* Wak   = (const float*)d_in[15];
    const float* bak   = (const float*)d_in[16];
    const float* Wav   = (const float*)d_in[17];
    const float* bav   = (const float*)d_in[18];
    const float* Wout  = (const float*)d_in[19];
    const float* bout  = (const float*)d_in[20];
    const float* Wadd  = (const float*)d_in[21];
    const float* badd  = (const float*)d_in[22];
    const float* nq_w  = (const float*)d_in[23];
    const float* nk_w  = (const float*)d_in[24];
    const float* naq_w = (const float*)d_in[25];
    const float* nak_w = (const float*)d_in[26];
    const float* lkd   = (const float*)d_in[27];
    const float* lku   = (const float*)d_in[28];
    const float* lvd   = (const float*)d_in[29];
    const float* lvu   = (const float*)d_in[30];

    float *q, *k;
    cudaGetSymbolAddress((void**)&q, g_q);
    cudaGetSymbolAddress((void**)&k, g_k);

    __half *Wh, *Wl, *Uh, *x16, *t16, *o16, *q16, *k16, *v16;
    cudaGetSymbolAddress((void**)&Wh, g_W16h);
    cudaGetSymbolAddress((void**)&Wl, g_W16l);
    cudaGetSymbolAddress((void**)&Uh, g_U16h);
    cudaGetSymbolAddress((void**)&x16, g_x16);
    cudaGetSymbolAddress((void**)&t16, g_t16);
    cudaGetSymbolAddress((void**)&o16, g_o16);
    cudaGetSymbolAddress((void**)&q16, g_q16);
    cudaGetSymbolAddress((void**)&k16, g_k16);
    cudaGetSymbolAddress((void**)&v16, g_v16);

    cudaFuncSetAttribute(gemm_fp16_kernel<1>, cudaFuncAttributeMaxDynamicSharedMemorySize,
                         GEMM_SMEM(1));
    cudaFuncSetAttribute(gemm_fp16_kernel<2>, cudaFuncAttributeMaxDynamicSharedMemorySize,
                         GEMM_SMEM(2));
    cudaFuncSetAttribute(attn_fp16_kernel, cudaFuncAttributeMaxDynamicSharedMemorySize,
                         ATTN_SMEM_BYTES);

    auto cvt = [](const float* src, __half* dst, size_t n) {
        cvt16_kernel<<<(unsigned)(n >> 12), 256>>>(src, dst);
    };
    auto splitw = [](const float* src, __half* h, __half* l, size_t n) {
        splitw_kernel<<<(unsigned)(n >> 12), 256>>>(src, h, l);
    };
    auto g1F = [](const __half* A, const __half* B, const float* bi, float* C,
                  int M, int N, int K) {
        gemm_fp16_kernel<1><<<dim3(N / 128, M / 128), 256, GEMM_SMEM(1)>>>(
            A, B, nullptr, bi, C, nullptr, M, N, K);
    };
    auto g1H = [](const __half* A, const __half* B, const float* bi, __half* C16,
                  int M, int N, int K) {
        gemm_fp16_kernel<1><<<dim3(N / 128, M / 128), 256, GEMM_SMEM(1)>>>(
            A, B, nullptr, bi, nullptr, C16, M, N, K);
    };
    auto g2F = [](const __half* A, const __half* Bh, const __half* Bl,
                  const float* bi, float* C, int M, int N, int K) {
        gemm_fp16_kernel<2><<<dim3(N / 128, M / 128), 256, GEMM_SMEM(2)>>>(
            A, Bh, Bl, bi, C, nullptr, M, N, K);
    };

    const size_t WSZ = (size_t)INNER * INNER;
    const size_t USZ = (size_t)INNER * RANK;
    const size_t off_hid = 0;
    const size_t off_enc = (size_t)S_IMG * INNER;
    const size_t off_ref = (size_t)(S_IMG + S_TXT) * INNER;

    // L1-L5: deps for the big GEMM; L6 = big GEMM (profiled by ncu -s 5 -c 1)
    cvt(hid, x16 + off_hid, (size_t)S_IMG * INNER);                     // L1
    cvt(Wq, Wh + 1 * WSZ, WSZ);                                         // L2
    cvt(enc, x16 + off_enc, (size_t)S_TXT * INNER);                     // L3
    cvt(ref, x16 + off_ref, (size_t)S_REF * INNER);                     // L4
    cvt(Waq, Wh + 0 * WSZ, WSZ);                                        // L5
    g1F(x16 + off_hid, Wh + 1 * WSZ, bq,                                // L6
        q + (size_t)S_TXT * INNER, S_IMG, INNER, INNER);

    cvt(Wak, Wh + 2 * WSZ, WSZ);
    cvt(Wk,  Wh + 3 * WSZ, WSZ);
    cvt(Wav, Wh + 4 * WSZ, WSZ);
    cvt(Wv,  Wh + 5 * WSZ, WSZ);
    splitw(Wout, Wh + 6 * WSZ, Wl + 0 * WSZ, WSZ);
    splitw(Wadd, Wh + 7 * WSZ, Wl + 1 * WSZ, WSZ);
    cvt(lkd, Uh + 0 * USZ, USZ);
    cvt(lvd, Uh + 1 * USZ, USZ);
    cvt(lku, Uh + 2 * USZ, USZ);
    cvt(lvu, Uh + 3 * USZ, USZ);

    g1F(x16 + off_enc, Wh + 0 * WSZ, baq, q,                         S_TXT, INNER, INNER);
    g1F(x16 + off_enc, Wh + 2 * WSZ, bak, k,                         S_TXT, INNER, INNER);
    g1F(x16 + off_hid, Wh + 3 * WSZ, bk,  k + (size_t)S_TXT * INNER, S_IMG, INNER, INNER);
    g1H(x16 + off_enc, Wh + 4 * WSZ, bav, v16,                       S_TXT, INNER, INNER);
    g1H(x16 + off_hid, Wh + 5 * WSZ, bv,  v16 + (size_t)S_TXT * INNER, S_IMG, INNER, INNER);

    // LoRA ref branch
    g1H(x16 + off_ref, Uh + 0 * USZ, nullptr, t16, S_REF, RANK, INNER);
    g1F(t16, Uh + 2 * USZ, nullptr, k + (size_t)SQ * INNER, S_REF, INNER, RANK);
    g1H(x16 + off_ref, Uh + 1 * USZ, nullptr, t16, S_REF, RANK, INNER);
    g1H(t16, Uh + 3 * USZ, nullptr, v16 + (size_t)SQ * INNER, S_REF, INNER, RANK);

    // RMSNorm + RoPE -> single fp16 q/k
    rmsnorm_rope_out_kernel<<<dim3(SQ, HEADS), 128>>>(
        q, q16, naq_w, nq_w, S_TXT, rcos, rsin, 1e-6f);
    rmsnorm_rope_out_kernel<<<dim3(SQ, HEADS), 128>>>(
        k, k16, nak_w, nk_w, S_TXT, rcos, rsin, 1e-6f);
    rmsnorm_rope_out_kernel<<<dim3(S_REF, HEADS), 128>>>(
        k + (size_t)SQ * INNER, k16 + (size_t)SQ * INNER,
        nullptr, nullptr, 0, ccos, csin, 1e-5f);

    attn_fp16_kernel<<<dim3(SQ / 128, HEADS), 256, ATTN_SMEM_BYTES>>>(
        q16, k16, v16, o16);

    float* outp = (float*)d_out;
    g2F(o16 + (size_t)S_TXT * INNER, Wh + 6 * WSZ, Wl + 0 * WSZ, bout,
        outp, S_IMG, INNER, INNER);
    g2F(o16, Wh + 7 * WSZ, Wl + 1 * WSZ, badd,
        outp + (size_t)S_IMG * INNER, S_TXT, INNER, INNER);
}

// round 12
// speedup vs baseline: 1.9362x; 1.0275x over previous
#include <cuda_runtime.h>
#include <cuda_fp16.h>
#include <cstdint>
#include <cstddef>

#define HEADS 24
#define HEAD_DIM 128
#define INNER 3072
#define RANK 1024
#define S_IMG 2048
#define S_TXT 512
#define S_REF 2048
#define SQ (S_TXT + S_IMG)          // 2560
#define SK (S_TXT + S_IMG + S_REF)  // 4608

// ---------------- scratch (device globals; no allocation) ----------------
__device__ float g_q[(size_t)SQ * INNER];
__device__ float g_k[(size_t)SK * INNER];

__device__ __half g_W16h[(size_t)8 * INNER * INNER];
__device__ __half g_U16h[(size_t)4 * INNER * RANK];
__device__ __half g_x16[(size_t)(S_IMG + S_TXT + S_REF) * INNER];
__device__ __half g_t16[(size_t)S_REF * RANK];
__device__ __half g_o16[(size_t)SQ * INNER];
__device__ __half g_q16[(size_t)SQ * INNER];
__device__ __half g_k16[(size_t)SK * INNER];
__device__ __half g_v16[(size_t)SK * INNER];

// ---------------- fp32 -> fp16 convert (32 elems/thread, MLP 8) ----------
__global__ void cvt16_kernel(const float* __restrict__ x, __half* __restrict__ y)
{
    size_t base = ((size_t)blockIdx.x * 256 + threadIdx.x) * 32;
    float4 v[8];
#pragma unroll
    for (int u = 0; u < 8; u++) v[u] = *(const float4*)(x + base + u * 4);
#pragma unroll
    for (int u = 0; u < 8; u++) {
        __half2* yp = (__half2*)(y + base + u * 4);
        yp[0] = __floats2half2_rn(v[u].x, v[u].y);
        yp[1] = __floats2half2_rn(v[u].z, v[u].w);
    }
}

// ---------------- ptx helpers ----------------
#define LDSM4(R, addr) \
    asm volatile("ldmatrix.sync.aligned.m8n8.x4.shared.b16 {%0,%1,%2,%3},[%4];" \
        : "=r"((R)[0]), "=r"((R)[1]), "=r"((R)[2]), "=r"((R)[3]) : "r"(addr))
#define LDSM4T(R, addr) \
    asm volatile("ldmatrix.sync.aligned.m8n8.x4.trans.shared.b16 {%0,%1,%2,%3},[%4];" \
        : "=r"((R)[0]), "=r"((R)[1]), "=r"((R)[2]), "=r"((R)[3]) : "r"(addr))
#define MMA_F16(C, A, B) \
    asm volatile("mma.sync.aligned.m16n8k16.row.col.f32.f16.f16.f32 " \
        "{%0,%1,%2,%3},{%4,%5,%6,%7},{%8,%9},{%0,%1,%2,%3};" \
        : "+f"((C)[0]), "+f"((C)[1]), "+f"((C)[2]), "+f"((C)[3]) \
        : "r"((A)[0]), "r"((A)[1]), "r"((A)[2]), "r"((A)[3]), "r"((B)[0]), "r"((B)[1]))
#define MMA_F16_B2(C, A, B0, B1) \
    asm volatile("mma.sync.aligned.m16n8k16.row.col.f32.f16.f16.f32 " \
        "{%0,%1,%2,%3},{%4,%5,%6,%7},{%8,%9},{%0,%1,%2,%3};" \
        : "+f"((C)[0]), "+f"((C)[1]), "+f"((C)[2]), "+f"((C)[3]) \
        : "r"((A)[0]), "r"((A)[1]), "r"((A)[2]), "r"((A)[3]), "r"(B0), "r"(B1))

__device__ __forceinline__ void cp16(const void* dst, const void* src) {
    unsigned d = (unsigned)__cvta_generic_to_shared(dst);
    asm volatile("cp.async.cg.shared.global [%0],[%1],16;" :: "r"(d), "l"(src));
}
#define CP_COMMIT() asm volatile("cp.async.commit_group;")
#define CP_WAIT0()  asm volatile("cp.async.wait_group 0;")
#define CP_WAIT1()  asm volatile("cp.async.wait_group 1;")

// ---------------- fp16 GEMM (single-term B, 3-stage cp.async) ------------
#define A_LD 40
#define B_LD 136
#define SA_ELEMS (128 * A_LD)
#define SB_ELEMS (32 * B_LD)
#define GSTAGE (SA_ELEMS + SB_ELEMS)
#define GEMM_SMEM_BYTES (GSTAGE * 3 * 2)

__global__ __launch_bounds__(256, 1) void gemm_fp16_kernel(
    const __half* __restrict__ A,
    const __half* __restrict__ B,
    const float* __restrict__ bias,
    float* __restrict__ Cf,
    __half* __restrict__ C16,
    int M, int N, int K)
{
    extern __shared__ __half dsm[];

    const int tid  = threadIdx.x;
    const int lane = tid & 31;
    const int wid  = tid >> 5;
    const int wm   = wid & 3;
    const int wn   = wid >> 2;
    const int bm   = blockIdx.y * 128;
    const int bn   = blockIdx.x * 128;

    const int ar = tid >> 1;
    const int ac = (tid & 1) * 16;
    const int br = tid >> 4;
    const int bc = (tid & 15) * 8;

    float c[2][8][4];
#pragma unroll
    for (int mi = 0; mi < 2; mi++)
#pragma unroll
        for (int ni = 0; ni < 8; ni++)
#pragma unroll
            for (int r = 0; r < 4; r++) c[mi][ni][r] = 0.f;

    const int iters = K >> 5;

    auto load_stage = [&](int s, int it) {
        int k0 = it << 5;
        __half* st = dsm + s * GSTAGE;
        __half* pA = st;
        __half* pB = st + SA_ELEMS;
        cp16(pA + ar * A_LD + ac,      A + (size_t)(bm + ar) * K + k0 + ac);
        cp16(pA + ar * A_LD + ac + 8,  A + (size_t)(bm + ar) * K + k0 + ac + 8);
        cp16(pB + br * B_LD + bc,        B + (size_t)(k0 + br) * N + bn + bc);
        cp16(pB + (br + 16) * B_LD + bc, B + (size_t)(k0 + br + 16) * N + bn + bc);
    };

    load_stage(0, 0); CP_COMMIT();
    load_stage(1, 1); CP_COMMIT();

    for (int it = 0; it < iters; it++) {
        if (it == iters - 1) { CP_WAIT0(); } else { CP_WAIT1(); }
        __syncthreads();
        if (it + 2 < iters) { load_stage((it + 2) % 3, it + 2); CP_COMMIT(); }

        const __half* st = dsm + (it % 3) * GSTAGE;
        const unsigned sA_b = (unsigned)__cvta_generic_to_shared(st);
        const unsigned sB_b = sA_b + SA_ELEMS * 2;

#pragma unroll
        for (int kh = 0; kh < 2; kh++) {
            unsigned af[2][4];
#pragma unroll
            for (int mi = 0; mi < 2; mi++) {
                unsigned off = (unsigned)(((wm * 32 + mi * 16 + (lane & 15)) * A_LD
                                           + kh * 16 + ((lane >> 4) << 3)) * 2);
                LDSM4(af[mi], sA_b + off);
            }
#pragma unroll
            for (int p = 0; p < 4; p++) {
                unsigned bh[4];
                unsigned off = (unsigned)(((kh * 16 + (lane & 15)) * B_LD
                                           + wn * 64 + p * 16 + ((lane >> 4) << 3)) * 2);
                LDSM4T(bh, sB_b + off);
#pragma unroll
                for (int mi = 0; mi < 2; mi++) {
                    MMA_F16(c[mi][2 * p],     af[mi], bh);
                    MMA_F16(c[mi][2 * p + 1], af[mi], bh + 2);
                }
            }
        }
    }

    const int row0 = bm + wm * 32 + (lane >> 2);
    const int col0 = bn + wn * 64 + (lane & 3) * 2;
#pragma unroll
    for (int mi = 0; mi < 2; mi++) {
#pragma unroll
        for (int ni = 0; ni < 8; ni++) {
            int r  = row0 + mi * 16;
            int cc = col0 + ni * 8;
            float b0 = bias ? bias[cc] : 0.f;
            float b1 = bias ? bias[cc + 1] : 0.f;
            float v0 = c[mi][ni][0] + b0, v1 = c[mi][ni][1] + b1;
            float v2 = c[mi][ni][2] + b0, v3 = c[mi][ni][3] + b1;
            if (Cf) {
                *(float2*)(Cf + (size_t)r * N + cc)       = float2{v0, v1};
                *(float2*)(Cf + (size_t)(r + 8) * N + cc) = float2{v2, v3};
            } else {
                *(__half2*)(C16 + (size_t)r * N + cc)       = __floats2half2_rn(v0, v1);
                *(__half2*)(C16 + (size_t)(r + 8) * N + cc) = __floats2half2_rn(v2, v3);
            }
        }
    }
}

// ------ fused RMSNorm + RoPE -> single fp16 --------
__global__ void rmsnorm_rope_out_kernel(
    const float* __restrict__ src,
    __half* __restrict__ out16,
    const float* __restrict__ w0, const float* __restrict__ w1, int split,
    const float* __restrict__ cos_t, const float* __restrict__ sin_t,
    float eps)
{
    const int row = blockIdx.x;
    const int h   = blockIdx.y;
    const int d   = threadIdx.x;

    const float* x = src + (size_t)row * INNER + h * HEAD_DIM;
    float v = x[d];
    float ss = v * v;
#pragma unroll
    for (int o = 16; o; o >>= 1) ss += __shfl_xor_sync(0xffffffffu, ss, o);
    __shared__ float red[4];
    if ((d & 31) == 0) red[d >> 5] = ss;
    __syncthreads();
    float tot = red[0] + red[1] + red[2] + red[3];
    float r = rsqrtf(tot * (1.0f / HEAD_DIM) + eps);

    const float* w = (row < split) ? w0 : w1;
    float y = v * r;
    if (w) y *= w[d];

    float other = __shfl_xor_sync(0xffffffffu, y, 1);
    float c = cos_t[(size_t)row * HEAD_DIM + d];
    float s = sin_t[(size_t)row * HEAD_DIM + d];
    float rot = (d & 1) ? other : -other;
    float out = y * c + rot * s;

    out16[(size_t)row * INNER + h * HEAD_DIM + d] = __float2half_rn(out);
}

// ---------------- tensor-core flash attention (fp16, cp.async KV) --------
#define LDQ 136
#define Q_ELEMS (128 * LDQ)
#define KV_ELEMS (64 * LDQ)
#define KVSTAGE_ELEMS (2 * KV_ELEMS)
#define ATTN_SMEM_BYTES ((Q_ELEMS + 2 * KVSTAGE_ELEMS) * 2)

__global__ __launch_bounds__(256, 1) void attn_fp16_kernel(
    const __half* __restrict__ Q16,
    const __half* __restrict__ K16,
    const __half* __restrict__ V16,
    __half* __restrict__ O16)
{
    extern __shared__ __half smh[];
    __half* sQ = smh;
    __half* kvBase = sQ + Q_ELEMS;

    const int h    = blockIdx.y;
    const int q0   = blockIdx.x * 128;
    const int tid  = threadIdx.x;
    const int lane = tid & 31;
    const int w    = tid >> 5;
    const float scale = 0.08838834764831845f;

    const unsigned sQ_b = (unsigned)__cvta_generic_to_shared(sQ);

    const int krow = tid >> 2;
    const int kcol = (tid & 3) * 32;

    auto load_kv = [&](int s, int kt) {
        __half* st = kvBase + s * KVSTAGE_ELEMS;
        __half* pK = st;
        __half* pV = st + KV_ELEMS;
#pragma unroll
        for (int seg = 0; seg < 4; seg++) {
            int cc = kcol + seg * 8;
            size_t g = (size_t)(kt * 64 + krow) * INNER + h * HEAD_DIM + cc;
            cp16(pK + krow * LDQ + cc, K16 + g);
            cp16(pV + krow * LDQ + cc, V16 + g);
        }
    };

    load_kv(0, 0); CP_COMMIT();

    for (int i = tid; i < 128 * 16; i += 256) {
        int row = i >> 4;
        int c8  = (i & 15) * 8;
        size_t g = (size_t)(q0 + row) * INNER + h * HEAD_DIM + c8;
        *(uint4*)(sQ + row * LDQ + c8) = *(const uint4*)(Q16 + g);
    }

    float o[16][4];
#pragma unroll
    for (int nt = 0; nt < 16; nt++)
#pragma unroll
        for (int r = 0; r < 4; r++) o[nt][r] = 0.f;
    float m_lo = -1e30f, m_hi = -1e30f, l_lo = 0.f, l_hi = 0.f;

    const int NT = SK / 64;
    for (int kt = 0; kt < NT; kt++) {
        CP_WAIT0();
        __syncthreads();
        if (kt + 1 < NT) { load_kv((kt + 1) & 1, kt + 1); CP_COMMIT(); }

        const __half* st = kvBase + (kt & 1) * KVSTAGE_ELEMS;
        const unsigned sK_b = (unsigned)__cvta_generic_to_shared(st);
        const unsigned sV_b = sK_b + KV_ELEMS * 2;

        float c[8][4];
#pragma unroll
        for (int n = 0; n < 8; n++)
#pragma unroll
            for (int r = 0; r < 4; r++) c[n][r] = 0.f;

#pragma unroll
        for (int kk = 0; kk < 8; kk++) {
            unsigned aq[4];
            unsigned qoff = (unsigned)(((w * 16 + (lane & 15)) * LDQ
                                        + kk * 16 + ((lane >> 4) << 3)) * 2);
            LDSM4(aq, sQ_b + qoff);
#pragma unroll
            for (int ng = 0; ng < 4; ng++) {
                unsigned bh[4];
                unsigned koff = (unsigned)(((ng * 16 + (lane & 15)) * LDQ
                                            + kk * 16 + ((lane >> 4) << 3)) * 2);
                LDSM4(bh, sK_b + koff);
                MMA_F16_B2(c[2 * ng],     aq, bh[0], bh[2]);
                MMA_F16_B2(c[2 * ng + 1], aq, bh[1], bh[3]);
            }
        }

        float tmx_lo = -1e30f, tmx_hi = -1e30f;
#pragma unroll
        for (int n = 0; n < 8; n++) {
            c[n][0] *= scale; c[n][1] *= scale; c[n][2] *= scale; c[n][3] *= scale;
            tmx_lo = fmaxf(tmx_lo, fmaxf(c[n][0], c[n][1]));
            tmx_hi = fmaxf(tmx_hi, fmaxf(c[n][2], c[n][3]));
        }
        tmx_lo = fmaxf(tmx_lo, __shfl_xor_sync(0xffffffffu, tmx_lo, 1));
        tmx_lo = fmaxf(tmx_lo, __shfl_xor_sync(0xffffffffu, tmx_lo, 2));
        tmx_hi = fmaxf(tmx_hi, __shfl_xor_sync(0xffffffffu, tmx_hi, 1));
        tmx_hi = fmaxf(tmx_hi, __shfl_xor_sync(0xffffffffu, tmx_hi, 2));

        float mn_lo = fmaxf(m_lo, tmx_lo);
        float mn_hi = fmaxf(m_hi, tmx_hi);
        float al_lo = __expf(m_lo - mn_lo);
        float al_hi = __expf(m_hi - mn_hi);
        m_lo = mn_lo; m_hi = mn_hi;

        unsigned ph[8][2];
        float sum_lo = 0.f, sum_hi = 0.f;
#pragma unroll
        for (int n = 0; n < 8; n++) {
            float p0 = __expf(c[n][0] - m_lo);
            float p1 = __expf(c[n][1] - m_lo);
            float p2 = __expf(c[n][2] - m_hi);
            float p3 = __expf(c[n][3] - m_hi);
            sum_lo += p0 + p1;
            sum_hi += p2 + p3;
            __half2 h01 = __floats2half2_rn(p0, p1);
            __half2 h23 = __floats2half2_rn(p2, p3);
            ph[n][0] = *(unsigned*)&h01; ph[n][1] = *(unsigned*)&h23;
        }
        sum_lo += __shfl_xor_sync(0xffffffffu, sum_lo, 1);
        sum_lo += __shfl_xor_sync(0xffffffffu, sum_lo, 2);
        sum_hi += __shfl_xor_sync(0xffffffffu, sum_hi, 1);
        sum_hi += __shfl_xor_sync(0xffffffffu, sum_hi, 2);
        l_lo = l_lo * al_lo + sum_lo;
        l_hi = l_hi * al_hi + sum_hi;

#pragma unroll
        for (int nt = 0; nt < 16; nt++) {
            o[nt][0] *= al_lo; o[nt][1] *= al_lo;
            o[nt][2] *= al_hi; o[nt][3] *= al_hi;
        }

#pragma unroll
        for (int j = 0; j < 4; j++) {
            unsigned Ap[4] = {ph[2 * j][0], ph[2 * j][1], ph[2 * j + 1][0], ph[2 * j + 1][1]};
#pragma unroll
            for (int dp = 0; dp < 8; dp++) {
                unsigned v4[4];
                unsigned voff = (unsigned)(((j * 16 + (lane & 15)) * LDQ
                                            + dp * 16 + ((lane >> 4) << 3)) * 2);
                LDSM4T(v4, sV_b + voff);
                MMA_F16_B2(o[2 * dp],     Ap, v4[0], v4[1]);
                MMA_F16_B2(o[2 * dp + 1], Ap, v4[2], v4[3]);
            }
        }
        __syncthreads();
    }

    float inv_lo = 1.0f / l_lo;
    float inv_hi = 1.0f / l_hi;
    const int row_lo = q0 + w * 16 + (lane >> 2);
    const int row_hi = row_lo + 8;
    const int cbase  = h * HEAD_DIM + (lane & 3) * 2;
#pragma unroll
    for (int nt = 0; nt < 16; nt++) {
        int d = cbase + nt * 8;
        *(__half2*)(O16 + (size_t)row_lo * INNER + d) =
            __floats2half2_rn(o[nt][0] * inv_lo, o[nt][1] * inv_lo);
        *(__half2*)(O16 + (size_t)row_hi * INNER + d) =
            __floats2half2_rn(o[nt][2] * inv_hi, o[nt][3] * inv_hi);
    }
}

// ---------------- launch ----------------
extern "C" void kernel_launch(void* const* d_in, const int* in_sizes, int n_in,
                              void* d_out, int out_size)
{
    (void)in_sizes; (void)n_in; (void)out_size;
    const float* hid   = (const float*)d_in[0];
    const float* enc   = (const float*)d_in[1];
    const float* ref   = (const float*)d_in[2];
    const float* rcos  = (const float*)d_in[3];
    const float* rsin  = (const float*)d_in[4];
    const float* ccos  = (const float*)d_in[5];
    const float* csin  = (const float*)d_in[6];
    const float* Wq    = (const float*)d_in[7];
    const float* bq    = (const float*)d_in[8];
    const float* Wk    = (const float*)d_in[9];
    const float* bk    = (const float*)d_in[10];
    const float* Wv    = (const float*)d_in[11];
    const float* bv    = (const float*)d_in[12];
    const float* Waq   = (const float*)d_in[13];
    const float* baq   = (const float*)d_in[14];
    const float* Wak   = (const float*)d_in[15];
    const float* bak   = (const float*)d_in[16];
    const float* Wav   = (const float*)d_in[17];
    const float* bav   = (const float*)d_in[18];
    const float* Wout  = (const float*)d_in[19];
    const float* bout  = (const float*)d_in[20];
    const float* Wadd  = (const float*)d_in[21];
    const float* badd  = (const float*)d_in[22];
    const float* nq_w  = (const float*)d_in[23];
    const float* nk_w  = (const float*)d_in[24];
    const float* naq_w = (const float*)d_in[25];
    const float* nak_w = (const float*)d_in[26];
    const float* lkd   = (const float*)d_in[27];
    const float* lku   = (const float*)d_in[28];
    const float* lvd   = (const float*)d_in[29];
    const float* lvu   = (const float*)d_in[30];

    float *q, *k;
    cudaGetSymbolAddress((void**)&q, g_q);
    cudaGetSymbolAddress((void**)&k, g_k);

    __half *Wh, *Uh, *x16, *t16, *o16, *q16, *k16, *v16;
    cudaGetSymbolAddress((void**)&Wh, g_W16h);
    cudaGetSymbolAddress((void**)&Uh, g_U16h);
    cudaGetSymbolAddress((void**)&x16, g_x16);
    cudaGetSymbolAddress((void**)&t16, g_t16);
    cudaGetSymbolAddress((void**)&o16, g_o16);
    cudaGetSymbolAddress((void**)&q16, g_q16);
    cudaGetSymbolAddress((void**)&k16, g_k16);
    cudaGetSymbolAddress((void**)&v16, g_v16);

    cudaFuncSetAttribute(gemm_fp16_kernel, cudaFuncAttributeMaxDynamicSharedMemorySize,
                         GEMM_SMEM_BYTES);
    cudaFuncSetAttribute(attn_fp16_kernel, cudaFuncAttributeMaxDynamicSharedMemorySize,
                         ATTN_SMEM_BYTES);

    auto cvt = [](const float* src, __half* dst, size_t n) {
        cvt16_kernel<<<(unsigned)(n >> 13), 256>>>(src, dst);
    };
    auto gF = [](const __half* A, const __half* B, const float* bi, float* C,
                 int M, int N, int K) {
        gemm_fp16_kernel<<<dim3(N / 128, M / 128), 256, GEMM_SMEM_BYTES>>>(
            A, B, bi, C, nullptr, M, N, K);
    };
    auto gH = [](const __half* A, const __half* B, const float* bi, __half* C16,
                 int M, int N, int K) {
        gemm_fp16_kernel<<<dim3(N / 128, M / 128), 256, GEMM_SMEM_BYTES>>>(
            A, B, bi, nullptr, C16, M, N, K);
    };

    const size_t WSZ = (size_t)INNER * INNER;
    const size_t USZ = (size_t)INNER * RANK;
    const size_t off_hid = 0;
    const size_t off_enc = (size_t)S_IMG * INNER;
    const size_t off_ref = (size_t)(S_IMG + S_TXT) * INNER;

    // L1-L5: deps for the big GEMM; L6 = big GEMM (profiled by ncu -s 5 -c 1)
    cvt(hid, x16 + off_hid, (size_t)S_IMG * INNER);                     // L1
    cvt(Wq, Wh + 1 * WSZ, WSZ);                                         // L2
    cvt(enc, x16 + off_enc, (size_t)S_TXT * INNER);                     // L3
    cvt(ref, x16 + off_ref, (size_t)S_REF * INNER);                     // L4
    cvt(Waq, Wh + 0 * WSZ, WSZ);                                        // L5
    gF(x16 + off_hid, Wh + 1 * WSZ, bq,                                 // L6
       q + (size_t)S_TXT * INNER, S_IMG, INNER, INNER);

    cvt(Wak,  Wh + 2 * WSZ, WSZ);
    cvt(Wk,   Wh + 3 * WSZ, WSZ);
    cvt(Wav,  Wh + 4 * WSZ, WSZ);
    cvt(Wv,   Wh + 5 * WSZ, WSZ);
    cvt(Wout, Wh + 6 * WSZ, WSZ);
    cvt(Wadd, Wh + 7 * WSZ, WSZ);
    cvt(lkd,  Uh + 0 * USZ, USZ);
    cvt(lvd,  Uh + 1 * USZ, USZ);
    cvt(lku,  Uh + 2 * USZ, USZ);
    cvt(lvu,  Uh + 3 * USZ, USZ);

    gF(x16 + off_enc, Wh + 0 * WSZ, baq, q,                         S_TXT, INNER, INNER);
    gF(x16 + off_enc, Wh + 2 * WSZ, bak, k,                         S_TXT, INNER, INNER);
    gF(x16 + off_hid, Wh + 3 * WSZ, bk,  k + (size_t)S_TXT * INNER, S_IMG, INNER, INNER);
    gH(x16 + off_enc, Wh + 4 * WSZ, bav, v16,                       S_TXT, INNER, INNER);
    gH(x16 + off_hid, Wh + 5 * WSZ, bv,  v16 + (size_t)S_TXT * INNER, S_IMG, INNER, INNER);

    // LoRA ref branch
    gH(x16 + off_ref, Uh + 0 * USZ, nullptr, t16, S_REF, RANK, INNER);
    gF(t16, Uh + 2 * USZ, nullptr, k + (size_t)SQ * INNER, S_REF, INNER, RANK);
    gH(x16 + off_ref, Uh + 1 * USZ, nullptr, t16, S_REF, RANK, INNER);
    gH(t16, Uh + 3 * USZ, nullptr, v16 + (size_t)SQ * INNER, S_REF, INNER, RANK);

    // RMSNorm + RoPE -> single fp16 q/k
    rmsnorm_rope_out_kernel<<<dim3(SQ, HEADS), 128>>>(
        q, q16, naq_w, nq_w, S_TXT, rcos, rsin, 1e-6f);
    rmsnorm_rope_out_kernel<<<dim3(SQ, HEADS), 128>>>(
        k, k16, nak_w, nk_w, S_TXT, rcos, rsin, 1e-6f);
    rmsnorm_rope_out_kernel<<<dim3(S_REF, HEADS), 128>>>(
        k + (size_t)SQ * INNER, k16 + (size_t)SQ * INNER,
        nullptr, nullptr, 0, ccos, csin, 1e-5f);

    attn_fp16_kernel<<<dim3(SQ / 128, HEADS), 256, ATTN_SMEM_BYTES>>>(
        q16, k16, v16, o16);

    float* outp = (float*)d_out;
    gF(o16 + (size_t)S_TXT * INNER, Wh + 6 * WSZ, bout, outp, S_IMG, INNER, INNER);
    gF(o16, Wh + 7 * WSZ, badd, outp + (size_t)S_IMG * INNER, S_TXT, INNER, INNER);
}

// round 13
// speedup vs baseline: 2.2860x; 1.1807x over previous
#include <cuda_runtime.h>
#include <cuda_fp16.h>
#include <cstdint>
#include <cstddef>

#define HEADS 24
#define HEAD_DIM 128
#define INNER 3072
#define RANK 1024
#define S_IMG 2048
#define S_TXT 512
#define S_REF 2048
#define SQ (S_TXT + S_IMG)          // 2560
#define SK (S_TXT + S_IMG + S_REF)  // 4608

// ---------------- scratch (device globals; no allocation) ----------------
__device__ __half g_Wqkv_enc[(size_t)INNER * (3 * INNER)];  // [K, 9216] Waq|Wak|Wav
__device__ __half g_Wqkv_hid[(size_t)INNER * (3 * INNER)];  // [K, 9216] Wq|Wk|Wv
__device__ __half g_Wout16[(size_t)INNER * INNER];
__device__ __half g_Wadd16[(size_t)INNER * INNER];
__device__ __half g_Ud[(size_t)INNER * (2 * RANK)];         // [K, 2048] lkd|lvd
__device__ __half g_Uku[(size_t)RANK * INNER];
__device__ __half g_Uvu[(size_t)RANK * INNER];
__device__ __half g_x16[(size_t)(S_IMG + S_TXT + S_REF) * INNER];
__device__ __half g_tk16[(size_t)S_REF * RANK];
__device__ __half g_tv16[(size_t)S_REF * RANK];
__device__ __half g_o16[(size_t)SQ * INNER];
__device__ __half g_qpre[(size_t)SQ * INNER];   // pre-norm q (fp16)
__device__ __half g_kpre[(size_t)SK * INNER];   // pre-norm k (fp16)
__device__ __half g_q16[(size_t)SQ * INNER];
__device__ __half g_k16[(size_t)SK * INNER];
__device__ __half g_v16[(size_t)SK * INNER];

// ---------------- fp32 -> fp16 convert (16 elems/thread) ----------------
__global__ void cvt16_kernel(const float* __restrict__ x, __half* __restrict__ y)
{
    size_t base = ((size_t)blockIdx.x * 256 + threadIdx.x) * 16;
#pragma unroll
    for (int u = 0; u < 4; u++) {
        float4 v = *(const float4*)(x + base + u * 4);
        __half2* yp = (__half2*)(y + base + u * 4);
        yp[0] = __floats2half2_rn(v.x, v.y);
        yp[1] = __floats2half2_rn(v.z, v.w);
    }
}

// ---- fp32 [K,srcN] -> fp16 column-segment of wide [K,dstN] at col off ----
__global__ void cvt16_seg_kernel(const float* __restrict__ x, __half* __restrict__ y,
                                 int srcN, int dstN, int off)
{
    size_t i = ((size_t)blockIdx.x * 256 + threadIdx.x) * 8;
    int k = (int)(i / (size_t)srcN);
    int n = (int)(i % (size_t)srcN);
    float4 v0 = *(const float4*)(x + i);
    float4 v1 = *(const float4*)(x + i + 4);
    __half2* yp = (__half2*)(y + (size_t)k * dstN + off + n);
    yp[0] = __floats2half2_rn(v0.x, v0.y);
    yp[1] = __floats2half2_rn(v0.z, v0.w);
    yp[2] = __floats2half2_rn(v1.x, v1.y);
    yp[3] = __floats2half2_rn(v1.z, v1.w);
}

// ---------------- ptx helpers ----------------
#define LDSM4(R, addr) \
    asm volatile("ldmatrix.sync.aligned.m8n8.x4.shared.b16 {%0,%1,%2,%3},[%4];" \
        : "=r"((R)[0]), "=r"((R)[1]), "=r"((R)[2]), "=r"((R)[3]) : "r"(addr))
#define LDSM4T(R, addr) \
    asm volatile("ldmatrix.sync.aligned.m8n8.x4.trans.shared.b16 {%0,%1,%2,%3},[%4];" \
        : "=r"((R)[0]), "=r"((R)[1]), "=r"((R)[2]), "=r"((R)[3]) : "r"(addr))
#define MMA_F16(C, A, B) \
    asm volatile("mma.sync.aligned.m16n8k16.row.col.f32.f16.f16.f32 " \
        "{%0,%1,%2,%3},{%4,%5,%6,%7},{%8,%9},{%0,%1,%2,%3};" \
        : "+f"((C)[0]), "+f"((C)[1]), "+f"((C)[2]), "+f"((C)[3]) \
        : "r"((A)[0]), "r"((A)[1]), "r"((A)[2]), "r"((A)[3]), "r"((B)[0]), "r"((B)[1]))
#define MMA_F16_B2(C, A, B0, B1) \
    asm volatile("mma.sync.aligned.m16n8k16.row.col.f32.f16.f16.f32 " \
        "{%0,%1,%2,%3},{%4,%5,%6,%7},{%8,%9},{%0,%1,%2,%3};" \
        : "+f"((C)[0]), "+f"((C)[1]), "+f"((C)[2]), "+f"((C)[3]) \
        : "r"((A)[0]), "r"((A)[1]), "r"((A)[2]), "r"((A)[3]), "r"(B0), "r"(B1))

__device__ __forceinline__ void cp16(const void* dst, const void* src) {
    unsigned d = (unsigned)__cvta_generic_to_shared(dst);
    asm volatile("cp.async.cg.shared.global [%0],[%1],16;" :: "r"(d), "l"(src));
}
#define CP_COMMIT() asm volatile("cp.async.commit_group;")
#define CP_WAIT0()  asm volatile("cp.async.wait_group 0;")
#define CP_WAIT1()  asm volatile("cp.async.wait_group 1;")

// ---------------- GEMM tiling constants ----------------
#define A_LD 40
#define B_LD 136
#define SA_ELEMS (128 * A_LD)
#define SB_ELEMS (32 * B_LD)
#define GSTAGE (SA_ELEMS + SB_ELEMS)
#define GEMM_SMEM_BYTES (GSTAGE * 3 * 2)

// ---------------- core mainloop (shared by both GEMMs) ----------------
// computes 128x128 tile accumulators into c[2][8][4]
#define GEMM_MAINLOOP(Aptr, Bptr, Nb) \
    load_stage(0, 0); CP_COMMIT(); \
    load_stage(1, 1); CP_COMMIT(); \
    for (int it = 0; it < iters; it++) { \
        if (it == iters - 1) { CP_WAIT0(); } else { CP_WAIT1(); } \
        __syncthreads(); \
        if (it + 2 < iters) { load_stage((it + 2) % 3, it + 2); CP_COMMIT(); } \
        const __half* st = dsm + (it % 3) * GSTAGE; \
        const unsigned sA_b = (unsigned)__cvta_generic_to_shared(st); \
        const unsigned sB_b = sA_b + SA_ELEMS * 2; \
        _Pragma("unroll") \
        for (int kh = 0; kh < 2; kh++) { \
            unsigned af[2][4]; \
            _Pragma("unroll") \
            for (int mi = 0; mi < 2; mi++) { \
                unsigned off = (unsigned)(((wm * 32 + mi * 16 + (lane & 15)) * A_LD \
                                           + kh * 16 + ((lane >> 4) << 3)) * 2); \
                LDSM4(af[mi], sA_b + off); \
            } \
            _Pragma("unroll") \
            for (int p = 0; p < 4; p++) { \
                unsigned bh[4]; \
                unsigned off = (unsigned)(((kh * 16 + (lane & 15)) * B_LD \
                                           + wn * 64 + p * 16 + ((lane >> 4) << 3)) * 2); \
                LDSM4T(bh, sB_b + off); \
                _Pragma("unroll") \
                for (int mi = 0; mi < 2; mi++) { \
                    MMA_F16(c[mi][2 * p],     af[mi], bh); \
                    MMA_F16(c[mi][2 * p + 1], af[mi], bh + 2); \
                } \
            } \
        } \
    }

// ---------------- fp16 GEMM, fp32 or fp16 output ----------------
__global__ __launch_bounds__(256, 1) void gemm_fp16_kernel(
    const __half* __restrict__ A, const __half* __restrict__ B,
    const float* __restrict__ bias,
    float* __restrict__ Cf, __half* __restrict__ C16,
    int M, int N, int K)
{
    extern __shared__ __half dsm[];
    const int tid  = threadIdx.x;
    const int lane = tid & 31;
    const int wid  = tid >> 5;
    const int wm   = wid & 3;
    const int wn   = wid >> 2;
    const int bm   = blockIdx.y * 128;
    const int bn   = blockIdx.x * 128;
    const int ar = tid >> 1, ac = (tid & 1) * 16;
    const int br = tid >> 4, bc = (tid & 15) * 8;

    float c[2][8][4];
#pragma unroll
    for (int mi = 0; mi < 2; mi++)
#pragma unroll
        for (int ni = 0; ni < 8; ni++)
#pragma unroll
            for (int r = 0; r < 4; r++) c[mi][ni][r] = 0.f;

    const int iters = K >> 5;
    auto load_stage = [&](int s, int it) {
        int k0 = it << 5;
        __half* st = dsm + s * GSTAGE;
        cp16(st + ar * A_LD + ac,     A + (size_t)(bm + ar) * K + k0 + ac);
        cp16(st + ar * A_LD + ac + 8, A + (size_t)(bm + ar) * K + k0 + ac + 8);
        __half* pB = st + SA_ELEMS;
        cp16(pB + br * B_LD + bc,        B + (size_t)(k0 + br) * N + bn + bc);
        cp16(pB + (br + 16) * B_LD + bc, B + (size_t)(k0 + br + 16) * N + bn + bc);
    };

    GEMM_MAINLOOP(A, B, N)

    const int row0 = bm + wm * 32 + (lane >> 2);
    const int col0 = bn + wn * 64 + (lane & 3) * 2;
#pragma unroll
    for (int mi = 0; mi < 2; mi++) {
#pragma unroll
        for (int ni = 0; ni < 8; ni++) {
            int r  = row0 + mi * 16;
            int cc = col0 + ni * 8;
            float b0 = bias ? bias[cc] : 0.f;
            float b1 = bias ? bias[cc + 1] : 0.f;
            float v0 = c[mi][ni][0] + b0, v1 = c[mi][ni][1] + b1;
            float v2 = c[mi][ni][2] + b0, v3 = c[mi][ni][3] + b1;
            if (Cf) {
                *(float2*)(Cf + (size_t)r * N + cc)       = float2{v0, v1};
                *(float2*)(Cf + (size_t)(r + 8) * N + cc) = float2{v2, v3};
            } else {
                *(__half2*)(C16 + (size_t)r * N + cc)       = __floats2half2_rn(v0, v1);
                *(__half2*)(C16 + (size_t)(r + 8) * N + cc) = __floats2half2_rn(v2, v3);
            }
        }
    }
}

// ---------------- fused segmented GEMM: B wide [K,N], up to 3 fp16 outputs
// seg = bn / SEGW; output col = bn - seg*SEGW; output row stride = SEGW.
__global__ __launch_bounds__(256, 1) void gemm_fused_kernel(
    const __half* __restrict__ A, const __half* __restrict__ B,
    const float* __restrict__ b0, const float* __restrict__ b1,
    const float* __restrict__ b2,
    __half* __restrict__ C0, __half* __restrict__ C1, __half* __restrict__ C2,
    int M, int N, int K, int SEGW)
{
    extern __shared__ __half dsm[];
    const int tid  = threadIdx.x;
    const int lane = tid & 31;
    const int wid  = tid >> 5;
    const int wm   = wid & 3;
    const int wn   = wid >> 2;
    const int bm   = blockIdx.y * 128;
    const int bn   = blockIdx.x * 128;
    const int ar = tid >> 1, ac = (tid & 1) * 16;
    const int br = tid >> 4, bc = (tid & 15) * 8;

    float c[2][8][4];
#pragma unroll
    for (int mi = 0; mi < 2; mi++)
#pragma unroll
        for (int ni = 0; ni < 8; ni++)
#pragma unroll
            for (int r = 0; r < 4; r++) c[mi][ni][r] = 0.f;

    const int iters = K >> 5;
    auto load_stage = [&](int s, int it) {
        int k0 = it << 5;
        __half* st = dsm + s * GSTAGE;
        cp16(st + ar * A_LD + ac,     A + (size_t)(bm + ar) * K + k0 + ac);
        cp16(st + ar * A_LD + ac + 8, A + (size_t)(bm + ar) * K + k0 + ac + 8);
        __half* pB = st + SA_ELEMS;
        cp16(pB + br * B_LD + bc,        B + (size_t)(k0 + br) * N + bn + bc);
        cp16(pB + (br + 16) * B_LD + bc, B + (size_t)(k0 + br + 16) * N + bn + bc);
    };

    GEMM_MAINLOOP(A, B, N)

    const int seg = bn / SEGW;
    __half* dst = (seg == 0) ? C0 : (seg == 1) ? C1 : C2;
    const float* bias = (seg == 0) ? b0 : (seg == 1) ? b1 : b2;
    const int row0 = bm + wm * 32 + (lane >> 2);
    const int col0 = (bn - seg * SEGW) + wn * 64 + (lane & 3) * 2;
#pragma unroll
    for (int mi = 0; mi < 2; mi++) {
#pragma unroll
        for (int ni = 0; ni < 8; ni++) {
            int r  = row0 + mi * 16;
            int cc = col0 + ni * 8;
            float b0v = bias ? bias[cc] : 0.f;
            float b1v = bias ? bias[cc + 1] : 0.f;
            float v0 = c[mi][ni][0] + b0v, v1 = c[mi][ni][1] + b1v;
            float v2 = c[mi][ni][2] + b0v, v3 = c[mi][ni][3] + b1v;
            *(__half2*)(dst + (size_t)r * SEGW + cc)       = __floats2half2_rn(v0, v1);
            *(__half2*)(dst + (size_t)(r + 8) * SEGW + cc) = __floats2half2_rn(v2, v3);
        }
    }
}

// ------ fused RMSNorm + RoPE (fp16 in) -> single fp16 --------
__global__ void rmsnorm_rope_out_kernel(
    const __half* __restrict__ src,
    __half* __restrict__ out16,
    const float* __restrict__ w0, const float* __restrict__ w1, int split,
    const float* __restrict__ cos_t, const float* __restrict__ sin_t,
    float eps)
{
    const int row = blockIdx.x;
    const int h   = blockIdx.y;
    const int d   = threadIdx.x;

    float v = __half2float(src[(size_t)row * INNER + h * HEAD_DIM + d]);
    float ss = v * v;
#pragma unroll
    for (int o = 16; o; o >>= 1) ss += __shfl_xor_sync(0xffffffffu, ss, o);
    __shared__ float red[4];
    if ((d & 31) == 0) red[d >> 5] = ss;
    __syncthreads();
    float tot = red[0] + red[1] + red[2] + red[3];
    float r = rsqrtf(tot * (1.0f / HEAD_DIM) + eps);

    const float* w = (row < split) ? w0 : w1;
    float y = v * r;
    if (w) y *= w[d];

    float other = __shfl_xor_sync(0xffffffffu, y, 1);
    float c = cos_t[(size_t)row * HEAD_DIM + d];
    float s = sin_t[(size_t)row * HEAD_DIM + d];
    float rot = (d & 1) ? other : -other;
    float out = y * c + rot * s;

    out16[(size_t)row * INNER + h * HEAD_DIM + d] = __float2half_rn(out);
}

// ---------------- tensor-core flash attention (fp16, cp.async KV) --------
#define LDQ 136
#define Q_ELEMS (128 * LDQ)
#define KV_ELEMS (64 * LDQ)
#define KVSTAGE_ELEMS (2 * KV_ELEMS)
#define ATTN_SMEM_BYTES ((Q_ELEMS + 2 * KVSTAGE_ELEMS) * 2)

__global__ __launch_bounds__(256, 2) void attn_fp16_kernel(
    const __half* __restrict__ Q16,
    const __half* __restrict__ K16,
    const __half* __restrict__ V16,
    __half* __restrict__ O16)
{
    extern __shared__ __half smh[];
    __half* sQ = smh;
    __half* kvBase = sQ + Q_ELEMS;

    const int h    = blockIdx.y;
    const int q0   = blockIdx.x * 128;
    const int tid  = threadIdx.x;
    const int lane = tid & 31;
    const int w    = tid >> 5;
    const float scale = 0.08838834764831845f;

    const unsigned sQ_b = (unsigned)__cvta_generic_to_shared(sQ);

    const int krow = tid >> 2;
    const int kcol = (tid & 3) * 32;

    auto load_kv = [&](int s, int kt) {
        __half* st = kvBase + s * KVSTAGE_ELEMS;
        __half* pK = st;
        __half* pV = st + KV_ELEMS;
#pragma unroll
        for (int seg = 0; seg < 4; seg++) {
            int cc = kcol + seg * 8;
            size_t g = (size_t)(kt * 64 + krow) * INNER + h * HEAD_DIM + cc;
            cp16(pK + krow * LDQ + cc, K16 + g);
            cp16(pV + krow * LDQ + cc, V16 + g);
        }
    };

    load_kv(0, 0); CP_COMMIT();

    for (int i = tid; i < 128 * 16; i += 256) {
        int row = i >> 4;
        int c8  = (i & 15) * 8;
        size_t g = (size_t)(q0 + row) * INNER + h * HEAD_DIM + c8;
        *(uint4*)(sQ + row * LDQ + c8) = *(const uint4*)(Q16 + g);
    }

    float o[16][4];
#pragma unroll
    for (int nt = 0; nt < 16; nt++)
#pragma unroll
        for (int r = 0; r < 4; r++) o[nt][r] = 0.f;
    float m_lo = -1e30f, m_hi = -1e30f, l_lo = 0.f, l_hi = 0.f;

    const int NT = SK / 64;
    for (int kt = 0; kt < NT; kt++) {
        CP_WAIT0();
        __syncthreads();
        if (kt + 1 < NT) { load_kv((kt + 1) & 1, kt + 1); CP_COMMIT(); }

        const __half* st = kvBase + (kt & 1) * KVSTAGE_ELEMS;
        const unsigned sK_b = (unsigned)__cvta_generic_to_shared(st);
        const unsigned sV_b = sK_b + KV_ELEMS * 2;

        float c[8][4];
#pragma unroll
        for (int n = 0; n < 8; n++)
#pragma unroll
            for (int r = 0; r < 4; r++) c[n][r] = 0.f;

#pragma unroll
        for (int kk = 0; kk < 8; kk++) {
            unsigned aq[4];
            unsigned qoff = (unsigned)(((w * 16 + (lane & 15)) * LDQ
                                        + kk * 16 + ((lane >> 4) << 3)) * 2);
            LDSM4(aq, sQ_b + qoff);
#pragma unroll
            for (int ng = 0; ng < 4; ng++) {
                unsigned bh[4];
                unsigned koff = (unsigned)(((ng * 16 + (lane & 15)) * LDQ
                                            + kk * 16 + ((lane >> 4) << 3)) * 2);
                LDSM4(bh, sK_b + koff);
                MMA_F16_B2(c[2 * ng],     aq, bh[0], bh[2]);
                MMA_F16_B2(c[2 * ng + 1], aq, bh[1], bh[3]);
            }
        }

        float tmx_lo = -1e30f, tmx_hi = -1e30f;
#pragma unroll
        for (int n = 0; n < 8; n++) {
            c[n][0] *= scale; c[n][1] *= scale; c[n][2] *= scale; c[n][3] *= scale;
            tmx_lo = fmaxf(tmx_lo, fmaxf(c[n][0], c[n][1]));
            tmx_hi = fmaxf(tmx_hi, fmaxf(c[n][2], c[n][3]));
        }
        tmx_lo = fmaxf(tmx_lo, __shfl_xor_sync(0xffffffffu, tmx_lo, 1));
        tmx_lo = fmaxf(tmx_lo, __shfl_xor_sync(0xffffffffu, tmx_lo, 2));
        tmx_hi = fmaxf(tmx_hi, __shfl_xor_sync(0xffffffffu, tmx_hi, 1));
        tmx_hi = fmaxf(tmx_hi, __shfl_xor_sync(0xffffffffu, tmx_hi, 2));

        float mn_lo = fmaxf(m_lo, tmx_lo);
        float mn_hi = fmaxf(m_hi, tmx_hi);
        float al_lo = __expf(m_lo - mn_lo);
        float al_hi = __expf(m_hi - mn_hi);
        m_lo = mn_lo; m_hi = mn_hi;

        unsigned ph[8][2];
        float sum_lo = 0.f, sum_hi = 0.f;
#pragma unroll
        for (int n = 0; n < 8; n++) {
            float p0 = __expf(c[n][0] - m_lo);
            float p1 = __expf(c[n][1] - m_lo);
            float p2 = __expf(c[n][2] - m_hi);
            float p3 = __expf(c[n][3] - m_hi);
            sum_lo += p0 + p1;
            sum_hi += p2 + p3;
            __half2 h01 = __floats2half2_rn(p0, p1);
            __half2 h23 = __floats2half2_rn(p2, p3);
            ph[n][0] = *(unsigned*)&h01; ph[n][1] = *(unsigned*)&h23;
        }
        sum_lo += __shfl_xor_sync(0xffffffffu, sum_lo, 1);
        sum_lo += __shfl_xor_sync(0xffffffffu, sum_lo, 2);
        sum_hi += __shfl_xor_sync(0xffffffffu, sum_hi, 1);
        sum_hi += __shfl_xor_sync(0xffffffffu, sum_hi, 2);
        l_lo = l_lo * al_lo + sum_lo;
        l_hi = l_hi * al_hi + sum_hi;

#pragma unroll
        for (int nt = 0; nt < 16; nt++) {
            o[nt][0] *= al_lo; o[nt][1] *= al_lo;
            o[nt][2] *= al_hi; o[nt][3] *= al_hi;
        }

#pragma unroll
        for (int j = 0; j < 4; j++) {
            unsigned Ap[4] = {ph[2 * j][0], ph[2 * j][1], ph[2 * j + 1][0], ph[2 * j + 1][1]};
#pragma unroll
            for (int dp = 0; dp < 8; dp++) {
                unsigned v4[4];
                unsigned voff = (unsigned)(((j * 16 + (lane & 15)) * LDQ
                                            + dp * 16 + ((lane >> 4) << 3)) * 2);
                LDSM4T(v4, sV_b + voff);
                MMA_F16_B2(o[2 * dp],     Ap, v4[0], v4[1]);
                MMA_F16_B2(o[2 * dp + 1], Ap, v4[2], v4[3]);
            }
        }
        __syncthreads();
    }

    float inv_lo = 1.0f / l_lo;
    float inv_hi = 1.0f / l_hi;
    const int row_lo = q0 + w * 16 + (lane >> 2);
    const int row_hi = row_lo + 8;
    const int cbase  = h * HEAD_DIM + (lane & 3) * 2;
#pragma unroll
    for (int nt = 0; nt < 16; nt++) {
        int d = cbase + nt * 8;
        *(__half2*)(O16 + (size_t)row_lo * INNER + d) =
            __floats2half2_rn(o[nt][0] * inv_lo, o[nt][1] * inv_lo);
        *(__half2*)(O16 + (size_t)row_hi * INNER + d) =
            __floats2half2_rn(o[nt][2] * inv_hi, o[nt][3] * inv_hi);
    }
}

// ---------------- launch ----------------
extern "C" void kernel_launch(void* const* d_in, const int* in_sizes, int n_in,
                              void* d_out, int out_size)
{
    (void)in_sizes; (void)n_in; (void)out_size;
    const float* hid   = (const float*)d_in[0];
    const float* enc   = (const float*)d_in[1];
    const float* ref   = (const float*)d_in[2];
    const float* rcos  = (const float*)d_in[3];
    const float* rsin  = (const float*)d_in[4];
    const float* ccos  = (const float*)d_in[5];
    const float* csin  = (const float*)d_in[6];
    const float* Wq    = (const float*)d_in[7];
    const float* bq    = (const float*)d_in[8];
    const float* Wk    = (const float*)d_in[9];
    const float* bk    = (const float*)d_in[10];
    const float* Wv    = (const float*)d_in[11];
    const float* bv    = (const float*)d_in[12];
    const float* Waq   = (const float*)d_in[13];
    const float* baq   = (const float*)d_in[14];
    const float* Wak   = (const float*)d_in[15];
    const float* bak   = (const float*)d_in[16];
    const float* Wav   = (const float*)d_in[17];
    const float* bav   = (const float*)d_in[18];
    const float* Wout  = (const float*)d_in[19];
    const float* bout  = (const float*)d_in[20];
    const float* Wadd  = (const float*)d_in[21];
    const float* badd  = (const float*)d_in[22];
    const float* nq_w  = (const float*)d_in[23];
    const float* nk_w  = (const float*)d_in[24];
    const float* naq_w = (const float*)d_in[25];
    const float* nak_w = (const float*)d_in[26];
    const float* lkd   = (const float*)d_in[27];
    const float* lku   = (const float*)d_in[28];
    const float* lvd   = (const float*)d_in[29];
    const float* lvu   = (const float*)d_in[30];

    __half *Wenc, *Whid, *Wo16, *Wa16, *Ud, *Uku, *Uvu;
    __half *x16, *tk16, *tv16, *o16, *qpre, *kpre, *q16, *k16, *v16;
    cudaGetSymbolAddress((void**)&Wenc, g_Wqkv_enc);
    cudaGetSymbolAddress((void**)&Whid, g_Wqkv_hid);
    cudaGetSymbolAddress((void**)&Wo16, g_Wout16);
    cudaGetSymbolAddress((void**)&Wa16, g_Wadd16);
    cudaGetSymbolAddress((void**)&Ud,  g_Ud);
    cudaGetSymbolAddress((void**)&Uku, g_Uku);
    cudaGetSymbolAddress((void**)&Uvu, g_Uvu);
    cudaGetSymbolAddress((void**)&x16, g_x16);
    cudaGetSymbolAddress((void**)&tk16, g_tk16);
    cudaGetSymbolAddress((void**)&tv16, g_tv16);
    cudaGetSymbolAddress((void**)&o16, g_o16);
    cudaGetSymbolAddress((void**)&qpre, g_qpre);
    cudaGetSymbolAddress((void**)&kpre, g_kpre);
    cudaGetSymbolAddress((void**)&q16, g_q16);
    cudaGetSymbolAddress((void**)&k16, g_k16);
    cudaGetSymbolAddress((void**)&v16, g_v16);

    cudaFuncSetAttribute(gemm_fp16_kernel, cudaFuncAttributeMaxDynamicSharedMemorySize,
                         GEMM_SMEM_BYTES);
    cudaFuncSetAttribute(gemm_fused_kernel, cudaFuncAttributeMaxDynamicSharedMemorySize,
                         GEMM_SMEM_BYTES);
    cudaFuncSetAttribute(attn_fp16_kernel, cudaFuncAttributeMaxDynamicSharedMemorySize,
                         ATTN_SMEM_BYTES);

    auto cvt = [](const float* src, __half* dst, size_t n) {
        cvt16_kernel<<<(unsigned)(n >> 12), 256>>>(src, dst);
    };
    auto cvtSeg = [](const float* src, __half* dst, int srcN, int dstN, int off, size_t n) {
        cvt16_seg_kernel<<<(unsigned)(n >> 11), 256>>>(src, dst, srcN, dstN, off);
    };
    auto gF = [](const __half* A, const __half* B, const float* bi, float* C,
                 int M, int N, int K) {
        gemm_fp16_kernel<<<dim3(N / 128, M / 128), 256, GEMM_SMEM_BYTES>>>(
            A, B, bi, C, nullptr, M, N, K);
    };
    auto gH = [](const __half* A, const __half* B, const float* bi, __half* C16,
                 int M, int N, int K) {
        gemm_fp16_kernel<<<dim3(N / 128, M / 128), 256, GEMM_SMEM_BYTES>>>(
            A, B, bi, nullptr, C16, M, N, K);
    };
    auto gFused = [](const __half* A, const __half* B,
                     const float* b0, const float* b1, const float* b2,
                     __half* C0, __half* C1, __half* C2,
                     int M, int N, int K, int SEGW) {
        gemm_fused_kernel<<<dim3(N / 128, M / 128), 256, GEMM_SMEM_BYTES>>>(
            A, B, b0, b1, b2, C0, C1, C2, M, N, K, SEGW);
    };

    const size_t WSZ = (size_t)INNER * INNER;
    const size_t USZ = (size_t)INNER * RANK;
    const size_t off_hid = 0;
    const size_t off_enc = (size_t)S_IMG * INNER;
    const size_t off_ref = (size_t)(S_IMG + S_TXT) * INNER;

    // L1-L5: deps for the big fused GEMM; L6 = fused hid QKV (profiled)
    cvt(hid, x16 + off_hid, (size_t)S_IMG * INNER);                     // L1
    cvtSeg(Wq, Whid, INNER, 3 * INNER, 0 * INNER, WSZ);                 // L2
    cvtSeg(Wk, Whid, INNER, 3 * INNER, 1 * INNER, WSZ);                 // L3
    cvtSeg(Wv, Whid, INNER, 3 * INNER, 2 * INNER, WSZ);                 // L4
    cvt(enc, x16 + off_enc, (size_t)S_TXT * INNER);                     // L5
    gFused(x16 + off_hid, Whid, bq, bk, bv,                             // L6
           qpre + (size_t)S_TXT * INNER, kpre + (size_t)S_TXT * INNER,
           v16 + (size_t)S_TXT * INNER,
           S_IMG, 3 * INNER, INNER, INNER);

    cvt(ref, x16 + off_ref, (size_t)S_REF * INNER);
    cvtSeg(Waq, Wenc, INNER, 3 * INNER, 0 * INNER, WSZ);
    cvtSeg(Wak, Wenc, INNER, 3 * INNER, 1 * INNER, WSZ);
    cvtSeg(Wav, Wenc, INNER, 3 * INNER, 2 * INNER, WSZ);
    cvtSeg(lkd, Ud, RANK, 2 * RANK, 0 * RANK, USZ);
    cvtSeg(lvd, Ud, RANK, 2 * RANK, 1 * RANK, USZ);
    cvt(lku, Uku, USZ);
    cvt(lvu, Uvu, USZ);
    cvt(Wout, Wo16, WSZ);
    cvt(Wadd, Wa16, WSZ);

    // enc QKV fused
    gFused(x16 + off_enc, Wenc, baq, bak, bav,
           qpre, kpre, v16, S_TXT, 3 * INNER, INNER, INNER);

    // LoRA down fused (lkd | lvd), outputs tk16, tv16
    gFused(x16 + off_ref, Ud, nullptr, nullptr, nullptr,
           tk16, tv16, nullptr, S_REF, 2 * RANK, INNER, RANK);
    // LoRA up
    gH(tk16, Uku, nullptr, kpre + (size_t)SQ * INNER, S_REF, INNER, RANK);
    gH(tv16, Uvu, nullptr, v16 + (size_t)SQ * INNER, S_REF, INNER, RANK);

    // RMSNorm + RoPE (fp16 in) -> fp16 q/k
    rmsnorm_rope_out_kernel<<<dim3(SQ, HEADS), 128>>>(
        qpre, q16, naq_w, nq_w, S_TXT, rcos, rsin, 1e-6f);
    rmsnorm_rope_out_kernel<<<dim3(SQ, HEADS), 128>>>(
        kpre, k16, nak_w, nk_w, S_TXT, rcos, rsin, 1e-6f);
    rmsnorm_rope_out_kernel<<<dim3(S_REF, HEADS), 128>>>(
        kpre + (size_t)SQ * INNER, k16 + (size_t)SQ * INNER,
        nullptr, nullptr, 0, ccos, csin, 1e-5f);

    attn_fp16_kernel<<<dim3(SQ / 128, HEADS), 256, ATTN_SMEM_BYTES>>>(
        q16, k16, v16, o16);

    float* outp = (float*)d_out;
    gF(o16 + (size_t)S_TXT * INNER, Wo16, bout, outp, S_IMG, INNER, INNER);
    gF(o16, Wa16, badd, outp + (size_t)S_IMG * INNER, S_TXT, INNER, INNER);
}

// round 14
// speedup vs baseline: 2.3768x; 1.0397x over previous
#include <cuda_runtime.h>
#include <cuda_fp16.h>
#include <cstdint>
#include <cstddef>

#define HEADS 24
#define HEAD_DIM 128
#define INNER 3072
#define RANK 1024
#define S_IMG 2048
#define S_TXT 512
#define S_REF 2048
#define SQ (S_TXT + S_IMG)          // 2560
#define SK (S_TXT + S_IMG + S_REF)  // 4608

// ---------------- scratch (device globals; no allocation) ----------------
__device__ __half g_Wqkv_enc[(size_t)INNER * (3 * INNER)];
__device__ __half g_Wqkv_hid[(size_t)INNER * (3 * INNER)];
__device__ __half g_Wout16[(size_t)INNER * INNER];
__device__ __half g_Wadd16[(size_t)INNER * INNER];
__device__ __half g_Ud[(size_t)INNER * (2 * RANK)];
__device__ __half g_Uku[(size_t)RANK * INNER];
__device__ __half g_Uvu[(size_t)RANK * INNER];
__device__ __half g_x16[(size_t)(S_IMG + S_TXT + S_REF) * INNER];
__device__ __half g_tk16[(size_t)S_REF * RANK];
__device__ __half g_tv16[(size_t)S_REF * RANK];
__device__ __half g_o16[(size_t)SQ * INNER];
__device__ __half g_qpre[(size_t)SQ * INNER];
__device__ __half g_kpre[(size_t)SK * INNER];
__device__ __half g_q16[(size_t)SQ * INNER];
__device__ __half g_k16[(size_t)SK * INNER];
__device__ __half g_v16[(size_t)SK * INNER];

// ---------------- multi-descriptor fp32->fp16 convert ----------------
// plain cvt = seg with dstN == srcN, off == 0.
struct CvtDesc { const float* src; __half* dst; int srcN, dstN, off, bstart; };
struct CvtArgs { CvtDesc d[15]; int nd; };

__global__ __launch_bounds__(256) void cvt_multi_kernel(CvtArgs args)
{
    int bid = blockIdx.x;
    int p = 0;
#pragma unroll
    for (int i = 1; i < 15; i++)
        if (i < args.nd && args.d[i].bstart <= bid) p = i;
    const CvtDesc& d = args.d[p];

    size_t i = ((size_t)(bid - d.bstart) * 256 + threadIdx.x) * 8;
    int k = (int)(i / (size_t)d.srcN);
    int n = (int)(i % (size_t)d.srcN);
    float4 v0 = *(const float4*)(d.src + i);
    float4 v1 = *(const float4*)(d.src + i + 4);
    __half2* yp = (__half2*)(d.dst + (size_t)k * d.dstN + d.off + n);
    yp[0] = __floats2half2_rn(v0.x, v0.y);
    yp[1] = __floats2half2_rn(v0.z, v0.w);
    yp[2] = __floats2half2_rn(v1.x, v1.y);
    yp[3] = __floats2half2_rn(v1.z, v1.w);
}

// ---------------- ptx helpers ----------------
#define LDSM4(R, addr) \
    asm volatile("ldmatrix.sync.aligned.m8n8.x4.shared.b16 {%0,%1,%2,%3},[%4];" \
        : "=r"((R)[0]), "=r"((R)[1]), "=r"((R)[2]), "=r"((R)[3]) : "r"(addr))
#define LDSM4T(R, addr) \
    asm volatile("ldmatrix.sync.aligned.m8n8.x4.trans.shared.b16 {%0,%1,%2,%3},[%4];" \
        : "=r"((R)[0]), "=r"((R)[1]), "=r"((R)[2]), "=r"((R)[3]) : "r"(addr))
#define MMA_F16(C, A, B) \
    asm volatile("mma.sync.aligned.m16n8k16.row.col.f32.f16.f16.f32 " \
        "{%0,%1,%2,%3},{%4,%5,%6,%7},{%8,%9},{%0,%1,%2,%3};" \
        : "+f"((C)[0]), "+f"((C)[1]), "+f"((C)[2]), "+f"((C)[3]) \
        : "r"((A)[0]), "r"((A)[1]), "r"((A)[2]), "r"((A)[3]), "r"((B)[0]), "r"((B)[1]))
#define MMA_F16_B2(C, A, B0, B1) \
    asm volatile("mma.sync.aligned.m16n8k16.row.col.f32.f16.f16.f32 " \
        "{%0,%1,%2,%3},{%4,%5,%6,%7},{%8,%9},{%0,%1,%2,%3};" \
        : "+f"((C)[0]), "+f"((C)[1]), "+f"((C)[2]), "+f"((C)[3]) \
        : "r"((A)[0]), "r"((A)[1]), "r"((A)[2]), "r"((A)[3]), "r"(B0), "r"(B1))

__device__ __forceinline__ void cp16(const void* dst, const void* src) {
    unsigned d = (unsigned)__cvta_generic_to_shared(dst);
    asm volatile("cp.async.cg.shared.global [%0],[%1],16;" :: "r"(d), "l"(src));
}
#define CP_COMMIT() asm volatile("cp.async.commit_group;")
#define CP_WAIT0()  asm volatile("cp.async.wait_group 0;")
#define CP_WAIT1()  asm volatile("cp.async.wait_group 1;")

// ---------------- batched fp16 GEMM (up to 3 sub-problems) ----------------
#define A_LD 40
#define B_LD 136
#define SA_ELEMS (128 * A_LD)
#define SB_ELEMS (32 * B_LD)
#define GSTAGE (SA_ELEMS + SB_ELEMS)
#define GEMM_SMEM_BYTES (GSTAGE * 3 * 2)

struct GDesc {
    const __half *A, *B;
    const float *b0, *b1, *b2;
    __half *C0, *C1, *C2;
    float *Cf;
    int M, N, K, SEGW, bstart;
};
struct GArgs { GDesc g[3]; int ng; };

__global__ __launch_bounds__(256, 1) void gemm_multi_kernel(GArgs args)
{
    extern __shared__ __half dsm[];
    int bid = blockIdx.x;
    int p = 0;
    if (args.ng > 1 && args.g[1].bstart <= bid) p = 1;
    if (args.ng > 2 && args.g[2].bstart <= bid) p = 2;
    const GDesc& d = args.g[p];

    const int nbx  = d.N >> 7;
    const int loc  = bid - d.bstart;
    const int bn   = (loc % nbx) * 128;
    const int bm   = (loc / nbx) * 128;
    const int N    = d.N;
    const int K    = d.K;

    const int tid  = threadIdx.x;
    const int lane = tid & 31;
    const int wid  = tid >> 5;
    const int wm   = wid & 3;
    const int wn   = wid >> 2;
    const int ar = tid >> 1, ac = (tid & 1) * 16;
    const int br = tid >> 4, bc = (tid & 15) * 8;

    float c[2][8][4];
#pragma unroll
    for (int mi = 0; mi < 2; mi++)
#pragma unroll
        for (int ni = 0; ni < 8; ni++)
#pragma unroll
            for (int r = 0; r < 4; r++) c[mi][ni][r] = 0.f;

    const int iters = K >> 5;
    const __half* A = d.A;
    const __half* B = d.B;

    auto load_stage = [&](int s, int it) {
        int k0 = it << 5;
        __half* st = dsm + s * GSTAGE;
        cp16(st + ar * A_LD + ac,     A + (size_t)(bm + ar) * K + k0 + ac);
        cp16(st + ar * A_LD + ac + 8, A + (size_t)(bm + ar) * K + k0 + ac + 8);
        __half* pB = st + SA_ELEMS;
        cp16(pB + br * B_LD + bc,        B + (size_t)(k0 + br) * N + bn + bc);
        cp16(pB + (br + 16) * B_LD + bc, B + (size_t)(k0 + br + 16) * N + bn + bc);
    };

    load_stage(0, 0); CP_COMMIT();
    load_stage(1, 1); CP_COMMIT();

    for (int it = 0; it < iters; it++) {
        if (it == iters - 1) { CP_WAIT0(); } else { CP_WAIT1(); }
        __syncthreads();
        if (it + 2 < iters) { load_stage((it + 2) % 3, it + 2); CP_COMMIT(); }

        const __half* st = dsm + (it % 3) * GSTAGE;
        const unsigned sA_b = (unsigned)__cvta_generic_to_shared(st);
        const unsigned sB_b = sA_b + SA_ELEMS * 2;

#pragma unroll
        for (int kh = 0; kh < 2; kh++) {
            unsigned af[2][4];
#pragma unroll
            for (int mi = 0; mi < 2; mi++) {
                unsigned off = (unsigned)(((wm * 32 + mi * 16 + (lane & 15)) * A_LD
                                           + kh * 16 + ((lane >> 4) << 3)) * 2);
                LDSM4(af[mi], sA_b + off);
            }
#pragma unroll
            for (int pp = 0; pp < 4; pp++) {
                unsigned bh[4];
                unsigned off = (unsigned)(((kh * 16 + (lane & 15)) * B_LD
                                           + wn * 64 + pp * 16 + ((lane >> 4) << 3)) * 2);
                LDSM4T(bh, sB_b + off);
#pragma unroll
                for (int mi = 0; mi < 2; mi++) {
                    MMA_F16(c[mi][2 * pp],     af[mi], bh);
                    MMA_F16(c[mi][2 * pp + 1], af[mi], bh + 2);
                }
            }
        }
    }

    const int row0 = bm + wm * 32 + (lane >> 2);
    if (d.Cf) {
        const int col0 = bn + wn * 64 + (lane & 3) * 2;
#pragma unroll
        for (int mi = 0; mi < 2; mi++) {
#pragma unroll
            for (int ni = 0; ni < 8; ni++) {
                int r  = row0 + mi * 16;
                int cc = col0 + ni * 8;
                float b0v = d.b0 ? d.b0[cc] : 0.f;
                float b1v = d.b0 ? d.b0[cc + 1] : 0.f;
                *(float2*)(d.Cf + (size_t)r * N + cc) =
                    float2{c[mi][ni][0] + b0v, c[mi][ni][1] + b1v};
                *(float2*)(d.Cf + (size_t)(r + 8) * N + cc) =
                    float2{c[mi][ni][2] + b0v, c[mi][ni][3] + b1v};
            }
        }
    } else {
        const int seg = bn / d.SEGW;
        __half* dst = (seg == 0) ? d.C0 : (seg == 1) ? d.C1 : d.C2;
        const float* bias = (seg == 0) ? d.b0 : (seg == 1) ? d.b1 : d.b2;
        const int col0 = (bn - seg * d.SEGW) + wn * 64 + (lane & 3) * 2;
#pragma unroll
        for (int mi = 0; mi < 2; mi++) {
#pragma unroll
            for (int ni = 0; ni < 8; ni++) {
                int r  = row0 + mi * 16;
                int cc = col0 + ni * 8;
                float b0v = bias ? bias[cc] : 0.f;
                float b1v = bias ? bias[cc + 1] : 0.f;
                *(__half2*)(dst + (size_t)r * d.SEGW + cc) =
                    __floats2half2_rn(c[mi][ni][0] + b0v, c[mi][ni][1] + b1v);
                *(__half2*)(dst + (size_t)(r + 8) * d.SEGW + cc) =
                    __floats2half2_rn(c[mi][ni][2] + b0v, c[mi][ni][3] + b1v);
            }
        }
    }
}

// ------ fused RMSNorm + RoPE, all three row-ranges in one launch ------
__global__ void rmsnorm_rope_all_kernel(
    const __half* __restrict__ qpre, const __half* __restrict__ kpre,
    __half* __restrict__ q16, __half* __restrict__ k16,
    const float* __restrict__ naq_w, const float* __restrict__ nq_w,
    const float* __restrict__ nak_w, const float* __restrict__ nk_w,
    const float* __restrict__ rcos, const float* __restrict__ rsin,
    const float* __restrict__ ccos, const float* __restrict__ csin)
{
    const int rr = blockIdx.x;
    const int h  = blockIdx.y;
    const int d  = threadIdx.x;

    const __half* src; __half* dst;
    const float *w, *cos_t, *sin_t;
    float eps;
    int row;
    if (rr < SQ) {
        row = rr; src = qpre; dst = q16;
        w = (row < S_TXT) ? naq_w : nq_w;
        cos_t = rcos; sin_t = rsin; eps = 1e-6f;
    } else if (rr < 2 * SQ) {
        row = rr - SQ; src = kpre; dst = k16;
        w = (row < S_TXT) ? nak_w : nk_w;
        cos_t = rcos; sin_t = rsin; eps = 1e-6f;
    } else {
        row = rr - 2 * SQ;
        src = kpre + (size_t)SQ * INNER; dst = k16 + (size_t)SQ * INNER;
        w = nullptr; cos_t = ccos; sin_t = csin; eps = 1e-5f;
    }

    float v = __half2float(src[(size_t)row * INNER + h * HEAD_DIM + d]);
    float ss = v * v;
#pragma unroll
    for (int o = 16; o; o >>= 1) ss += __shfl_xor_sync(0xffffffffu, ss, o);
    __shared__ float red[4];
    if ((d & 31) == 0) red[d >> 5] = ss;
    __syncthreads();
    float tot = red[0] + red[1] + red[2] + red[3];
    float r = rsqrtf(tot * (1.0f / HEAD_DIM) + eps);

    float y = v * r;
    if (w) y *= w[d];

    float other = __shfl_xor_sync(0xffffffffu, y, 1);
    float c = cos_t[(size_t)row * HEAD_DIM + d];
    float s = sin_t[(size_t)row * HEAD_DIM + d];
    float rot = (d & 1) ? other : -other;
    float out = y * c + rot * s;

    dst[(size_t)row * INNER + h * HEAD_DIM + d] = __float2half_rn(out);
}

// ---------------- tensor-core flash attention (fp16, cp.async KV) --------
#define LDQ 136
#define Q_ELEMS (128 * LDQ)
#define KV_ELEMS (64 * LDQ)
#define KVSTAGE_ELEMS (2 * KV_ELEMS)
#define ATTN_SMEM_BYTES ((Q_ELEMS + 2 * KVSTAGE_ELEMS) * 2)

__global__ __launch_bounds__(256, 2) void attn_fp16_kernel(
    const __half* __restrict__ Q16,
    const __half* __restrict__ K16,
    const __half* __restrict__ V16,
    __half* __restrict__ O16)
{
    extern __shared__ __half smh[];
    __half* sQ = smh;
    __half* kvBase = sQ + Q_ELEMS;

    const int h    = blockIdx.y;
    const int q0   = blockIdx.x * 128;
    const int tid  = threadIdx.x;
    const int lane = tid & 31;
    const int w    = tid >> 5;
    const float scale = 0.08838834764831845f;

    const unsigned sQ_b = (unsigned)__cvta_generic_to_shared(sQ);

    const int krow = tid >> 2;
    const int kcol = (tid & 3) * 32;

    auto load_kv = [&](int s, int kt) {
        __half* st = kvBase + s * KVSTAGE_ELEMS;
        __half* pK = st;
        __half* pV = st + KV_ELEMS;
#pragma unroll
        for (int seg = 0; seg < 4; seg++) {
            int cc = kcol + seg * 8;
            size_t g = (size_t)(kt * 64 + krow) * INNER + h * HEAD_DIM + cc;
            cp16(pK + krow * LDQ + cc, K16 + g);
            cp16(pV + krow * LDQ + cc, V16 + g);
        }
    };

    load_kv(0, 0); CP_COMMIT();

    for (int i = tid; i < 128 * 16; i += 256) {
        int row = i >> 4;
        int c8  = (i & 15) * 8;
        size_t g = (size_t)(q0 + row) * INNER + h * HEAD_DIM + c8;
        *(uint4*)(sQ + row * LDQ + c8) = *(const uint4*)(Q16 + g);
    }

    float o[16][4];
#pragma unroll
    for (int nt = 0; nt < 16; nt++)
#pragma unroll
        for (int r = 0; r < 4; r++) o[nt][r] = 0.f;
    float m_lo = -1e30f, m_hi = -1e30f, l_lo = 0.f, l_hi = 0.f;

    const int NT = SK / 64;
    for (int kt = 0; kt < NT; kt++) {
        CP_WAIT0();
        __syncthreads();
        if (kt + 1 < NT) { load_kv((kt + 1) & 1, kt + 1); CP_COMMIT(); }

        const __half* st = kvBase + (kt & 1) * KVSTAGE_ELEMS;
        const unsigned sK_b = (unsigned)__cvta_generic_to_shared(st);
        const unsigned sV_b = sK_b + KV_ELEMS * 2;

        float c[8][4];
#pragma unroll
        for (int n = 0; n < 8; n++)
#pragma unroll
            for (int r = 0; r < 4; r++) c[n][r] = 0.f;

#pragma unroll
        for (int kk = 0; kk < 8; kk++) {
            unsigned aq[4];
            unsigned qoff = (unsigned)(((w * 16 + (lane & 15)) * LDQ
                                        + kk * 16 + ((lane >> 4) << 3)) * 2);
            LDSM4(aq, sQ_b + qoff);
#pragma unroll
            for (int ng = 0; ng < 4; ng++) {
                unsigned bh[4];
                unsigned koff = (unsigned)(((ng * 16 + (lane & 15)) * LDQ
                                            + kk * 16 + ((lane >> 4) << 3)) * 2);
                LDSM4(bh, sK_b + koff);
                MMA_F16_B2(c[2 * ng],     aq, bh[0], bh[2]);
                MMA_F16_B2(c[2 * ng + 1], aq, bh[1], bh[3]);
            }
        }

        float tmx_lo = -1e30f, tmx_hi = -1e30f;
#pragma unroll
        for (int n = 0; n < 8; n++) {
            c[n][0] *= scale; c[n][1] *= scale; c[n][2] *= scale; c[n][3] *= scale;
            tmx_lo = fmaxf(tmx_lo, fmaxf(c[n][0], c[n][1]));
            tmx_hi = fmaxf(tmx_hi, fmaxf(c[n][2], c[n][3]));
        }
        tmx_lo = fmaxf(tmx_lo, __shfl_xor_sync(0xffffffffu, tmx_lo, 1));
        tmx_lo = fmaxf(tmx_lo, __shfl_xor_sync(0xffffffffu, tmx_lo, 2));
        tmx_hi = fmaxf(tmx_hi, __shfl_xor_sync(0xffffffffu, tmx_hi, 1));
        tmx_hi = fmaxf(tmx_hi, __shfl_xor_sync(0xffffffffu, tmx_hi, 2));

        float mn_lo = fmaxf(m_lo, tmx_lo);
        float mn_hi = fmaxf(m_hi, tmx_hi);
        float al_lo = __expf(m_lo - mn_lo);
        float al_hi = __expf(m_hi - mn_hi);
        m_lo = mn_lo; m_hi = mn_hi;

        unsigned ph[8][2];
        float sum_lo = 0.f, sum_hi = 0.f;
#pragma unroll
        for (int n = 0; n < 8; n++) {
            float p0 = __expf(c[n][0] - m_lo);
            float p1 = __expf(c[n][1] - m_lo);
            float p2 = __expf(c[n][2] - m_hi);
            float p3 = __expf(c[n][3] - m_hi);
            sum_lo += p0 + p1;
            sum_hi += p2 + p3;
            __half2 h01 = __floats2half2_rn(p0, p1);
            __half2 h23 = __floats2half2_rn(p2, p3);
            ph[n][0] = *(unsigned*)&h01; ph[n][1] = *(unsigned*)&h23;
        }
        sum_lo += __shfl_xor_sync(0xffffffffu, sum_lo, 1);
        sum_lo += __shfl_xor_sync(0xffffffffu, sum_lo, 2);
        sum_hi += __shfl_xor_sync(0xffffffffu, sum_hi, 1);
        sum_hi += __shfl_xor_sync(0xffffffffu, sum_hi, 2);
        l_lo = l_lo * al_lo + sum_lo;
        l_hi = l_hi * al_hi + sum_hi;

#pragma unroll
        for (int nt = 0; nt < 16; nt++) {
            o[nt][0] *= al_lo; o[nt][1] *= al_lo;
            o[nt][2] *= al_hi; o[nt][3] *= al_hi;
        }

#pragma unroll
        for (int j = 0; j < 4; j++) {
            unsigned Ap[4] = {ph[2 * j][0], ph[2 * j][1], ph[2 * j + 1][0], ph[2 * j + 1][1]};
#pragma unroll
            for (int dp = 0; dp < 8; dp++) {
                unsigned v4[4];
                unsigned voff = (unsigned)(((j * 16 + (lane & 15)) * LDQ
                                            + dp * 16 + ((lane >> 4) << 3)) * 2);
                LDSM4T(v4, sV_b + voff);
                MMA_F16_B2(o[2 * dp],     Ap, v4[0], v4[1]);
                MMA_F16_B2(o[2 * dp + 1], Ap, v4[2], v4[3]);
            }
        }
        __syncthreads();
    }

    float inv_lo = 1.0f / l_lo;
    float inv_hi = 1.0f / l_hi;
    const int row_lo = q0 + w * 16 + (lane >> 2);
    const int row_hi = row_lo + 8;
    const int cbase  = h * HEAD_DIM + (lane & 3) * 2;
#pragma unroll
    for (int nt = 0; nt < 16; nt++) {
        int d = cbase + nt * 8;
        *(__half2*)(O16 + (size_t)row_lo * INNER + d) =
            __floats2half2_rn(o[nt][0] * inv_lo, o[nt][1] * inv_lo);
        *(__half2*)(O16 + (size_t)row_hi * INNER + d) =
            __floats2half2_rn(o[nt][2] * inv_hi, o[nt][3] * inv_hi);
    }
}

// ---------------- launch ----------------
extern "C" void kernel_launch(void* const* d_in, const int* in_sizes, int n_in,
                              void* d_out, int out_size)
{
    (void)in_sizes; (void)n_in; (void)out_size;
    const float* hid   = (const float*)d_in[0];
    const float* enc   = (const float*)d_in[1];
    const float* ref   = (const float*)d_in[2];
    const float* rcos  = (const float*)d_in[3];
    const float* rsin  = (const float*)d_in[4];
    const float* ccos  = (const float*)d_in[5];
    const float* csin  = (const float*)d_in[6];
    const float* Wq    = (const float*)d_in[7];
    const float* bq    = (const float*)d_in[8];
    const float* Wk    = (const float*)d_in[9];
    const float* bk    = (const float*)d_in[10];
    const float* Wv    = (const float*)d_in[11];
    const float* bv    = (const float*)d_in[12];
    const float* Waq   = (const float*)d_in[13];
    const float* baq   = (const float*)d_in[14];
    const float* Wak   = (const float*)d_in[15];
    const float* bak   = (const float*)d_in[16];
    const float* Wav   = (const float*)d_in[17];
    const float* bav   = (const float*)d_in[18];
    const float* Wout  = (const float*)d_in[19];
    const float* bout  = (const float*)d_in[20];
    const float* Wadd  = (const float*)d_in[21];
    const float* badd  = (const float*)d_in[22];
    const float* nq_w  = (const float*)d_in[23];
    const float* nk_w  = (const float*)d_in[24];
    const float* naq_w = (const float*)d_in[25];
    const float* nak_w = (const float*)d_in[26];
    const float* lkd   = (const float*)d_in[27];
    const float* lku   = (const float*)d_in[28];
    const float* lvd   = (const float*)d_in[29];
    const float* lvu   = (const float*)d_in[30];

    __half *Wenc, *Whid, *Wo16, *Wa16, *Ud, *Uku, *Uvu;
    __half *x16, *tk16, *tv16, *o16, *qpre, *kpre, *q16, *k16, *v16;
    cudaGetSymbolAddress((void**)&Wenc, g_Wqkv_enc);
    cudaGetSymbolAddress((void**)&Whid, g_Wqkv_hid);
    cudaGetSymbolAddress((void**)&Wo16, g_Wout16);
    cudaGetSymbolAddress((void**)&Wa16, g_Wadd16);
    cudaGetSymbolAddress((void**)&Ud,  g_Ud);
    cudaGetSymbolAddress((void**)&Uku, g_Uku);
    cudaGetSymbolAddress((void**)&Uvu, g_Uvu);
    cudaGetSymbolAddress((void**)&x16, g_x16);
    cudaGetSymbolAddress((void**)&tk16, g_tk16);
    cudaGetSymbolAddress((void**)&tv16, g_tv16);
    cudaGetSymbolAddress((void**)&o16, g_o16);
    cudaGetSymbolAddress((void**)&qpre, g_qpre);
    cudaGetSymbolAddress((void**)&kpre, g_kpre);
    cudaGetSymbolAddress((void**)&q16, g_q16);
    cudaGetSymbolAddress((void**)&k16, g_k16);
    cudaGetSymbolAddress((void**)&v16, g_v16);

    cudaFuncSetAttribute(gemm_multi_kernel, cudaFuncAttributeMaxDynamicSharedMemorySize,
                         GEMM_SMEM_BYTES);
    cudaFuncSetAttribute(attn_fp16_kernel, cudaFuncAttributeMaxDynamicSharedMemorySize,
                         ATTN_SMEM_BYTES);

    const size_t WSZ = (size_t)INNER * INNER;      // 9437184
    const size_t USZ = (size_t)INNER * RANK;       // 3145728
    const size_t off_hid = 0;
    const size_t off_enc = (size_t)S_IMG * INNER;
    const size_t off_ref = (size_t)(S_IMG + S_TXT) * INNER;

    // ---- mega convert (15 descriptors, one launch) ----
    CvtArgs ca{};
    int cb = 0;
    auto addCvt = [&](int idx, const float* src, __half* dst,
                      int srcN, int dstN, int off, size_t elems) {
        ca.d[idx] = CvtDesc{src, dst, srcN, dstN, off, cb};
        cb += (int)(elems >> 11);   // 2048 elems per block
    };
    addCvt(0,  hid,  x16 + off_hid, INNER, INNER, 0, (size_t)S_IMG * INNER);
    addCvt(1,  enc,  x16 + off_enc, INNER, INNER, 0, (size_t)S_TXT * INNER);
    addCvt(2,  ref,  x16 + off_ref, INNER, INNER, 0, (size_t)S_REF * INNER);
    addCvt(3,  Wq,   Whid, INNER, 3 * INNER, 0 * INNER, WSZ);
    addCvt(4,  Wk,   Whid, INNER, 3 * INNER, 1 * INNER, WSZ);
    addCvt(5,  Wv,   Whid, INNER, 3 * INNER, 2 * INNER, WSZ);
    addCvt(6,  Waq,  Wenc, INNER, 3 * INNER, 0 * INNER, WSZ);
    addCvt(7,  Wak,  Wenc, INNER, 3 * INNER, 1 * INNER, WSZ);
    addCvt(8,  Wav,  Wenc, INNER, 3 * INNER, 2 * INNER, WSZ);
    addCvt(9,  lkd,  Ud, RANK, 2 * RANK, 0 * RANK, USZ);
    addCvt(10, lvd,  Ud, RANK, 2 * RANK, 1 * RANK, USZ);
    addCvt(11, lku,  Uku, INNER, INNER, 0, USZ);
    addCvt(12, lvu,  Uvu, INNER, INNER, 0, USZ);
    addCvt(13, Wout, Wo16, INNER, INNER, 0, WSZ);
    addCvt(14, Wadd, Wa16, INNER, INNER, 0, WSZ);
    ca.nd = 15;
    cvt_multi_kernel<<<cb, 256>>>(ca);

    // ---- G1: hid QKV + enc QKV + LoRA-down ----
    {
        GArgs ga{};
        int gb = 0;
        ga.g[0] = GDesc{x16 + off_hid, Whid, bq, bk, bv,
                        qpre + (size_t)S_TXT * INNER, kpre + (size_t)S_TXT * INNER,
                        v16 + (size_t)S_TXT * INNER, nullptr,
                        S_IMG, 3 * INNER, INNER, INNER, gb};
        gb += (S_IMG / 128) * (3 * INNER / 128);
        ga.g[1] = GDesc{x16 + off_enc, Wenc, baq, bak, bav,
                        qpre, kpre, v16, nullptr,
                        S_TXT, 3 * INNER, INNER, INNER, gb};
        gb += (S_TXT / 128) * (3 * INNER / 128);
        ga.g[2] = GDesc{x16 + off_ref, Ud, nullptr, nullptr, nullptr,
                        tk16, tv16, nullptr, nullptr,
                        S_REF, 2 * RANK, INNER, RANK, gb};
        gb += (S_REF / 128) * (2 * RANK / 128);
        ga.ng = 3;
        gemm_multi_kernel<<<gb, 256, GEMM_SMEM_BYTES>>>(ga);
    }

    // ---- G2: LoRA-up k and v ----
    {
        GArgs ga{};
        int gb = 0;
        ga.g[0] = GDesc{tk16, Uku, nullptr, nullptr, nullptr,
                        kpre + (size_t)SQ * INNER, nullptr, nullptr, nullptr,
                        S_REF, INNER, RANK, INNER, gb};
        gb += (S_REF / 128) * (INNER / 128);
        ga.g[1] = GDesc{tv16, Uvu, nullptr, nullptr, nullptr,
                        v16 + (size_t)SQ * INNER, nullptr, nullptr, nullptr,
                        S_REF, INNER, RANK, INNER, gb};
        gb += (S_REF / 128) * (INNER / 128);
        ga.ng = 2;
        gemm_multi_kernel<<<gb, 256, GEMM_SMEM_BYTES>>>(ga);
    }

    // ---- RMSNorm + RoPE (one launch, 3 row ranges) ----
    rmsnorm_rope_all_kernel<<<dim3(2 * SQ + S_REF, HEADS), 128>>>(
        qpre, kpre, q16, k16, naq_w, nq_w, nak_w, nk_w, rcos, rsin, ccos, csin);

    // ---- attention ----
    attn_fp16_kernel<<<dim3(SQ / 128, HEADS), 256, ATTN_SMEM_BYTES>>>(
        q16, k16, v16, o16);

    // ---- G3: output projections (fp32 out) ----
    {
        float* outp = (float*)d_out;
        GArgs ga{};
        int gb = 0;
        ga.g[0] = GDesc{o16 + (size_t)S_TXT * INNER, Wo16, bout, nullptr, nullptr,
                        nullptr, nullptr, nullptr, outp,
                        S_IMG, INNER, INNER, INNER, gb};
        gb += (S_IMG / 128) * (INNER / 128);
        ga.g[1] = GDesc{o16, Wa16, badd, nullptr, nullptr,
                        nullptr, nullptr, nullptr, outp + (size_t)S_IMG * INNER,
                        S_TXT, INNER, INNER, INNER, gb};
        gb += (S_TXT / 128) * (INNER / 128);
        ga.ng = 2;
        gemm_multi_kernel<<<gb, 256, GEMM_SMEM_BYTES>>>(ga);
    }
}

// round 15
// speedup vs baseline: 2.4538x; 1.0324x over previous
#include <cuda_runtime.h>
#include <cuda_fp16.h>
#include <cstdint>
#include <cstddef>

#define HEADS 24
#define HEAD_DIM 128
#define INNER 3072
#define RANK 1024
#define S_IMG 2048
#define S_TXT 512
#define S_REF 2048
#define SQ (S_TXT + S_IMG)          // 2560
#define SK (S_TXT + S_IMG + S_REF)  // 4608

// ---------------- scratch (device globals; no allocation) ----------------
__device__ __half g_Wqkv_enc[(size_t)INNER * (3 * INNER)];
__device__ __half g_Wqkv_hid[(size_t)INNER * (3 * INNER)];
__device__ __half g_Wout16[(size_t)INNER * INNER];
__device__ __half g_Wadd16[(size_t)INNER * INNER];
__device__ __half g_Ud[(size_t)INNER * (2 * RANK)];
__device__ __half g_Uku[(size_t)RANK * INNER];
__device__ __half g_Uvu[(size_t)RANK * INNER];
__device__ __half g_x16[(size_t)(S_IMG + S_TXT + S_REF) * INNER];
__device__ __half g_tk16[(size_t)S_REF * RANK];
__device__ __half g_tv16[(size_t)S_REF * RANK];
__device__ __half g_o16[(size_t)SQ * INNER];
__device__ __half g_qpre[(size_t)SQ * INNER];
__device__ __half g_kpre[(size_t)SK * INNER];
__device__ __half g_q16[(size_t)SQ * INNER];
__device__ __half g_k16[(size_t)SK * INNER];
__device__ __half g_v16[(size_t)SK * INNER];

// ---------------- multi-descriptor fp32->fp16 convert ----------------
struct CvtDesc { const float* src; __half* dst; int srcN, dstN, off, bstart; };
struct CvtArgs { CvtDesc d[15]; int nd; };

__global__ __launch_bounds__(256) void cvt_multi_kernel(CvtArgs args)
{
    int bid = blockIdx.x;
    int p = 0;
#pragma unroll
    for (int i = 1; i < 15; i++)
        if (i < args.nd && args.d[i].bstart <= bid) p = i;
    const CvtDesc& d = args.d[p];

    size_t i = ((size_t)(bid - d.bstart) * 256 + threadIdx.x) * 8;
    int k = (int)(i / (size_t)d.srcN);
    int n = (int)(i % (size_t)d.srcN);
    float4 v0 = *(const float4*)(d.src + i);
    float4 v1 = *(const float4*)(d.src + i + 4);
    __half2* yp = (__half2*)(d.dst + (size_t)k * d.dstN + d.off + n);
    yp[0] = __floats2half2_rn(v0.x, v0.y);
    yp[1] = __floats2half2_rn(v0.z, v0.w);
    yp[2] = __floats2half2_rn(v1.x, v1.y);
    yp[3] = __floats2half2_rn(v1.z, v1.w);
}

// ---------------- ptx helpers ----------------
#define LDSM4(R, addr) \
    asm volatile("ldmatrix.sync.aligned.m8n8.x4.shared.b16 {%0,%1,%2,%3},[%4];" \
        : "=r"((R)[0]), "=r"((R)[1]), "=r"((R)[2]), "=r"((R)[3]) : "r"(addr))
#define LDSM4T(R, addr) \
    asm volatile("ldmatrix.sync.aligned.m8n8.x4.trans.shared.b16 {%0,%1,%2,%3},[%4];" \
        : "=r"((R)[0]), "=r"((R)[1]), "=r"((R)[2]), "=r"((R)[3]) : "r"(addr))
#define MMA_F16(C, A, B) \
    asm volatile("mma.sync.aligned.m16n8k16.row.col.f32.f16.f16.f32 " \
        "{%0,%1,%2,%3},{%4,%5,%6,%7},{%8,%9},{%0,%1,%2,%3};" \
        : "+f"((C)[0]), "+f"((C)[1]), "+f"((C)[2]), "+f"((C)[3]) \
        : "r"((A)[0]), "r"((A)[1]), "r"((A)[2]), "r"((A)[3]), "r"((B)[0]), "r"((B)[1]))
#define MMA_F16_B2(C, A, B0, B1) \
    asm volatile("mma.sync.aligned.m16n8k16.row.col.f32.f16.f16.f32 " \
        "{%0,%1,%2,%3},{%4,%5,%6,%7},{%8,%9},{%0,%1,%2,%3};" \
        : "+f"((C)[0]), "+f"((C)[1]), "+f"((C)[2]), "+f"((C)[3]) \
        : "r"((A)[0]), "r"((A)[1]), "r"((A)[2]), "r"((A)[3]), "r"(B0), "r"(B1))

__device__ __forceinline__ void cp16(const void* dst, const void* src) {
    unsigned d = (unsigned)__cvta_generic_to_shared(dst);
    asm volatile("cp.async.cg.shared.global [%0],[%1],16;" :: "r"(d), "l"(src));
}
#define CP_COMMIT() asm volatile("cp.async.commit_group;")
#define CP_WAIT0()  asm volatile("cp.async.wait_group 0;")
#define CP_WAIT1()  asm volatile("cp.async.wait_group 1;")

// ---------------- batched fp16 GEMM (up to 3 sub-problems) ----------------
#define A_LD 40
#define B_LD 136
#define SA_ELEMS (128 * A_LD)
#define SB_ELEMS (32 * B_LD)
#define GSTAGE (SA_ELEMS + SB_ELEMS)
#define GEMM_SMEM_BYTES (GSTAGE * 3 * 2)

struct GDesc {
    const __half *A, *B;
    const float *b0, *b1, *b2;
    __half *C0, *C1, *C2;
    float *Cf;
    int M, N, K, SEGW, bstart;
};
struct GArgs { GDesc g[3]; int ng; };

__global__ __launch_bounds__(256, 1) void gemm_multi_kernel(GArgs args)
{
    extern __shared__ __half dsm[];
    int bid = blockIdx.x;
    int p = 0;
    if (args.ng > 1 && args.g[1].bstart <= bid) p = 1;
    if (args.ng > 2 && args.g[2].bstart <= bid) p = 2;
    const GDesc& d = args.g[p];

    const int nbx  = d.N >> 7;
    const int loc  = bid - d.bstart;
    const int bn   = (loc % nbx) * 128;
    const int bm   = (loc / nbx) * 128;
    const int N    = d.N;
    const int K    = d.K;

    const int tid  = threadIdx.x;
    const int lane = tid & 31;
    const int wid  = tid >> 5;
    const int wm   = wid & 3;
    const int wn   = wid >> 2;
    const int ar = tid >> 1, ac = (tid & 1) * 16;
    const int br = tid >> 4, bc = (tid & 15) * 8;

    float c[2][8][4];
#pragma unroll
    for (int mi = 0; mi < 2; mi++)
#pragma unroll
        for (int ni = 0; ni < 8; ni++)
#pragma unroll
            for (int r = 0; r < 4; r++) c[mi][ni][r] = 0.f;

    const int iters = K >> 5;
    const __half* A = d.A;
    const __half* B = d.B;

    auto load_stage = [&](int s, int it) {
        int k0 = it << 5;
        __half* st = dsm + s * GSTAGE;
        cp16(st + ar * A_LD + ac,     A + (size_t)(bm + ar) * K + k0 + ac);
        cp16(st + ar * A_LD + ac + 8, A + (size_t)(bm + ar) * K + k0 + ac + 8);
        __half* pB = st + SA_ELEMS;
        cp16(pB + br * B_LD + bc,        B + (size_t)(k0 + br) * N + bn + bc);
        cp16(pB + (br + 16) * B_LD + bc, B + (size_t)(k0 + br + 16) * N + bn + bc);
    };

    load_stage(0, 0); CP_COMMIT();
    load_stage(1, 1); CP_COMMIT();

    for (int it = 0; it < iters; it++) {
        if (it == iters - 1) { CP_WAIT0(); } else { CP_WAIT1(); }
        __syncthreads();
        if (it + 2 < iters) { load_stage((it + 2) % 3, it + 2); CP_COMMIT(); }

        const __half* st = dsm + (it % 3) * GSTAGE;
        const unsigned sA_b = (unsigned)__cvta_generic_to_shared(st);
        const unsigned sB_b = sA_b + SA_ELEMS * 2;

#pragma unroll
        for (int kh = 0; kh < 2; kh++) {
            unsigned af[2][4];
#pragma unroll
            for (int mi = 0; mi < 2; mi++) {
                unsigned off = (unsigned)(((wm * 32 + mi * 16 + (lane & 15)) * A_LD
                                           + kh * 16 + ((lane >> 4) << 3)) * 2);
                LDSM4(af[mi], sA_b + off);
            }
#pragma unroll
            for (int pp = 0; pp < 4; pp++) {
                unsigned bh[4];
                unsigned off = (unsigned)(((kh * 16 + (lane & 15)) * B_LD
                                           + wn * 64 + pp * 16 + ((lane >> 4) << 3)) * 2);
                LDSM4T(bh, sB_b + off);
#pragma unroll
                for (int mi = 0; mi < 2; mi++) {
                    MMA_F16(c[mi][2 * pp],     af[mi], bh);
                    MMA_F16(c[mi][2 * pp + 1], af[mi], bh + 2);
                }
            }
        }
    }

    const int row0 = bm + wm * 32 + (lane >> 2);
    if (d.Cf) {
        const int col0 = bn + wn * 64 + (lane & 3) * 2;
#pragma unroll
        for (int mi = 0; mi < 2; mi++) {
#pragma unroll
            for (int ni = 0; ni < 8; ni++) {
                int r  = row0 + mi * 16;
                int cc = col0 + ni * 8;
                float b0v = d.b0 ? d.b0[cc] : 0.f;
                float b1v = d.b0 ? d.b0[cc + 1] : 0.f;
                *(float2*)(d.Cf + (size_t)r * N + cc) =
                    float2{c[mi][ni][0] + b0v, c[mi][ni][1] + b1v};
                *(float2*)(d.Cf + (size_t)(r + 8) * N + cc) =
                    float2{c[mi][ni][2] + b0v, c[mi][ni][3] + b1v};
            }
        }
    } else {
        const int seg = bn / d.SEGW;
        __half* dst = (seg == 0) ? d.C0 : (seg == 1) ? d.C1 : d.C2;
        const float* bias = (seg == 0) ? d.b0 : (seg == 1) ? d.b1 : d.b2;
        const int col0 = (bn - seg * d.SEGW) + wn * 64 + (lane & 3) * 2;
#pragma unroll
        for (int mi = 0; mi < 2; mi++) {
#pragma unroll
            for (int ni = 0; ni < 8; ni++) {
                int r  = row0 + mi * 16;
                int cc = col0 + ni * 8;
                float b0v = bias ? bias[cc] : 0.f;
                float b1v = bias ? bias[cc + 1] : 0.f;
                *(__half2*)(dst + (size_t)r * d.SEGW + cc) =
                    __floats2half2_rn(c[mi][ni][0] + b0v, c[mi][ni][1] + b1v);
                *(__half2*)(dst + (size_t)(r + 8) * d.SEGW + cc) =
                    __floats2half2_rn(c[mi][ni][2] + b0v, c[mi][ni][3] + b1v);
            }
        }
    }
}

// ------ fused RMSNorm + RoPE: one WARP per (row, head), 4 dims/lane ------
__global__ __launch_bounds__(256) void rmsnorm_rope_all_kernel(
    const __half* __restrict__ qpre, const __half* __restrict__ kpre,
    __half* __restrict__ q16, __half* __restrict__ k16,
    const float* __restrict__ naq_w, const float* __restrict__ nq_w,
    const float* __restrict__ nak_w, const float* __restrict__ nk_w,
    const float* __restrict__ rcos, const float* __restrict__ rsin,
    const float* __restrict__ ccos, const float* __restrict__ csin)
{
    const int wg   = blockIdx.x * 8 + (threadIdx.x >> 5);  // global warp id
    const int lane = threadIdx.x & 31;
    const int rr   = wg / HEADS;
    const int h    = wg - rr * HEADS;
    const int d0   = lane * 4;

    const __half* src; __half* dst;
    const float *w, *cos_t, *sin_t;
    float eps;
    int row;
    if (rr < SQ) {
        row = rr; src = qpre; dst = q16;
        w = (row < S_TXT) ? naq_w : nq_w;
        cos_t = rcos; sin_t = rsin; eps = 1e-6f;
    } else if (rr < 2 * SQ) {
        row = rr - SQ; src = kpre; dst = k16;
        w = (row < S_TXT) ? nak_w : nk_w;
        cos_t = rcos; sin_t = rsin; eps = 1e-6f;
    } else {
        row = rr - 2 * SQ;
        src = kpre + (size_t)SQ * INNER; dst = k16 + (size_t)SQ * INNER;
        w = nullptr; cos_t = ccos; sin_t = csin; eps = 1e-5f;
    }

    const size_t base = (size_t)row * INNER + h * HEAD_DIM + d0;
    __half2 hv[2];
    *(uint2*)hv = *(const uint2*)(src + base);
    float x0 = __half2float(hv[0].x), x1 = __half2float(hv[0].y);
    float x2 = __half2float(hv[1].x), x3 = __half2float(hv[1].y);

    float ss = x0 * x0 + x1 * x1 + x2 * x2 + x3 * x3;
#pragma unroll
    for (int o = 16; o; o >>= 1) ss += __shfl_xor_sync(0xffffffffu, ss, o);
    float r = rsqrtf(ss * (1.0f / HEAD_DIM) + eps);

    float y0 = x0 * r, y1 = x1 * r, y2 = x2 * r, y3 = x3 * r;
    if (w) {
        float4 wv = *(const float4*)(w + d0);
        y0 *= wv.x; y1 *= wv.y; y2 *= wv.z; y3 *= wv.w;
    }

    float4 cv = *(const float4*)(cos_t + (size_t)row * HEAD_DIM + d0);
    float4 sv = *(const float4*)(sin_t + (size_t)row * HEAD_DIM + d0);
    // RoPE pairs (d0,d0+1) and (d0+2,d0+3) are local to this lane
    float o0 = y0 * cv.x - y1 * sv.x;
    float o1 = y1 * cv.y + y0 * sv.y;
    float o2 = y2 * cv.z - y3 * sv.z;
    float o3 = y3 * cv.w + y2 * sv.w;

    __half2 out[2];
    out[0] = __floats2half2_rn(o0, o1);
    out[1] = __floats2half2_rn(o2, o3);
    *(uint2*)(dst + base) = *(uint2*)out;
}

// ---------------- tensor-core flash attention (fp16, cp.async KV) --------
#define LDQ 136
#define Q_ELEMS (128 * LDQ)
#define KV_ELEMS (64 * LDQ)
#define KVSTAGE_ELEMS (2 * KV_ELEMS)
#define ATTN_SMEM_BYTES ((Q_ELEMS + 2 * KVSTAGE_ELEMS) * 2)

__global__ __launch_bounds__(256, 2) void attn_fp16_kernel(
    const __half* __restrict__ Q16,
    const __half* __restrict__ K16,
    const __half* __restrict__ V16,
    __half* __restrict__ O16)
{
    extern __shared__ __half smh[];
    __half* sQ = smh;
    __half* kvBase = sQ + Q_ELEMS;

    const int h    = blockIdx.y;
    const int q0   = blockIdx.x * 128;
    const int tid  = threadIdx.x;
    const int lane = tid & 31;
    const int w    = tid >> 5;
    const float scale = 0.08838834764831845f;

    const unsigned sQ_b = (unsigned)__cvta_generic_to_shared(sQ);

    const int krow = tid >> 2;
    const int kcol = (tid & 3) * 32;

    auto load_kv = [&](int s, int kt) {
        __half* st = kvBase + s * KVSTAGE_ELEMS;
        __half* pK = st;
        __half* pV = st + KV_ELEMS;
#pragma unroll
        for (int seg = 0; seg < 4; seg++) {
            int cc = kcol + seg * 8;
            size_t g = (size_t)(kt * 64 + krow) * INNER + h * HEAD_DIM + cc;
            cp16(pK + krow * LDQ + cc, K16 + g);
            cp16(pV + krow * LDQ + cc, V16 + g);
        }
    };

    load_kv(0, 0); CP_COMMIT();

    for (int i = tid; i < 128 * 16; i += 256) {
        int row = i >> 4;
        int c8  = (i & 15) * 8;
        size_t g = (size_t)(q0 + row) * INNER + h * HEAD_DIM + c8;
        *(uint4*)(sQ + row * LDQ + c8) = *(const uint4*)(Q16 + g);
    }

    float o[16][4];
#pragma unroll
    for (int nt = 0; nt < 16; nt++)
#pragma unroll
        for (int r = 0; r < 4; r++) o[nt][r] = 0.f;
    float m_lo = -1e30f, m_hi = -1e30f, l_lo = 0.f, l_hi = 0.f;

    const int NT = SK / 64;
    for (int kt = 0; kt < NT; kt++) {
        CP_WAIT0();
        __syncthreads();
        if (kt + 1 < NT) { load_kv((kt + 1) & 1, kt + 1); CP_COMMIT(); }

        const __half* st = kvBase + (kt & 1) * KVSTAGE_ELEMS;
        const unsigned sK_b = (unsigned)__cvta_generic_to_shared(st);
        const unsigned sV_b = sK_b + KV_ELEMS * 2;

        float c[8][4];
#pragma unroll
        for (int n = 0; n < 8; n++)
#pragma unroll
            for (int r = 0; r < 4; r++) c[n][r] = 0.f;

#pragma unroll
        for (int kk = 0; kk < 8; kk++) {
            unsigned aq[4];
            unsigned qoff = (unsigned)(((w * 16 + (lane & 15)) * LDQ
                                        + kk * 16 + ((lane >> 4) << 3)) * 2);
            LDSM4(aq, sQ_b + qoff);
#pragma unroll
            for (int ng = 0; ng < 4; ng++) {
                unsigned bh[4];
                unsigned koff = (unsigned)(((ng * 16 + (lane & 15)) * LDQ
                                            + kk * 16 + ((lane >> 4) << 3)) * 2);
                LDSM4(bh, sK_b + koff);
                MMA_F16_B2(c[2 * ng],     aq, bh[0], bh[2]);
                MMA_F16_B2(c[2 * ng + 1], aq, bh[1], bh[3]);
            }
        }

        float tmx_lo = -1e30f, tmx_hi = -1e30f;
#pragma unroll
        for (int n = 0; n < 8; n++) {
            c[n][0] *= scale; c[n][1] *= scale; c[n][2] *= scale; c[n][3] *= scale;
            tmx_lo = fmaxf(tmx_lo, fmaxf(c[n][0], c[n][1]));
            tmx_hi = fmaxf(tmx_hi, fmaxf(c[n][2], c[n][3]));
        }
        tmx_lo = fmaxf(tmx_lo, __shfl_xor_sync(0xffffffffu, tmx_lo, 1));
        tmx_lo = fmaxf(tmx_lo, __shfl_xor_sync(0xffffffffu, tmx_lo, 2));
        tmx_hi = fmaxf(tmx_hi, __shfl_xor_sync(0xffffffffu, tmx_hi, 1));
        tmx_hi = fmaxf(tmx_hi, __shfl_xor_sync(0xffffffffu, tmx_hi, 2));

        float mn_lo = fmaxf(m_lo, tmx_lo);
        float mn_hi = fmaxf(m_hi, tmx_hi);
        float al_lo = __expf(m_lo - mn_lo);
        float al_hi = __expf(m_hi - mn_hi);
        m_lo = mn_lo; m_hi = mn_hi;

        unsigned ph[8][2];
        float sum_lo = 0.f, sum_hi = 0.f;
#pragma unroll
        for (int n = 0; n < 8; n++) {
            float p0 = __expf(c[n][0] - m_lo);
            float p1 = __expf(c[n][1] - m_lo);
            float p2 = __expf(c[n][2] - m_hi);
            float p3 = __expf(c[n][3] - m_hi);
            sum_lo += p0 + p1;
            sum_hi += p2 + p3;
            __half2 h01 = __floats2half2_rn(p0, p1);
            __half2 h23 = __floats2half2_rn(p2, p3);
            ph[n][0] = *(unsigned*)&h01; ph[n][1] = *(unsigned*)&h23;
        }
        sum_lo += __shfl_xor_sync(0xffffffffu, sum_lo, 1);
        sum_lo += __shfl_xor_sync(0xffffffffu, sum_lo, 2);
        sum_hi += __shfl_xor_sync(0xffffffffu, sum_hi, 1);
        sum_hi += __shfl_xor_sync(0xffffffffu, sum_hi, 2);
        l_lo = l_lo * al_lo + sum_lo;
        l_hi = l_hi * al_hi + sum_hi;

#pragma unroll
        for (int nt = 0; nt < 16; nt++) {
            o[nt][0] *= al_lo; o[nt][1] *= al_lo;
            o[nt][2] *= al_hi; o[nt][3] *= al_hi;
        }

#pragma unroll
        for (int j = 0; j < 4; j++) {
            unsigned Ap[4] = {ph[2 * j][0], ph[2 * j][1], ph[2 * j + 1][0], ph[2 * j + 1][1]};
#pragma unroll
            for (int dp = 0; dp < 8; dp++) {
                unsigned v4[4];
                unsigned voff = (unsigned)(((j * 16 + (lane & 15)) * LDQ
                                            + dp * 16 + ((lane >> 4) << 3)) * 2);
                LDSM4T(v4, sV_b + voff);
                MMA_F16_B2(o[2 * dp],     Ap, v4[0], v4[1]);
                MMA_F16_B2(o[2 * dp + 1], Ap, v4[2], v4[3]);
            }
        }
        __syncthreads();
    }

    float inv_lo = 1.0f / l_lo;
    float inv_hi = 1.0f / l_hi;
    const int row_lo = q0 + w * 16 + (lane >> 2);
    const int row_hi = row_lo + 8;
    const int cbase  = h * HEAD_DIM + (lane & 3) * 2;
#pragma unroll
    for (int nt = 0; nt < 16; nt++) {
        int d = cbase + nt * 8;
        *(__half2*)(O16 + (size_t)row_lo * INNER + d) =
            __floats2half2_rn(o[nt][0] * inv_lo, o[nt][1] * inv_lo);
        *(__half2*)(O16 + (size_t)row_hi * INNER + d) =
            __floats2half2_rn(o[nt][2] * inv_hi, o[nt][3] * inv_hi);
    }
}

// ---------------- launch ----------------
extern "C" void kernel_launch(void* const* d_in, const int* in_sizes, int n_in,
                              void* d_out, int out_size)
{
    (void)in_sizes; (void)n_in; (void)out_size;
    const float* hid   = (const float*)d_in[0];
    const float* enc   = (const float*)d_in[1];
    const float* ref   = (const float*)d_in[2];
    const float* rcos  = (const float*)d_in[3];
    const float* rsin  = (const float*)d_in[4];
    const float* ccos  = (const float*)d_in[5];
    const float* csin  = (const float*)d_in[6];
    const float* Wq    = (const float*)d_in[7];
    const float* bq    = (const float*)d_in[8];
    const float* Wk    = (const float*)d_in[9];
    const float* bk    = (const float*)d_in[10];
    const float* Wv    = (const float*)d_in[11];
    const float* bv    = (const float*)d_in[12];
    const float* Waq   = (const float*)d_in[13];
    const float* baq   = (const float*)d_in[14];
    const float* Wak   = (const float*)d_in[15];
    const float* bak   = (const float*)d_in[16];
    const float* Wav   = (const float*)d_in[17];
    const float* bav   = (const float*)d_in[18];
    const float* Wout  = (const float*)d_in[19];
    const float* bout  = (const float*)d_in[20];
    const float* Wadd  = (const float*)d_in[21];
    const float* badd  = (const float*)d_in[22];
    const float* nq_w  = (const float*)d_in[23];
    const float* nk_w  = (const float*)d_in[24];
    const float* naq_w = (const float*)d_in[25];
    const float* nak_w = (const float*)d_in[26];
    const float* lkd   = (const float*)d_in[27];
    const float* lku   = (const float*)d_in[28];
    const float* lvd   = (const float*)d_in[29];
    const float* lvu   = (const float*)d_in[30];

    __half *Wenc, *Whid, *Wo16, *Wa16, *Ud, *Uku, *Uvu;
    __half *x16, *tk16, *tv16, *o16, *qpre, *kpre, *q16, *k16, *v16;
    cudaGetSymbolAddress((void**)&Wenc, g_Wqkv_enc);
    cudaGetSymbolAddress((void**)&Whid, g_Wqkv_hid);
    cudaGetSymbolAddress((void**)&Wo16, g_Wout16);
    cudaGetSymbolAddress((void**)&Wa16, g_Wadd16);
    cudaGetSymbolAddress((void**)&Ud,  g_Ud);
    cudaGetSymbolAddress((void**)&Uku, g_Uku);
    cudaGetSymbolAddress((void**)&Uvu, g_Uvu);
    cudaGetSymbolAddress((void**)&x16, g_x16);
    cudaGetSymbolAddress((void**)&tk16, g_tk16);
    cudaGetSymbolAddress((void**)&tv16, g_tv16);
    cudaGetSymbolAddress((void**)&o16, g_o16);
    cudaGetSymbolAddress((void**)&qpre, g_qpre);
    cudaGetSymbolAddress((void**)&kpre, g_kpre);
    cudaGetSymbolAddress((void**)&q16, g_q16);
    cudaGetSymbolAddress((void**)&k16, g_k16);
    cudaGetSymbolAddress((void**)&v16, g_v16);

    cudaFuncSetAttribute(gemm_multi_kernel, cudaFuncAttributeMaxDynamicSharedMemorySize,
                         GEMM_SMEM_BYTES);
    cudaFuncSetAttribute(attn_fp16_kernel, cudaFuncAttributeMaxDynamicSharedMemorySize,
                         ATTN_SMEM_BYTES);

    const size_t WSZ = (size_t)INNER * INNER;
    const size_t USZ = (size_t)INNER * RANK;
    const size_t off_hid = 0;
    const size_t off_enc = (size_t)S_IMG * INNER;
    const size_t off_ref = (size_t)(S_IMG + S_TXT) * INNER;

    // ---- mega convert (15 descriptors, one launch) ----
    CvtArgs ca{};
    int cb = 0;
    auto addCvt = [&](int idx, const float* src, __half* dst,
                      int srcN, int dstN, int off, size_t elems) {
        ca.d[idx] = CvtDesc{src, dst, srcN, dstN, off, cb};
        cb += (int)(elems >> 11);
    };
    addCvt(0,  hid,  x16 + off_hid, INNER, INNER, 0, (size_t)S_IMG * INNER);
    addCvt(1,  enc,  x16 + off_enc, INNER, INNER, 0, (size_t)S_TXT * INNER);
    addCvt(2,  ref,  x16 + off_ref, INNER, INNER, 0, (size_t)S_REF * INNER);
    addCvt(3,  Wq,   Whid, INNER, 3 * INNER, 0 * INNER, WSZ);
    addCvt(4,  Wk,   Whid, INNER, 3 * INNER, 1 * INNER, WSZ);
    addCvt(5,  Wv,   Whid, INNER, 3 * INNER, 2 * INNER, WSZ);
    addCvt(6,  Waq,  Wenc, INNER, 3 * INNER, 0 * INNER, WSZ);
    addCvt(7,  Wak,  Wenc, INNER, 3 * INNER, 1 * INNER, WSZ);
    addCvt(8,  Wav,  Wenc, INNER, 3 * INNER, 2 * INNER, WSZ);
    addCvt(9,  lkd,  Ud, RANK, 2 * RANK, 0 * RANK, USZ);
    addCvt(10, lvd,  Ud, RANK, 2 * RANK, 1 * RANK, USZ);
    addCvt(11, lku,  Uku, INNER, INNER, 0, USZ);
    addCvt(12, lvu,  Uvu, INNER, INNER, 0, USZ);
    addCvt(13, Wout, Wo16, INNER, INNER, 0, WSZ);
    addCvt(14, Wadd, Wa16, INNER, INNER, 0, WSZ);
    ca.nd = 15;
    cvt_multi_kernel<<<cb, 256>>>(ca);

    // ---- G1: hid QKV + enc QKV + LoRA-down ----
    {
        GArgs ga{};
        int gb = 0;
        ga.g[0] = GDesc{x16 + off_hid, Whid, bq, bk, bv,
                        qpre + (size_t)S_TXT * INNER, kpre + (size_t)S_TXT * INNER,
                        v16 + (size_t)S_TXT * INNER, nullptr,
                        S_IMG, 3 * INNER, INNER, INNER, gb};
        gb += (S_IMG / 128) * (3 * INNER / 128);
        ga.g[1] = GDesc{x16 + off_enc, Wenc, baq, bak, bav,
                        qpre, kpre, v16, nullptr,
                        S_TXT, 3 * INNER, INNER, INNER, gb};
        gb += (S_TXT / 128) * (3 * INNER / 128);
        ga.g[2] = GDesc{x16 + off_ref, Ud, nullptr, nullptr, nullptr,
                        tk16, tv16, nullptr, nullptr,
                        S_REF, 2 * RANK, INNER, RANK, gb};
        gb += (S_REF / 128) * (2 * RANK / 128);
        ga.ng = 3;
        gemm_multi_kernel<<<gb, 256, GEMM_SMEM_BYTES>>>(ga);
    }

    // ---- G2: LoRA-up k and v ----
    {
        GArgs ga{};
        int gb = 0;
        ga.g[0] = GDesc{tk16, Uku, nullptr, nullptr, nullptr,
                        kpre + (size_t)SQ * INNER, nullptr, nullptr, nullptr,
                        S_REF, INNER, RANK, INNER, gb};
        gb += (S_REF / 128) * (INNER / 128);
        ga.g[1] = GDesc{tv16, Uvu, nullptr, nullptr, nullptr,
                        v16 + (size_t)SQ * INNER, nullptr, nullptr, nullptr,
                        S_REF, INNER, RANK, INNER, gb};
        gb += (S_REF / 128) * (INNER / 128);
        ga.ng = 2;
        gemm_multi_kernel<<<gb, 256, GEMM_SMEM_BYTES>>>(ga);
    }

    // ---- RMSNorm + RoPE (one launch, warp per row-head) ----
    {
        int total_warps = (2 * SQ + S_REF) * HEADS;   // 172032
        rmsnorm_rope_all_kernel<<<total_warps / 8, 256>>>(
            qpre, kpre, q16, k16, naq_w, nq_w, nak_w, nk_w, rcos, rsin, ccos, csin);
    }

    // ---- attention ----
    attn_fp16_kernel<<<dim3(SQ / 128, HEADS), 256, ATTN_SMEM_BYTES>>>(
        q16, k16, v16, o16);

    // ---- G3: output projections (fp32 out) ----
    {
        float* outp = (float*)d_out;
        GArgs ga{};
        int gb = 0;
        ga.g[0] = GDesc{o16 + (size_t)S_TXT * INNER, Wo16, bout, nullptr, nullptr,
                        nullptr, nullptr, nullptr, outp,
                        S_IMG, INNER, INNER, INNER, gb};
        gb += (S_IMG / 128) * (INNER / 128);
        ga.g[1] = GDesc{o16, Wa16, badd, nullptr, nullptr,
                        nullptr, nullptr, nullptr, outp + (size_t)S_IMG * INNER,
                        S_TXT, INNER, INNER, INNER, gb};
        gb += (S_TXT / 128) * (INNER / 128);
        ga.ng = 2;
        gemm_multi_kernel<<<gb, 256, GEMM_SMEM_BYTES>>>(ga);
    }
}